// round 6
// baseline (speedup 1.0000x reference)
#include <cuda_runtime.h>
#include <cuda_bf16.h>
#include <cstdint>
#include <cmath>

#define DIMX 768
#define NHEAD 12
#define HD 64
#define BATCH 4
#define SEQ 2048
#define ROWS_TOT (BATCH*SEQ)   /* 8192 */
#define ATTN_SCALE 0.125f
#define BHT (BATCH*NHEAD)

// ---- scratch (allocation-free: __device__ globals; device-side access ONLY) ----
__device__ __align__(16) __nv_bfloat16 g_xhi[ROWS_TOT*DIMX],  g_xlo[ROWS_TOT*DIMX];
__device__ __align__(16) __nv_bfloat16 g_w1hi[3*DIMX*DIMX],   g_w1lo[3*DIMX*DIMX];
__device__ __align__(16) __nv_bfloat16 g_w2hi[DIMX*DIMX],     g_w2lo[DIMX*DIMX];
__device__ __align__(16) __nv_bfloat16 g_qhi[BHT*SEQ*HD],  g_qlo[BHT*SEQ*HD];
__device__ __align__(16) __nv_bfloat16 g_khi[BHT*SEQ*HD],  g_klo[BHT*SEQ*HD];
__device__ __align__(16) __nv_bfloat16 g_vthi[BHT*HD*SEQ], g_vtlo[BHT*HD*SEQ];
__device__ __align__(16) __nv_bfloat16 g_atthi[ROWS_TOT*DIMX], g_attlo[ROWS_TOT*DIMX];

// ---- mma.sync m16n8k16 bf16 (row.col), fp32 accum ----
#define MMA16816(d0,d1,d2,d3,a0,a1,a2,a3,b0,b1)                              \
  asm volatile("mma.sync.aligned.m16n8k16.row.col.f32.bf16.bf16.f32 "        \
               "{%0,%1,%2,%3}, {%4,%5,%6,%7}, {%8,%9}, {%0,%1,%2,%3};\n"     \
               : "+f"(d0), "+f"(d1), "+f"(d2), "+f"(d3)                      \
               : "r"(a0), "r"(a1), "r"(a2), "r"(a3), "r"(b0), "r"(b1))

#define LDSM4(r0,r1,r2,r3, addr)                                             \
  asm volatile("ldmatrix.sync.aligned.m8n8.x4.shared.b16 {%0,%1,%2,%3}, [%4];\n" \
               : "=r"(r0), "=r"(r1), "=r"(r2), "=r"(r3) : "r"(addr))

#define CP16(d, s)                                                            \
  asm volatile("cp.async.cg.shared.global [%0], [%1], 16;\n"                  \
               :: "r"(d), "l"(s))
#define CPCOMMIT asm volatile("cp.async.commit_group;\n")

__device__ __forceinline__ void split2(float x, float y,
                                       unsigned int &h, unsigned int &l)
{
    __nv_bfloat162 hb = __floats2bfloat162_rn(x, y);
    float rx = x - __bfloat162float(hb.x);
    float ry = y - __bfloat162float(hb.y);
    __nv_bfloat162 lb = __floats2bfloat162_rn(rx, ry);
    h = *reinterpret_cast<unsigned int*>(&hb);
    l = *reinterpret_cast<unsigned int*>(&lb);
}

__device__ __forceinline__ void split_store(float x, float y,
                                            __nv_bfloat16* ph, __nv_bfloat16* pl)
{
    __nv_bfloat162 hb = __floats2bfloat162_rn(x, y);
    *reinterpret_cast<__nv_bfloat162*>(ph) = hb;
    float rx = x - __bfloat162float(hb.x);
    float ry = y - __bfloat162float(hb.y);
    *reinterpret_cast<__nv_bfloat162*>(pl) = __floats2bfloat162_rn(rx, ry);
}

__device__ __forceinline__ void split1(float x, __nv_bfloat16 &h, __nv_bfloat16 &l)
{
    h = __float2bfloat16(x);
    l = __float2bfloat16(x - __bfloat162float(h));
}

// ============================================================
// Elementwise fp32 -> bf16 hi/lo split. Destination selected
// INSIDE the kernel (device globals must not cross host boundary).
// WHICH: 0 -> g_x, 1 -> g_w1, 2 -> g_w2
// ============================================================
template<int WHICH>
__global__ void split_f32(const float4* __restrict__ src, int n4)
{
    __nv_bfloat162* hi = (WHICH == 0) ? (__nv_bfloat162*)g_xhi
                       : (WHICH == 1) ? (__nv_bfloat162*)g_w1hi
                                      : (__nv_bfloat162*)g_w2hi;
    __nv_bfloat162* lo = (WHICH == 0) ? (__nv_bfloat162*)g_xlo
                       : (WHICH == 1) ? (__nv_bfloat162*)g_w1lo
                                      : (__nv_bfloat162*)g_w2lo;
    int i = blockIdx.x*blockDim.x + threadIdx.x;
    if (i >= n4) return;
    float4 v = src[i];
    __nv_bfloat162 h0 = __floats2bfloat162_rn(v.x, v.y);
    __nv_bfloat162 h1 = __floats2bfloat162_rn(v.z, v.w);
    hi[i*2]   = h0;
    hi[i*2+1] = h1;
    lo[i*2]   = __floats2bfloat162_rn(v.x - __bfloat162float(h0.x),
                                      v.y - __bfloat162float(h0.y));
    lo[i*2+1] = __floats2bfloat162_rn(v.z - __bfloat162float(h1.x),
                                      v.w - __bfloat162float(h1.y));
}

// ============================================================
// bf16x3 GEMM, cp.async + ldmatrix + HMMA pipeline.
// BM=128 BN=128 BK=32, 256 thr, warp grid 2(m)x4(n), 64x32/warp.
// Operands read from device globals selected by QKV.
// ============================================================
#define AS_B (128*40*2)          /* bytes per smem array     */
#define STAGE_B (4*AS_B)         /* Ah|Al|Bh|Bl per stage    */

template<bool QKV>
__global__ __launch_bounds__(256) void gemm_bf16x3(const float* __restrict__ bias,
                                                   float* __restrict__ out)
{
    const __nv_bfloat16* __restrict__ a_hi = QKV ? g_xhi  : g_atthi;
    const __nv_bfloat16* __restrict__ a_lo = QKV ? g_xlo  : g_attlo;
    const __nv_bfloat16* __restrict__ b_hi = QKV ? g_w1hi : g_w2hi;
    const __nv_bfloat16* __restrict__ b_lo = QKV ? g_w1lo : g_w2lo;

    extern __shared__ __nv_bfloat16 smg[];
    const unsigned int smem_u32 = (unsigned int)__cvta_generic_to_shared(smg);

    const int tid  = threadIdx.x;
    const int lane = tid & 31;
    const int w    = tid >> 5;
    const int g    = lane >> 2;
    const int tig  = lane & 3;
    const int wm   = w & 1;
    const int wn   = w >> 1;
    const int bm   = blockIdx.y * 128;
    const int bn   = blockIdx.x * 128;

    // ldmatrix per-lane offset (stride 40 elems)
    const unsigned int aoff = (unsigned int)(((lane & 15)*40 + ((lane >> 4) << 3)) * 2);

    float acc[4][4][4];
    #pragma unroll
    for (int i = 0; i < 4; i++)
        #pragma unroll
        for (int j = 0; j < 4; j++)
            #pragma unroll
            for (int r = 0; r < 4; r++) acc[i][j][r] = 0.f;

    auto load_stage = [&](int st, int k0) {
        unsigned int base = smem_u32 + st*STAGE_B;
        #pragma unroll
        for (int t = 0; t < 2; t++) {
            int idx = tid*2 + t;             // 0..511
            int row = idx >> 2;
            int ch  = (idx & 3) * 8;         // bf16 elems
            unsigned int doff = (unsigned int)(row*40 + ch)*2;
            CP16(base +          doff, &a_hi[(size_t)(bm+row)*DIMX + k0 + ch]);
            CP16(base +   AS_B + doff, &a_lo[(size_t)(bm+row)*DIMX + k0 + ch]);
            CP16(base + 2*AS_B + doff, &b_hi[(size_t)(bn+row)*DIMX + k0 + ch]);
            CP16(base + 3*AS_B + doff, &b_lo[(size_t)(bn+row)*DIMX + k0 + ch]);
        }
    };

    load_stage(0, 0); CPCOMMIT;
    int s = 0;

    for (int k0 = 0; k0 < DIMX; k0 += 32) {
        if (k0 + 32 < DIMX) {
            load_stage(s^1, k0+32); CPCOMMIT;
            asm volatile("cp.async.wait_group 1;\n");
        } else {
            asm volatile("cp.async.wait_group 0;\n");
        }
        __syncthreads();

        const unsigned int sA = smem_u32 + s*STAGE_B;
        const unsigned int sB = sA + 2*AS_B;

        #pragma unroll
        for (int ks = 0; ks < 32; ks += 16) {
            unsigned int ah[4][4], al[4][4];
            #pragma unroll
            for (int mf = 0; mf < 4; mf++) {
                unsigned int ra = sA + (unsigned int)(((wm*64 + mf*16)*40 + ks)*2) + aoff;
                LDSM4(ah[mf][0], ah[mf][1], ah[mf][2], ah[mf][3], ra);
                LDSM4(al[mf][0], al[mf][1], al[mf][2], al[mf][3], ra + AS_B);
            }
            unsigned int bhf[4][2], blf[4][2];
            #pragma unroll
            for (int p = 0; p < 2; p++) {
                unsigned int rb = sB + (unsigned int)(((wn*32 + p*16)*40 + ks)*2) + aoff;
                unsigned int r0, r1, r2, r3;
                LDSM4(r0, r1, r2, r3, rb);
                bhf[p*2][0] = r0; bhf[p*2+1][0] = r1;
                bhf[p*2][1] = r2; bhf[p*2+1][1] = r3;
                LDSM4(r0, r1, r2, r3, rb + AS_B);
                blf[p*2][0] = r0; blf[p*2+1][0] = r1;
                blf[p*2][1] = r2; blf[p*2+1][1] = r3;
            }
            #pragma unroll
            for (int nf = 0; nf < 4; nf++)
                #pragma unroll
                for (int mf = 0; mf < 4; mf++) {
                    MMA16816(acc[mf][nf][0], acc[mf][nf][1], acc[mf][nf][2], acc[mf][nf][3],
                             ah[mf][0], ah[mf][1], ah[mf][2], ah[mf][3],
                             bhf[nf][0], bhf[nf][1]);
                    MMA16816(acc[mf][nf][0], acc[mf][nf][1], acc[mf][nf][2], acc[mf][nf][3],
                             ah[mf][0], ah[mf][1], ah[mf][2], ah[mf][3],
                             blf[nf][0], blf[nf][1]);
                    MMA16816(acc[mf][nf][0], acc[mf][nf][1], acc[mf][nf][2], acc[mf][nf][3],
                             al[mf][0], al[mf][1], al[mf][2], al[mf][3],
                             bhf[nf][0], bhf[nf][1]);
                }
        }
        s ^= 1;
        __syncthreads();
    }

    // ---- epilogue ----
    #pragma unroll
    for (int nf = 0; nf < 4; nf++) {
        int col = bn + wn*32 + nf*8 + tig*2;
        float bx = bias[col], by = bias[col+1];
        if (QKV) {
            int c  = col / DIMX;            // 0=Q 1=K 2=V
            int hh = (col % DIMX) >> 6;
            int dd = col & 63;
            #pragma unroll
            for (int mf = 0; mf < 4; mf++)
                #pragma unroll
                for (int h2 = 0; h2 < 2; h2++) {
                    int row = bm + wm*64 + mf*16 + g + h2*8;
                    int b_ = row >> 11, n_ = row & 2047;
                    float vx = acc[mf][nf][h2*2+0] + bx;
                    float vy = acc[mf][nf][h2*2+1] + by;
                    if (c == 0) {
                        size_t idx = (((size_t)(b_*NHEAD + hh))*SEQ + n_)*HD + dd;
                        split_store(vx*ATTN_SCALE, vy*ATTN_SCALE, &g_qhi[idx], &g_qlo[idx]);
                    } else if (c == 1) {
                        size_t idx = (((size_t)(b_*NHEAD + hh))*SEQ + n_)*HD + dd;
                        split_store(vx, vy, &g_khi[idx], &g_klo[idx]);
                    } else {
                        size_t idx = (((size_t)(b_*NHEAD + hh))*HD + dd)*SEQ + n_;
                        split1(vx, g_vthi[idx],     g_vtlo[idx]);
                        split1(vy, g_vthi[idx+SEQ], g_vtlo[idx+SEQ]);
                    }
                }
        } else {
            #pragma unroll
            for (int mf = 0; mf < 4; mf++)
                #pragma unroll
                for (int h2 = 0; h2 < 2; h2++) {
                    int row = bm + wm*64 + mf*16 + g + h2*8;
                    float2 v = make_float2(acc[mf][nf][h2*2+0] + bx,
                                           acc[mf][nf][h2*2+1] + by);
                    *(float2*)&out[(size_t)row*DIMX + col] = v;
                }
        }
    }
}

// ============================================================
// Flash attention: cp.async K/V double buffer + ldmatrix frags.
// Block = (b*h, 128 query rows), 8 warps. S/P in registers.
// ============================================================
#define TSE (64*72)           /* elems per smem array  */
#define TSB (TSE*2)           /* bytes per smem array  */

__global__ __launch_bounds__(256) void attn_mma()
{
    extern __shared__ __nv_bfloat16 sma[];
    const unsigned int smem_u32 = (unsigned int)__cvta_generic_to_shared(sma);

    const int tid  = threadIdx.x;
    const int lane = tid & 31;
    const int w    = tid >> 5;
    const int g    = lane >> 2;
    const int tig  = lane & 3;
    const int bh   = blockIdx.y;
    const int q0   = blockIdx.x * 128;
    const size_t kbase = (size_t)bh * SEQ * HD;
    const size_t vbase = (size_t)bh * HD * SEQ;
    const int row0 = q0 + w*16 + g;

    // ldmatrix per-lane offset (stride 72 elems)
    const unsigned int aoff = (unsigned int)(((lane & 15)*72 + ((lane >> 4) << 3)) * 2);

    // Q fragments (pre-scaled & pre-split in gmem)
    unsigned int qhi[4][4], qlo[4][4];
    #pragma unroll
    for (int ks = 0; ks < 4; ks++) {
        int c0 = ks*16 + tig*2;
        qhi[ks][0] = *(const unsigned int*)&g_qhi[kbase + (size_t) row0   *HD + c0];
        qhi[ks][1] = *(const unsigned int*)&g_qhi[kbase + (size_t)(row0+8)*HD + c0];
        qhi[ks][2] = *(const unsigned int*)&g_qhi[kbase + (size_t) row0   *HD + c0+8];
        qhi[ks][3] = *(const unsigned int*)&g_qhi[kbase + (size_t)(row0+8)*HD + c0+8];
        qlo[ks][0] = *(const unsigned int*)&g_qlo[kbase + (size_t) row0   *HD + c0];
        qlo[ks][1] = *(const unsigned int*)&g_qlo[kbase + (size_t)(row0+8)*HD + c0];
        qlo[ks][2] = *(const unsigned int*)&g_qlo[kbase + (size_t) row0   *HD + c0+8];
        qlo[ks][3] = *(const unsigned int*)&g_qlo[kbase + (size_t)(row0+8)*HD + c0+8];
    }

    float m0 = -INFINITY, m1 = -INFINITY, l0 = 0.f, l1 = 0.f;
    float o[8][4];
    #pragma unroll
    for (int nf = 0; nf < 8; nf++)
        #pragma unroll
        for (int r = 0; r < 4; r++) o[nf][r] = 0.f;

    auto load_tile = [&](int st, int j0) {
        unsigned int sb = smem_u32 + st*(4*TSB);
        #pragma unroll
        for (int t = 0; t < 2; t++) {
            int idx = tid*2 + t;          // 0..511
            int row = idx >> 3;
            int ch  = (idx & 7) * 8;
            unsigned int doff = (unsigned int)(row*72 + ch) * 2;
            CP16(sb +         doff, &g_khi [kbase + (size_t)(j0+row)*HD + ch]);
            CP16(sb +   TSB + doff, &g_klo [kbase + (size_t)(j0+row)*HD + ch]);
            CP16(sb + 2*TSB + doff, &g_vthi[vbase + (size_t)row*SEQ + j0 + ch]);
            CP16(sb + 3*TSB + doff, &g_vtlo[vbase + (size_t)row*SEQ + j0 + ch]);
        }
    };

    load_tile(0, 0); CPCOMMIT;
    int s = 0;

    for (int j0 = 0; j0 < SEQ; j0 += 64) {
        if (j0 + 64 < SEQ) {
            load_tile(s^1, j0+64); CPCOMMIT;
            asm volatile("cp.async.wait_group 1;\n");
        } else {
            asm volatile("cp.async.wait_group 0;\n");
        }
        __syncthreads();

        const unsigned int sK = smem_u32 + s*(4*TSB);
        const unsigned int sV = sK + 2*TSB;

        // ---- S = Q K^T ----
        float sres[8][4];
        #pragma unroll
        for (int nf = 0; nf < 8; nf++)
            #pragma unroll
            for (int r = 0; r < 4; r++) sres[nf][r] = 0.f;

        #pragma unroll
        for (int ks = 0; ks < 4; ks++) {
            #pragma unroll
            for (int p = 0; p < 4; p++) {
                unsigned int rb = sK + (unsigned int)((p*16*72 + ks*16)*2) + aoff;
                unsigned int h0, h1, h2, h3, l0r, l1r, l2r, l3r;
                LDSM4(h0, h1, h2, h3, rb);
                LDSM4(l0r, l1r, l2r, l3r, rb + TSB);
                MMA16816(sres[2*p][0], sres[2*p][1], sres[2*p][2], sres[2*p][3],
                         qhi[ks][0], qhi[ks][1], qhi[ks][2], qhi[ks][3], h0, h2);
                MMA16816(sres[2*p][0], sres[2*p][1], sres[2*p][2], sres[2*p][3],
                         qhi[ks][0], qhi[ks][1], qhi[ks][2], qhi[ks][3], l0r, l2r);
                MMA16816(sres[2*p][0], sres[2*p][1], sres[2*p][2], sres[2*p][3],
                         qlo[ks][0], qlo[ks][1], qlo[ks][2], qlo[ks][3], h0, h2);
                MMA16816(sres[2*p+1][0], sres[2*p+1][1], sres[2*p+1][2], sres[2*p+1][3],
                         qhi[ks][0], qhi[ks][1], qhi[ks][2], qhi[ks][3], h1, h3);
                MMA16816(sres[2*p+1][0], sres[2*p+1][1], sres[2*p+1][2], sres[2*p+1][3],
                         qhi[ks][0], qhi[ks][1], qhi[ks][2], qhi[ks][3], l1r, l3r);
                MMA16816(sres[2*p+1][0], sres[2*p+1][1], sres[2*p+1][2], sres[2*p+1][3],
                         qlo[ks][0], qlo[ks][1], qlo[ks][2], qlo[ks][3], h1, h3);
            }
        }

        // ---- online softmax ----
        float rm0 = -INFINITY, rm1 = -INFINITY;
        #pragma unroll
        for (int nf = 0; nf < 8; nf++) {
            rm0 = fmaxf(rm0, fmaxf(sres[nf][0], sres[nf][1]));
            rm1 = fmaxf(rm1, fmaxf(sres[nf][2], sres[nf][3]));
        }
        rm0 = fmaxf(rm0, __shfl_xor_sync(0xFFFFFFFFu, rm0, 1));
        rm0 = fmaxf(rm0, __shfl_xor_sync(0xFFFFFFFFu, rm0, 2));
        rm1 = fmaxf(rm1, __shfl_xor_sync(0xFFFFFFFFu, rm1, 1));
        rm1 = fmaxf(rm1, __shfl_xor_sync(0xFFFFFFFFu, rm1, 2));
        float mn0 = fmaxf(m0, rm0), mn1 = fmaxf(m1, rm1);
        float al0 = __expf(m0 - mn0), al1 = __expf(m1 - mn1);
        m0 = mn0; m1 = mn1;

        float rs0 = 0.f, rs1 = 0.f;
        #pragma unroll
        for (int nf = 0; nf < 8; nf++) {
            sres[nf][0] = __expf(sres[nf][0] - mn0);
            sres[nf][1] = __expf(sres[nf][1] - mn0);
            sres[nf][2] = __expf(sres[nf][2] - mn1);
            sres[nf][3] = __expf(sres[nf][3] - mn1);
            rs0 += sres[nf][0] + sres[nf][1];
            rs1 += sres[nf][2] + sres[nf][3];
        }
        rs0 += __shfl_xor_sync(0xFFFFFFFFu, rs0, 1);
        rs0 += __shfl_xor_sync(0xFFFFFFFFu, rs0, 2);
        rs1 += __shfl_xor_sync(0xFFFFFFFFu, rs1, 1);
        rs1 += __shfl_xor_sync(0xFFFFFFFFu, rs1, 2);
        l0 = l0*al0 + rs0;
        l1 = l1*al1 + rs1;

        #pragma unroll
        for (int nf = 0; nf < 8; nf++) {
            o[nf][0] *= al0; o[nf][1] *= al0;
            o[nf][2] *= al1; o[nf][3] *= al1;
        }

        // ---- O += P @ V ----
        #pragma unroll
        for (int jj = 0; jj < 4; jj++) {
            unsigned int pah[4], pal[4];
            split2(sres[2*jj  ][0], sres[2*jj  ][1], pah[0], pal[0]);
            split2(sres[2*jj  ][2], sres[2*jj  ][3], pah[1], pal[1]);
            split2(sres[2*jj+1][0], sres[2*jj+1][1], pah[2], pal[2]);
            split2(sres[2*jj+1][2], sres[2*jj+1][3], pah[3], pal[3]);
            #pragma unroll
            for (int p = 0; p < 4; p++) {
                unsigned int rb = sV + (unsigned int)((p*16*72 + jj*16)*2) + aoff;
                unsigned int h0, h1, h2, h3, l0r, l1r, l2r, l3r;
                LDSM4(h0, h1, h2, h3, rb);
                LDSM4(l0r, l1r, l2r, l3r, rb + TSB);
                MMA16816(o[2*p][0], o[2*p][1], o[2*p][2], o[2*p][3],
                         pah[0], pah[1], pah[2], pah[3], h0, h2);
                MMA16816(o[2*p][0], o[2*p][1], o[2*p][2], o[2*p][3],
                         pah[0], pah[1], pah[2], pah[3], l0r, l2r);
                MMA16816(o[2*p][0], o[2*p][1], o[2*p][2], o[2*p][3],
                         pal[0], pal[1], pal[2], pal[3], h0, h2);
                MMA16816(o[2*p+1][0], o[2*p+1][1], o[2*p+1][2], o[2*p+1][3],
                         pah[0], pah[1], pah[2], pah[3], h1, h3);
                MMA16816(o[2*p+1][0], o[2*p+1][1], o[2*p+1][2], o[2*p+1][3],
                         pah[0], pah[1], pah[2], pah[3], l1r, l3r);
                MMA16816(o[2*p+1][0], o[2*p+1][1], o[2*p+1][2], o[2*p+1][3],
                         pal[0], pal[1], pal[2], pal[3], h1, h3);
            }
        }

        s ^= 1;
        __syncthreads();
    }

    // ---- epilogue: normalize, split-store to g_att hi/lo ----
    float inv0 = 1.0f / l0, inv1 = 1.0f / l1;
    int b_ = bh / NHEAD, hh = bh % NHEAD;
    #pragma unroll
    for (int nf = 0; nf < 8; nf++) {
        int col = hh*64 + nf*8 + tig*2;
        size_t i0 = ((size_t)(b_*SEQ + row0  ))*DIMX + col;
        size_t i1 = ((size_t)(b_*SEQ + row0+8))*DIMX + col;
        split_store(o[nf][0]*inv0, o[nf][1]*inv0, &g_atthi[i0], &g_attlo[i0]);
        split_store(o[nf][2]*inv1, o[nf][3]*inv1, &g_atthi[i1], &g_attlo[i1]);
    }
}

// ============================================================
extern "C" void kernel_launch(void* const* d_in, const int* in_sizes, int n_in,
                              void* d_out, int out_size)
{
    const float* x      = (const float*)d_in[0];
    const float* qkv_w  = (const float*)d_in[1];
    const float* qkv_b  = (const float*)d_in[2];
    const float* proj_w = (const float*)d_in[3];
    const float* proj_b = (const float*)d_in[4];
    float* out = (float*)d_out;
    (void)in_sizes; (void)n_in; (void)out_size;

    const int gemm_smem = 2*STAGE_B;           // 81920 B
    const int attn_smem = 2*4*TSB;             // 73728 B
    cudaFuncSetAttribute(gemm_bf16x3<true>,
                         cudaFuncAttributeMaxDynamicSharedMemorySize, gemm_smem);
    cudaFuncSetAttribute(gemm_bf16x3<false>,
                         cudaFuncAttributeMaxDynamicSharedMemorySize, gemm_smem);
    cudaFuncSetAttribute(attn_mma,
                         cudaFuncAttributeMaxDynamicSharedMemorySize, attn_smem);

    // pre-split inputs (destinations are device globals chosen in-kernel)
    {
        int n4 = ROWS_TOT*DIMX/4;
        split_f32<0><<<(n4+255)/256, 256>>>((const float4*)x, n4);
        n4 = 3*DIMX*DIMX/4;
        split_f32<1><<<(n4+255)/256, 256>>>((const float4*)qkv_w, n4);
        n4 = DIMX*DIMX/4;
        split_f32<2><<<(n4+255)/256, 256>>>((const float4*)proj_w, n4);
    }

    dim3 g1(2304/128, ROWS_TOT/128);   // (18, 64)
    gemm_bf16x3<true><<<g1, 256, gemm_smem>>>(qkv_b, nullptr);

    dim3 g2(SEQ/128, BATCH*NHEAD);     // (16, 48)
    attn_mma<<<g2, 256, attn_smem>>>();

    dim3 g3(DIMX/128, ROWS_TOT/128);   // (6, 64)
    gemm_bf16x3<false><<<g3, 256, gemm_smem>>>(proj_b, out);
}

// round 8
// speedup vs baseline: 1.5198x; 1.5198x over previous
#include <cuda_runtime.h>
#include <cuda_bf16.h>
#include <cuda_fp16.h>
#include <cstdint>
#include <cmath>

#define DIMX 768
#define NHEAD 12
#define HD 64
#define BATCH 4
#define SEQ 2048
#define ROWS_TOT (BATCH*SEQ)   /* 8192 */
#define ATTN_SCALE 0.125f
#define BHT (BATCH*NHEAD)

// ---- scratch (allocation-free __device__ globals; device-side access ONLY) ----
__device__ __align__(16) float  g_q[BHT*SEQ*HD];        // tf32-rounded, pre-scaled
__device__ __align__(16) float  g_k[BHT*SEQ*HD];        // tf32-rounded
__device__ __align__(16) __half g_vthi[BHT*HD*SEQ];     // V transposed, fp16 hi
__device__ __align__(16) __half g_vtlo[BHT*HD*SEQ];     // V transposed, fp16 lo
__device__ __align__(16) float  g_att[ROWS_TOT*DIMX];   // attention output

// ---- mma.sync m16n8k8 tf32 (row.col), fp32 accum ----
#define MMA_TF32(d0,d1,d2,d3,a0,a1,a2,a3,b0,b1)                              \
  asm volatile("mma.sync.aligned.m16n8k8.row.col.f32.tf32.tf32.f32 "         \
               "{%0,%1,%2,%3}, {%4,%5,%6,%7}, {%8,%9}, {%0,%1,%2,%3};\n"     \
               : "+f"(d0), "+f"(d1), "+f"(d2), "+f"(d3)                      \
               : "r"(a0), "r"(a1), "r"(a2), "r"(a3), "r"(b0), "r"(b1))

// ---- mma.sync m16n8k16 fp16 (row.col), fp32 accum ----
#define MMA_F16(d0,d1,d2,d3,a0,a1,a2,a3,b0,b1)                               \
  asm volatile("mma.sync.aligned.m16n8k16.row.col.f32.f16.f16.f32 "          \
               "{%0,%1,%2,%3}, {%4,%5,%6,%7}, {%8,%9}, {%0,%1,%2,%3};\n"     \
               : "+f"(d0), "+f"(d1), "+f"(d2), "+f"(d3)                      \
               : "r"(a0), "r"(a1), "r"(a2), "r"(a3), "r"(b0), "r"(b1))

#define CP16(d, s)                                                            \
  asm volatile("cp.async.cg.shared.global [%0], [%1], 16;\n"                  \
               :: "r"(d), "l"(s))
#define CPCOMMIT asm volatile("cp.async.commit_group;\n")

// round fp32 -> tf32 (rne) keeping fp32 bit container
__device__ __forceinline__ float tf32r(float x)
{
    unsigned u;
    asm("cvt.rna.tf32.f32 %0, %1;" : "=r"(u) : "f"(x));
    return __uint_as_float(u);
}

__device__ __forceinline__ void split1h(float x, __half &h, __half &l)
{
    h = __float2half_rn(x);
    l = __float2half_rn(x - __half2float(h));
}

// ============================================================
// tf32 GEMM: C[m,j] = sum_k A[m,k]*W[j,k] + bias[j]
// BM=128 BN=128 BK=32, 256 thr, warp grid 2(m)x4(n), 64x32/warp.
// Register-prefetch double-buffered smem (R4 scheme).
// QKV=true: scatter Q(scaled,tf32)/K(tf32)/V(fp16 hi/lo, transposed).
// ============================================================
#define SA 36                     /* smem row stride (floats), conflict-free */
#define GS_ARR (128*SA)           /* floats per array */
#define GS_STG (2*GS_ARR)         /* A|B per stage    */

template<bool QKV>
__global__ __launch_bounds__(256) void gemm_tf32(const float* __restrict__ Ain,
                                                 const float* __restrict__ W,
                                                 const float* __restrict__ bias,
                                                 float* __restrict__ out)
{
    const float* __restrict__ A = QKV ? Ain : (const float*)g_att;

    extern __shared__ float smg[];

    const int tid  = threadIdx.x;
    const int lane = tid & 31;
    const int w    = tid >> 5;
    const int g    = lane >> 2;
    const int tig  = lane & 3;
    const int wm   = w & 1;
    const int wn   = w >> 1;
    const int bm   = blockIdx.y * 128;
    const int bn   = blockIdx.x * 128;

    float acc[4][4][4];
    #pragma unroll
    for (int i = 0; i < 4; i++)
        #pragma unroll
        for (int j = 0; j < 4; j++)
            #pragma unroll
            for (int r = 0; r < 4; r++) acc[i][j][r] = 0.f;

    float4 ra[4], rb[4];
    #pragma unroll
    for (int t = 0; t < 4; t++) {
        int idx = tid + t*256;
        int m  = idx >> 3;
        int kq = (idx & 7) * 4;
        ra[t] = *(const float4*)&A[(size_t)(bm+m)*DIMX + kq];
        rb[t] = *(const float4*)&W[(size_t)(bn+m)*DIMX + kq];
    }

    int s = 0;
    for (int k0 = 0; k0 < DIMX; k0 += 32) {
        float* As = smg + s*GS_STG;
        float* Bs = As + GS_ARR;

        #pragma unroll
        for (int t = 0; t < 4; t++) {
            int idx = tid + t*256;
            int m  = idx >> 3;
            int kq = (idx & 7) * 4;
            float4 ca = make_float4(tf32r(ra[t].x), tf32r(ra[t].y),
                                    tf32r(ra[t].z), tf32r(ra[t].w));
            float4 cb = make_float4(tf32r(rb[t].x), tf32r(rb[t].y),
                                    tf32r(rb[t].z), tf32r(rb[t].w));
            *(float4*)&As[m*SA + kq] = ca;
            *(float4*)&Bs[m*SA + kq] = cb;
        }
        __syncthreads();

        if (k0 + 32 < DIMX) {
            #pragma unroll
            for (int t = 0; t < 4; t++) {
                int idx = tid + t*256;
                int m  = idx >> 3;
                int kq = (idx & 7) * 4;
                ra[t] = *(const float4*)&A[(size_t)(bm+m)*DIMX + k0+32 + kq];
                rb[t] = *(const float4*)&W[(size_t)(bn+m)*DIMX + k0+32 + kq];
            }
        }

        #pragma unroll
        for (int ks = 0; ks < 32; ks += 8) {
            unsigned af[4][4];
            #pragma unroll
            for (int mf = 0; mf < 4; mf++) {
                int rm = wm*64 + mf*16 + g;
                af[mf][0] = __float_as_uint(As[ rm   *SA + ks + tig    ]);
                af[mf][1] = __float_as_uint(As[(rm+8)*SA + ks + tig    ]);
                af[mf][2] = __float_as_uint(As[ rm   *SA + ks + tig + 4]);
                af[mf][3] = __float_as_uint(As[(rm+8)*SA + ks + tig + 4]);
            }
            #pragma unroll
            for (int nf = 0; nf < 4; nf++) {
                int n = wn*32 + nf*8 + g;
                unsigned b0 = __float_as_uint(Bs[n*SA + ks + tig    ]);
                unsigned b1 = __float_as_uint(Bs[n*SA + ks + tig + 4]);
                #pragma unroll
                for (int mf = 0; mf < 4; mf++)
                    MMA_TF32(acc[mf][nf][0], acc[mf][nf][1],
                             acc[mf][nf][2], acc[mf][nf][3],
                             af[mf][0], af[mf][1], af[mf][2], af[mf][3], b0, b1);
            }
        }
        s ^= 1;
        __syncthreads();
    }

    // ---- epilogue ----
    #pragma unroll
    for (int nf = 0; nf < 4; nf++) {
        int col = bn + wn*32 + nf*8 + tig*2;
        float bx = bias[col], by = bias[col+1];
        if (QKV) {
            int c  = col / DIMX;            // 0=Q 1=K 2=V
            int hh = (col % DIMX) >> 6;
            int dd = col & 63;
            #pragma unroll
            for (int mf = 0; mf < 4; mf++)
                #pragma unroll
                for (int h2 = 0; h2 < 2; h2++) {
                    int row = bm + wm*64 + mf*16 + g + h2*8;
                    int b_ = row >> 11, n_ = row & 2047;
                    float vx = acc[mf][nf][h2*2+0] + bx;
                    float vy = acc[mf][nf][h2*2+1] + by;
                    if (c == 0) {
                        size_t idx = (((size_t)(b_*NHEAD + hh))*SEQ + n_)*HD + dd;
                        *(float2*)&g_q[idx] =
                            make_float2(tf32r(vx*ATTN_SCALE), tf32r(vy*ATTN_SCALE));
                    } else if (c == 1) {
                        size_t idx = (((size_t)(b_*NHEAD + hh))*SEQ + n_)*HD + dd;
                        *(float2*)&g_k[idx] = make_float2(tf32r(vx), tf32r(vy));
                    } else {
                        size_t idx = (((size_t)(b_*NHEAD + hh))*HD + dd)*SEQ + n_;
                        split1h(vx, g_vthi[idx],     g_vtlo[idx]);
                        split1h(vy, g_vthi[idx+SEQ], g_vtlo[idx+SEQ]);
                    }
                }
        } else {
            #pragma unroll
            for (int mf = 0; mf < 4; mf++)
                #pragma unroll
                for (int h2 = 0; h2 < 2; h2++) {
                    int row = bm + wm*64 + mf*16 + g + h2*8;
                    float2 v = make_float2(acc[mf][nf][h2*2+0] + bx,
                                           acc[mf][nf][h2*2+1] + by);
                    *(float2*)&out[(size_t)row*DIMX + col] = v;
                }
        }
    }
}

// ============================================================
// Flash attention: QK^T in tf32 (m16n8k8), PV in fp16 2-term
// (m16n8k16, C-frag == A-frag layout). cp.async double buffer.
// Block = (b*h, 128 q rows), 8 warps, 16 rows/warp.
// ============================================================
#define KS_STRIDE 68                       /* floats per K row  */
#define VT_STRIDE 72                       /* halves per Vt row */
#define K_BYTES   (64*KS_STRIDE*4)         /* 17408 */
#define V_BYTES   (64*VT_STRIDE*2)         /* 9216  */
#define AT_STG    (K_BYTES + 2*V_BYTES)    /* 35840 per stage */
#define AT_SMEM   (2*AT_STG)               /* 71680 */

__global__ __launch_bounds__(256) void attn_mma()
{
    extern __shared__ char sma[];
    const unsigned smem_u32 = (unsigned)__cvta_generic_to_shared(sma);

    const int tid  = threadIdx.x;
    const int lane = tid & 31;
    const int w    = tid >> 5;
    const int g    = lane >> 2;
    const int tig  = lane & 3;
    const int bh   = blockIdx.y;
    const int q0   = blockIdx.x * 128;
    const size_t kbase = (size_t)bh * SEQ * HD;
    const size_t vbase = (size_t)bh * HD * SEQ;
    const int row0 = q0 + w*16 + g;

    // Q fragments: 8 k-steps x 4 regs (tf32-rounded, pre-scaled in gmem)
    unsigned qf[8][4];
    #pragma unroll
    for (int ks = 0; ks < 8; ks++) {
        int c0 = ks*8 + tig;
        qf[ks][0] = __float_as_uint(g_q[kbase + (size_t) row0   *HD + c0    ]);
        qf[ks][1] = __float_as_uint(g_q[kbase + (size_t)(row0+8)*HD + c0    ]);
        qf[ks][2] = __float_as_uint(g_q[kbase + (size_t) row0   *HD + c0 + 4]);
        qf[ks][3] = __float_as_uint(g_q[kbase + (size_t)(row0+8)*HD + c0 + 4]);
    }

    float m0 = -INFINITY, m1 = -INFINITY, l0 = 0.f, l1 = 0.f;
    float o[8][4];
    #pragma unroll
    for (int nf = 0; nf < 8; nf++)
        #pragma unroll
        for (int r = 0; r < 4; r++) o[nf][r] = 0.f;

    auto load_tile = [&](int st, int j0) {
        unsigned sb = smem_u32 + (unsigned)st*AT_STG;
        // K: 64 rows x 64 fp32 (1024 16B chunks)
        #pragma unroll
        for (int t = 0; t < 4; t++) {
            int idx = tid + t*256;
            int row = idx >> 4;
            int c4  = (idx & 15) * 4;
            CP16(sb + (unsigned)(row*KS_STRIDE + c4)*4u,
                 &g_k[kbase + (size_t)(j0+row)*HD + c4]);
        }
        // V hi/lo: 64 d-rows x 64 fp16 each (512 chunks each)
        unsigned vb = sb + K_BYTES;
        #pragma unroll
        for (int t = 0; t < 2; t++) {
            int idx = tid + t*256;
            int d   = idx >> 3;
            int c8  = (idx & 7) * 8;
            unsigned doff = (unsigned)(d*VT_STRIDE + c8)*2u;
            CP16(vb +           doff, &g_vthi[vbase + (size_t)d*SEQ + j0 + c8]);
            CP16(vb + V_BYTES + doff, &g_vtlo[vbase + (size_t)d*SEQ + j0 + c8]);
        }
    };

    load_tile(0, 0); CPCOMMIT;
    int s = 0;

    for (int j0 = 0; j0 < SEQ; j0 += 64) {
        if (j0 + 64 < SEQ) {
            load_tile(s^1, j0+64); CPCOMMIT;
            asm volatile("cp.async.wait_group 1;\n");
        } else {
            asm volatile("cp.async.wait_group 0;\n");
        }
        __syncthreads();

        const float*  Ks = (const float*)(sma + s*AT_STG);
        const __half* Vh = (const __half*)(sma + s*AT_STG + K_BYTES);
        const __half* Vl = (const __half*)(sma + s*AT_STG + K_BYTES + V_BYTES);

        // ---- S = Q K^T (tf32) ----
        float sres[8][4];
        #pragma unroll
        for (int nf = 0; nf < 8; nf++)
            #pragma unroll
            for (int r = 0; r < 4; r++) sres[nf][r] = 0.f;

        #pragma unroll
        for (int ks = 0; ks < 8; ks++) {
            #pragma unroll
            for (int nf = 0; nf < 8; nf++) {
                int kv = nf*8 + g;
                unsigned b0 = __float_as_uint(Ks[kv*KS_STRIDE + ks*8 + tig    ]);
                unsigned b1 = __float_as_uint(Ks[kv*KS_STRIDE + ks*8 + tig + 4]);
                MMA_TF32(sres[nf][0], sres[nf][1], sres[nf][2], sres[nf][3],
                         qf[ks][0], qf[ks][1], qf[ks][2], qf[ks][3], b0, b1);
            }
        }

        // ---- online softmax ----
        float rm0 = -INFINITY, rm1 = -INFINITY;
        #pragma unroll
        for (int nf = 0; nf < 8; nf++) {
            rm0 = fmaxf(rm0, fmaxf(sres[nf][0], sres[nf][1]));
            rm1 = fmaxf(rm1, fmaxf(sres[nf][2], sres[nf][3]));
        }
        rm0 = fmaxf(rm0, __shfl_xor_sync(0xFFFFFFFFu, rm0, 1));
        rm0 = fmaxf(rm0, __shfl_xor_sync(0xFFFFFFFFu, rm0, 2));
        rm1 = fmaxf(rm1, __shfl_xor_sync(0xFFFFFFFFu, rm1, 1));
        rm1 = fmaxf(rm1, __shfl_xor_sync(0xFFFFFFFFu, rm1, 2));
        float mn0 = fmaxf(m0, rm0), mn1 = fmaxf(m1, rm1);
        float al0 = __expf(m0 - mn0), al1 = __expf(m1 - mn1);
        m0 = mn0; m1 = mn1;

        float rs0 = 0.f, rs1 = 0.f;
        #pragma unroll
        for (int nf = 0; nf < 8; nf++) {
            sres[nf][0] = __expf(sres[nf][0] - mn0);
            sres[nf][1] = __expf(sres[nf][1] - mn0);
            sres[nf][2] = __expf(sres[nf][2] - mn1);
            sres[nf][3] = __expf(sres[nf][3] - mn1);
            rs0 += sres[nf][0] + sres[nf][1];
            rs1 += sres[nf][2] + sres[nf][3];
        }
        rs0 += __shfl_xor_sync(0xFFFFFFFFu, rs0, 1);
        rs0 += __shfl_xor_sync(0xFFFFFFFFu, rs0, 2);
        rs1 += __shfl_xor_sync(0xFFFFFFFFu, rs1, 1);
        rs1 += __shfl_xor_sync(0xFFFFFFFFu, rs1, 2);
        l0 = l0*al0 + rs0;
        l1 = l1*al1 + rs1;

        #pragma unroll
        for (int nf = 0; nf < 8; nf++) {
            o[nf][0] *= al0; o[nf][1] *= al0;
            o[nf][2] *= al1; o[nf][3] *= al1;
        }

        // ---- O += P @ V  (fp16 2-term; C-frag -> A-frag direct) ----
        #pragma unroll
        for (int jj = 0; jj < 4; jj++) {
            __half2 ph[4];
            ph[0] = __floats2half2_rn(sres[2*jj  ][0], sres[2*jj  ][1]);
            ph[1] = __floats2half2_rn(sres[2*jj  ][2], sres[2*jj  ][3]);
            ph[2] = __floats2half2_rn(sres[2*jj+1][0], sres[2*jj+1][1]);
            ph[3] = __floats2half2_rn(sres[2*jj+1][2], sres[2*jj+1][3]);
            unsigned pa0 = *reinterpret_cast<unsigned*>(&ph[0]);
            unsigned pa1 = *reinterpret_cast<unsigned*>(&ph[1]);
            unsigned pa2 = *reinterpret_cast<unsigned*>(&ph[2]);
            unsigned pa3 = *reinterpret_cast<unsigned*>(&ph[3]);
            int kc = jj*16 + tig*2;
            #pragma unroll
            for (int nf = 0; nf < 8; nf++) {
                int d = nf*8 + g;
                unsigned v0h = *(const unsigned*)&Vh[d*VT_STRIDE + kc    ];
                unsigned v1h = *(const unsigned*)&Vh[d*VT_STRIDE + kc + 8];
                unsigned v0l = *(const unsigned*)&Vl[d*VT_STRIDE + kc    ];
                unsigned v1l = *(const unsigned*)&Vl[d*VT_STRIDE + kc + 8];
                MMA_F16(o[nf][0], o[nf][1], o[nf][2], o[nf][3],
                        pa0, pa1, pa2, pa3, v0h, v1h);
                MMA_F16(o[nf][0], o[nf][1], o[nf][2], o[nf][3],
                        pa0, pa1, pa2, pa3, v0l, v1l);
            }
        }

        s ^= 1;
        __syncthreads();
    }

    // ---- epilogue: normalize, write g_att ----
    float inv0 = 1.0f / l0, inv1 = 1.0f / l1;
    int b_ = bh / NHEAD, hh = bh % NHEAD;
    #pragma unroll
    for (int nf = 0; nf < 8; nf++) {
        int col = hh*64 + nf*8 + tig*2;
        *(float2*)&g_att[((size_t)(b_*SEQ + row0  ))*DIMX + col] =
            make_float2(o[nf][0]*inv0, o[nf][1]*inv0);
        *(float2*)&g_att[((size_t)(b_*SEQ + row0+8))*DIMX + col] =
            make_float2(o[nf][2]*inv1, o[nf][3]*inv1);
    }
}

// ============================================================
extern "C" void kernel_launch(void* const* d_in, const int* in_sizes, int n_in,
                              void* d_out, int out_size)
{
    const float* x      = (const float*)d_in[0];
    const float* qkv_w  = (const float*)d_in[1];
    const float* qkv_b  = (const float*)d_in[2];
    const float* proj_w = (const float*)d_in[3];
    const float* proj_b = (const float*)d_in[4];
    float* out = (float*)d_out;
    (void)in_sizes; (void)n_in; (void)out_size;

    const int gemm_smem = 2*GS_STG*4;          // 73728 B
    cudaFuncSetAttribute(gemm_tf32<true>,
                         cudaFuncAttributeMaxDynamicSharedMemorySize, gemm_smem);
    cudaFuncSetAttribute(gemm_tf32<false>,
                         cudaFuncAttributeMaxDynamicSharedMemorySize, gemm_smem);
    cudaFuncSetAttribute(attn_mma,
                         cudaFuncAttributeMaxDynamicSharedMemorySize, AT_SMEM);

    dim3 g1(2304/128, ROWS_TOT/128);   // (18, 64)
    gemm_tf32<true><<<g1, 256, gemm_smem>>>(x, qkv_w, qkv_b, nullptr);

    dim3 g2(SEQ/128, BATCH*NHEAD);     // (16, 48)
    attn_mma<<<g2, 256, AT_SMEM>>>();

    dim3 g3(DIMX/128, ROWS_TOT/128);   // (6, 64)
    gemm_tf32<false><<<g3, 256, gemm_smem>>>(nullptr, proj_w, proj_b, out);
}

// round 9
// speedup vs baseline: 1.6237x; 1.0683x over previous
#include <cuda_runtime.h>
#include <cuda_fp16.h>
#include <cstdint>
#include <cmath>

#define DIMX 768
#define NHEAD 12
#define HD 64
#define BATCH 4
#define SEQ 2048
#define ROWS_TOT (BATCH*SEQ)   /* 8192 */
#define ATTN_SCALE 0.125f
#define BHT (BATCH*NHEAD)

// ---- scratch (allocation-free __device__ globals; device-side access ONLY) ----
__device__ __align__(16) float  g_x32[ROWS_TOT*DIMX];   // x, tf32-rounded
__device__ __align__(16) float  g_w132[3*DIMX*DIMX];    // qkv_w, tf32-rounded
__device__ __align__(16) float  g_w232[DIMX*DIMX];      // proj_w, tf32-rounded
__device__ __align__(16) float  g_q[BHT*SEQ*HD];        // tf32-rounded, pre-scaled
__device__ __align__(16) float  g_k[BHT*SEQ*HD];        // tf32-rounded
__device__ __align__(16) __half g_vthi[BHT*HD*SEQ];     // V transposed, fp16 hi
__device__ __align__(16) __half g_vtlo[BHT*HD*SEQ];     // V transposed, fp16 lo
__device__ __align__(16) float  g_att[ROWS_TOT*DIMX];   // attn out, tf32-rounded

// ---- mma.sync m16n8k8 tf32 (row.col), fp32 accum ----
#define MMA_TF32(d0,d1,d2,d3,a0,a1,a2,a3,b0,b1)                              \
  asm volatile("mma.sync.aligned.m16n8k8.row.col.f32.tf32.tf32.f32 "         \
               "{%0,%1,%2,%3}, {%4,%5,%6,%7}, {%8,%9}, {%0,%1,%2,%3};\n"     \
               : "+f"(d0), "+f"(d1), "+f"(d2), "+f"(d3)                      \
               : "r"(a0), "r"(a1), "r"(a2), "r"(a3), "r"(b0), "r"(b1))

// ---- mma.sync m16n8k16 fp16 (row.col), fp32 accum ----
#define MMA_F16(d0,d1,d2,d3,a0,a1,a2,a3,b0,b1)                               \
  asm volatile("mma.sync.aligned.m16n8k16.row.col.f32.f16.f16.f32 "          \
               "{%0,%1,%2,%3}, {%4,%5,%6,%7}, {%8,%9}, {%0,%1,%2,%3};\n"     \
               : "+f"(d0), "+f"(d1), "+f"(d2), "+f"(d3)                      \
               : "r"(a0), "r"(a1), "r"(a2), "r"(a3), "r"(b0), "r"(b1))

#define CP16(d, s)                                                            \
  asm volatile("cp.async.cg.shared.global [%0], [%1], 16;\n"                  \
               :: "r"(d), "l"(s))
#define CPCOMMIT asm volatile("cp.async.commit_group;\n")

// round fp32 -> tf32 (rne) keeping fp32 bit container
__device__ __forceinline__ float tf32r(float x)
{
    unsigned u;
    asm("cvt.rna.tf32.f32 %0, %1;" : "=r"(u) : "f"(x));
    return __uint_as_float(u);
}

__device__ __forceinline__ void split1h(float x, __half &h, __half &l)
{
    h = __float2half_rn(x);
    l = __float2half_rn(x - __half2float(h));
}

// ============================================================
// fp32 -> tf32-rounded fp32 (vectorized). WHICH: 0->x 1->qkv_w 2->proj_w
// ============================================================
template<int WHICH>
__global__ void cvt_tf32(const float4* __restrict__ src, int n4)
{
    float4* dst = (WHICH == 0) ? (float4*)g_x32
                : (WHICH == 1) ? (float4*)g_w132
                               : (float4*)g_w232;
    int i = blockIdx.x*blockDim.x + threadIdx.x;
    if (i >= n4) return;
    float4 v = src[i];
    dst[i] = make_float4(tf32r(v.x), tf32r(v.y), tf32r(v.z), tf32r(v.w));
}

// ============================================================
// tf32 GEMM: C[m,j] = sum_k A[m,k]*W[j,k] + bias[j]
// BM=128 BN=128 BK=32, 256 thr, 2 CTAs/SM (launch_bounds),
// cp.async 2-stage double buffer, inputs pre-rounded to tf32.
// QKV=true: scatter Q(scaled)/K/V(fp16 hi/lo, transposed).
// ============================================================
#define SA 36                         /* smem row stride (floats) */
#define GS_ARR (128*SA)               /* floats per array  */
#define GS_STG (2*GS_ARR)             /* A|B per stage     */
#define GS_STG_B (GS_STG*4)           /* bytes per stage   */
#define GS_AB_OFF (GS_ARR*4)          /* B offset in stage */
#define NKT (DIMX/32)                 /* 24 k-tiles        */

template<bool QKV>
__global__ __launch_bounds__(256, 2) void gemm_tf32(const float* __restrict__ bias,
                                                    float* __restrict__ out)
{
    const float* __restrict__ A = QKV ? g_x32  : g_att;
    const float* __restrict__ B = QKV ? g_w132 : g_w232;

    extern __shared__ float smg[];
    const unsigned smem_u32 = (unsigned)__cvta_generic_to_shared(smg);

    const int tid  = threadIdx.x;
    const int lane = tid & 31;
    const int w    = tid >> 5;
    const int g    = lane >> 2;
    const int tig  = lane & 3;
    const int wm   = w & 1;
    const int wn   = w >> 1;
    const int bm   = blockIdx.y * 128;
    const int bn   = blockIdx.x * 128;

    float acc[4][4][4];
    #pragma unroll
    for (int i = 0; i < 4; i++)
        #pragma unroll
        for (int j = 0; j < 4; j++)
            #pragma unroll
            for (int r = 0; r < 4; r++) acc[i][j][r] = 0.f;

    auto load_stage = [&](int st, int k0) {
        unsigned base = smem_u32 + (unsigned)st*GS_STG_B;
        #pragma unroll
        for (int t = 0; t < 4; t++) {
            int idx = tid + t*256;        // 0..1023
            int row = idx >> 3;
            int c4  = (idx & 7) * 4;
            unsigned doff = (unsigned)(row*SA + c4)*4u;
            CP16(base +             doff, &A[(size_t)(bm+row)*DIMX + k0 + c4]);
            CP16(base + GS_AB_OFF + doff, &B[(size_t)(bn+row)*DIMX + k0 + c4]);
        }
    };

    load_stage(0, 0);  CPCOMMIT;
    load_stage(1, 32); CPCOMMIT;

    for (int kt = 0; kt < NKT; kt++) {
        const int s = kt & 1;
        if (kt < NKT-1) asm volatile("cp.async.wait_group 1;\n");
        else            asm volatile("cp.async.wait_group 0;\n");
        __syncthreads();

        const float* As = smg + s*GS_STG;
        const float* Bs = As + GS_ARR;

        #pragma unroll
        for (int ks = 0; ks < 32; ks += 8) {
            unsigned af[4][4];
            #pragma unroll
            for (int mf = 0; mf < 4; mf++) {
                int rm = wm*64 + mf*16 + g;
                af[mf][0] = __float_as_uint(As[ rm   *SA + ks + tig    ]);
                af[mf][1] = __float_as_uint(As[(rm+8)*SA + ks + tig    ]);
                af[mf][2] = __float_as_uint(As[ rm   *SA + ks + tig + 4]);
                af[mf][3] = __float_as_uint(As[(rm+8)*SA + ks + tig + 4]);
            }
            #pragma unroll
            for (int nf = 0; nf < 4; nf++) {
                int n = wn*32 + nf*8 + g;
                unsigned b0 = __float_as_uint(Bs[n*SA + ks + tig    ]);
                unsigned b1 = __float_as_uint(Bs[n*SA + ks + tig + 4]);
                #pragma unroll
                for (int mf = 0; mf < 4; mf++)
                    MMA_TF32(acc[mf][nf][0], acc[mf][nf][1],
                             acc[mf][nf][2], acc[mf][nf][3],
                             af[mf][0], af[mf][1], af[mf][2], af[mf][3], b0, b1);
            }
        }
        __syncthreads();

        if (kt + 2 < NKT) {
            load_stage(s, (kt+2)*32);
            CPCOMMIT;
        }
    }

    // ---- epilogue ----
    #pragma unroll
    for (int nf = 0; nf < 4; nf++) {
        int col = bn + wn*32 + nf*8 + tig*2;
        float bx = bias[col], by = bias[col+1];
        if (QKV) {
            int c  = col / DIMX;            // 0=Q 1=K 2=V
            int hh = (col % DIMX) >> 6;
            int dd = col & 63;
            #pragma unroll
            for (int mf = 0; mf < 4; mf++)
                #pragma unroll
                for (int h2 = 0; h2 < 2; h2++) {
                    int row = bm + wm*64 + mf*16 + g + h2*8;
                    int b_ = row >> 11, n_ = row & 2047;
                    float vx = acc[mf][nf][h2*2+0] + bx;
                    float vy = acc[mf][nf][h2*2+1] + by;
                    if (c == 0) {
                        size_t idx = (((size_t)(b_*NHEAD + hh))*SEQ + n_)*HD + dd;
                        *(float2*)&g_q[idx] =
                            make_float2(tf32r(vx*ATTN_SCALE), tf32r(vy*ATTN_SCALE));
                    } else if (c == 1) {
                        size_t idx = (((size_t)(b_*NHEAD + hh))*SEQ + n_)*HD + dd;
                        *(float2*)&g_k[idx] = make_float2(tf32r(vx), tf32r(vy));
                    } else {
                        size_t idx = (((size_t)(b_*NHEAD + hh))*HD + dd)*SEQ + n_;
                        split1h(vx, g_vthi[idx],     g_vtlo[idx]);
                        split1h(vy, g_vthi[idx+SEQ], g_vtlo[idx+SEQ]);
                    }
                }
        } else {
            #pragma unroll
            for (int mf = 0; mf < 4; mf++)
                #pragma unroll
                for (int h2 = 0; h2 < 2; h2++) {
                    int row = bm + wm*64 + mf*16 + g + h2*8;
                    float2 v = make_float2(acc[mf][nf][h2*2+0] + bx,
                                           acc[mf][nf][h2*2+1] + by);
                    *(float2*)&out[(size_t)row*DIMX + col] = v;
                }
        }
    }
}

// ============================================================
// Flash attention (R8 proven): QK^T tf32 m16n8k8, PV fp16 2-term.
// cp.async double buffer. Block = (b*h, 128 q rows), 8 warps.
// Epilogue writes tf32-rounded g_att (proj reads it raw).
// ============================================================
#define KS_STRIDE 68                       /* floats per K row  */
#define VT_STRIDE 72                       /* halves per Vt row */
#define K_BYTES   (64*KS_STRIDE*4)         /* 17408 */
#define V_BYTES   (64*VT_STRIDE*2)         /* 9216  */
#define AT_STG    (K_BYTES + 2*V_BYTES)    /* 35840 per stage */
#define AT_SMEM   (2*AT_STG)               /* 71680 */

__global__ __launch_bounds__(256) void attn_mma()
{
    extern __shared__ char sma[];
    const unsigned smem_u32 = (unsigned)__cvta_generic_to_shared(sma);

    const int tid  = threadIdx.x;
    const int lane = tid & 31;
    const int w    = tid >> 5;
    const int g    = lane >> 2;
    const int tig  = lane & 3;
    const int bh   = blockIdx.y;
    const int q0   = blockIdx.x * 128;
    const size_t kbase = (size_t)bh * SEQ * HD;
    const size_t vbase = (size_t)bh * HD * SEQ;
    const int row0 = q0 + w*16 + g;

    // Q fragments: 8 k-steps x 4 regs (tf32-rounded, pre-scaled in gmem)
    unsigned qf[8][4];
    #pragma unroll
    for (int ks = 0; ks < 8; ks++) {
        int c0 = ks*8 + tig;
        qf[ks][0] = __float_as_uint(g_q[kbase + (size_t) row0   *HD + c0    ]);
        qf[ks][1] = __float_as_uint(g_q[kbase + (size_t)(row0+8)*HD + c0    ]);
        qf[ks][2] = __float_as_uint(g_q[kbase + (size_t) row0   *HD + c0 + 4]);
        qf[ks][3] = __float_as_uint(g_q[kbase + (size_t)(row0+8)*HD + c0 + 4]);
    }

    float m0 = -INFINITY, m1 = -INFINITY, l0 = 0.f, l1 = 0.f;
    float o[8][4];
    #pragma unroll
    for (int nf = 0; nf < 8; nf++)
        #pragma unroll
        for (int r = 0; r < 4; r++) o[nf][r] = 0.f;

    auto load_tile = [&](int st, int j0) {
        unsigned sb = smem_u32 + (unsigned)st*AT_STG;
        #pragma unroll
        for (int t = 0; t < 4; t++) {
            int idx = tid + t*256;
            int row = idx >> 4;
            int c4  = (idx & 15) * 4;
            CP16(sb + (unsigned)(row*KS_STRIDE + c4)*4u,
                 &g_k[kbase + (size_t)(j0+row)*HD + c4]);
        }
        unsigned vb = sb + K_BYTES;
        #pragma unroll
        for (int t = 0; t < 2; t++) {
            int idx = tid + t*256;
            int d   = idx >> 3;
            int c8  = (idx & 7) * 8;
            unsigned doff = (unsigned)(d*VT_STRIDE + c8)*2u;
            CP16(vb +           doff, &g_vthi[vbase + (size_t)d*SEQ + j0 + c8]);
            CP16(vb + V_BYTES + doff, &g_vtlo[vbase + (size_t)d*SEQ + j0 + c8]);
        }
    };

    load_tile(0, 0); CPCOMMIT;
    int s = 0;

    for (int j0 = 0; j0 < SEQ; j0 += 64) {
        if (j0 + 64 < SEQ) {
            load_tile(s^1, j0+64); CPCOMMIT;
            asm volatile("cp.async.wait_group 1;\n");
        } else {
            asm volatile("cp.async.wait_group 0;\n");
        }
        __syncthreads();

        const float*  Ks = (const float*)(sma + s*AT_STG);
        const __half* Vh = (const __half*)(sma + s*AT_STG + K_BYTES);
        const __half* Vl = (const __half*)(sma + s*AT_STG + K_BYTES + V_BYTES);

        // ---- S = Q K^T (tf32) ----
        float sres[8][4];
        #pragma unroll
        for (int nf = 0; nf < 8; nf++)
            #pragma unroll
            for (int r = 0; r < 4; r++) sres[nf][r] = 0.f;

        #pragma unroll
        for (int ks = 0; ks < 8; ks++) {
            #pragma unroll
            for (int nf = 0; nf < 8; nf++) {
                int kv = nf*8 + g;
                unsigned b0 = __float_as_uint(Ks[kv*KS_STRIDE + ks*8 + tig    ]);
                unsigned b1 = __float_as_uint(Ks[kv*KS_STRIDE + ks*8 + tig + 4]);
                MMA_TF32(sres[nf][0], sres[nf][1], sres[nf][2], sres[nf][3],
                         qf[ks][0], qf[ks][1], qf[ks][2], qf[ks][3], b0, b1);
            }
        }

        // ---- online softmax ----
        float rm0 = -INFINITY, rm1 = -INFINITY;
        #pragma unroll
        for (int nf = 0; nf < 8; nf++) {
            rm0 = fmaxf(rm0, fmaxf(sres[nf][0], sres[nf][1]));
            rm1 = fmaxf(rm1, fmaxf(sres[nf][2], sres[nf][3]));
        }
        rm0 = fmaxf(rm0, __shfl_xor_sync(0xFFFFFFFFu, rm0, 1));
        rm0 = fmaxf(rm0, __shfl_xor_sync(0xFFFFFFFFu, rm0, 2));
        rm1 = fmaxf(rm1, __shfl_xor_sync(0xFFFFFFFFu, rm1, 1));
        rm1 = fmaxf(rm1, __shfl_xor_sync(0xFFFFFFFFu, rm1, 2));
        float mn0 = fmaxf(m0, rm0), mn1 = fmaxf(m1, rm1);
        float al0 = __expf(m0 - mn0), al1 = __expf(m1 - mn1);
        m0 = mn0; m1 = mn1;

        float rs0 = 0.f, rs1 = 0.f;
        #pragma unroll
        for (int nf = 0; nf < 8; nf++) {
            sres[nf][0] = __expf(sres[nf][0] - mn0);
            sres[nf][1] = __expf(sres[nf][1] - mn0);
            sres[nf][2] = __expf(sres[nf][2] - mn1);
            sres[nf][3] = __expf(sres[nf][3] - mn1);
            rs0 += sres[nf][0] + sres[nf][1];
            rs1 += sres[nf][2] + sres[nf][3];
        }
        rs0 += __shfl_xor_sync(0xFFFFFFFFu, rs0, 1);
        rs0 += __shfl_xor_sync(0xFFFFFFFFu, rs0, 2);
        rs1 += __shfl_xor_sync(0xFFFFFFFFu, rs1, 1);
        rs1 += __shfl_xor_sync(0xFFFFFFFFu, rs1, 2);
        l0 = l0*al0 + rs0;
        l1 = l1*al1 + rs1;

        #pragma unroll
        for (int nf = 0; nf < 8; nf++) {
            o[nf][0] *= al0; o[nf][1] *= al0;
            o[nf][2] *= al1; o[nf][3] *= al1;
        }

        // ---- O += P @ V  (fp16 2-term; C-frag -> A-frag direct) ----
        #pragma unroll
        for (int jj = 0; jj < 4; jj++) {
            __half2 ph[4];
            ph[0] = __floats2half2_rn(sres[2*jj  ][0], sres[2*jj  ][1]);
            ph[1] = __floats2half2_rn(sres[2*jj  ][2], sres[2*jj  ][3]);
            ph[2] = __floats2half2_rn(sres[2*jj+1][0], sres[2*jj+1][1]);
            ph[3] = __floats2half2_rn(sres[2*jj+1][2], sres[2*jj+1][3]);
            unsigned pa0 = *reinterpret_cast<unsigned*>(&ph[0]);
            unsigned pa1 = *reinterpret_cast<unsigned*>(&ph[1]);
            unsigned pa2 = *reinterpret_cast<unsigned*>(&ph[2]);
            unsigned pa3 = *reinterpret_cast<unsigned*>(&ph[3]);
            int kc = jj*16 + tig*2;
            #pragma unroll
            for (int nf = 0; nf < 8; nf++) {
                int d = nf*8 + g;
                unsigned v0h = *(const unsigned*)&Vh[d*VT_STRIDE + kc    ];
                unsigned v1h = *(const unsigned*)&Vh[d*VT_STRIDE + kc + 8];
                unsigned v0l = *(const unsigned*)&Vl[d*VT_STRIDE + kc    ];
                unsigned v1l = *(const unsigned*)&Vl[d*VT_STRIDE + kc + 8];
                MMA_F16(o[nf][0], o[nf][1], o[nf][2], o[nf][3],
                        pa0, pa1, pa2, pa3, v0h, v1h);
                MMA_F16(o[nf][0], o[nf][1], o[nf][2], o[nf][3],
                        pa0, pa1, pa2, pa3, v0l, v1l);
            }
        }

        s ^= 1;
        __syncthreads();
    }

    // ---- epilogue: normalize, tf32-round, write g_att ----
    float inv0 = 1.0f / l0, inv1 = 1.0f / l1;
    int b_ = bh / NHEAD, hh = bh % NHEAD;
    #pragma unroll
    for (int nf = 0; nf < 8; nf++) {
        int col = hh*64 + nf*8 + tig*2;
        *(float2*)&g_att[((size_t)(b_*SEQ + row0  ))*DIMX + col] =
            make_float2(tf32r(o[nf][0]*inv0), tf32r(o[nf][1]*inv0));
        *(float2*)&g_att[((size_t)(b_*SEQ + row0+8))*DIMX + col] =
            make_float2(tf32r(o[nf][2]*inv1), tf32r(o[nf][3]*inv1));
    }
}

// ============================================================
extern "C" void kernel_launch(void* const* d_in, const int* in_sizes, int n_in,
                              void* d_out, int out_size)
{
    const float* x      = (const float*)d_in[0];
    const float* qkv_w  = (const float*)d_in[1];
    const float* qkv_b  = (const float*)d_in[2];
    const float* proj_w = (const float*)d_in[3];
    const float* proj_b = (const float*)d_in[4];
    float* out = (float*)d_out;
    (void)in_sizes; (void)n_in; (void)out_size;

    const int gemm_smem = 2*GS_STG_B;          // 73728 B
    cudaFuncSetAttribute(gemm_tf32<true>,
                         cudaFuncAttributeMaxDynamicSharedMemorySize, gemm_smem);
    cudaFuncSetAttribute(gemm_tf32<false>,
                         cudaFuncAttributeMaxDynamicSharedMemorySize, gemm_smem);
    cudaFuncSetAttribute(attn_mma,
                         cudaFuncAttributeMaxDynamicSharedMemorySize, AT_SMEM);

    // pre-round inputs to tf32 (rne)
    {
        int n4 = ROWS_TOT*DIMX/4;
        cvt_tf32<0><<<(n4+255)/256, 256>>>((const float4*)x, n4);
        n4 = 3*DIMX*DIMX/4;
        cvt_tf32<1><<<(n4+255)/256, 256>>>((const float4*)qkv_w, n4);
        n4 = DIMX*DIMX/4;
        cvt_tf32<2><<<(n4+255)/256, 256>>>((const float4*)proj_w, n4);
    }

    dim3 g1(2304/128, ROWS_TOT/128);   // (18, 64)
    gemm_tf32<true><<<g1, 256, gemm_smem>>>(qkv_b, nullptr);

    dim3 g2(SEQ/128, BATCH*NHEAD);     // (16, 48)
    attn_mma<<<g2, 256, AT_SMEM>>>();

    dim3 g3(DIMX/128, ROWS_TOT/128);   // (6, 64)
    gemm_tf32<false><<<g3, 256, gemm_smem>>>(proj_b, out);
}

// round 10
// speedup vs baseline: 1.6245x; 1.0005x over previous
#include <cuda_runtime.h>
#include <cuda_fp16.h>
#include <cstdint>
#include <cmath>

#define DIMX 768
#define NHEAD 12
#define HD 64
#define BATCH 4
#define SEQ 2048
#define ROWS_TOT (BATCH*SEQ)   /* 8192 */
#define ATTN_SCALE 0.125f
#define BHT (BATCH*NHEAD)

// ---- scratch (allocation-free __device__ globals; device-side access ONLY) ----
__device__ __align__(16) float  g_x32[ROWS_TOT*DIMX];   // x, tf32-rounded
__device__ __align__(16) float  g_w132[3*DIMX*DIMX];    // qkv_w, tf32-rounded
__device__ __align__(16) float  g_w232[DIMX*DIMX];      // proj_w, tf32-rounded
__device__ __align__(16) float  g_q[BHT*SEQ*HD];        // tf32-rounded, pre-scaled
__device__ __align__(16) float  g_k[BHT*SEQ*HD];        // tf32-rounded
__device__ __align__(16) __half g_vthi[BHT*HD*SEQ];     // V transposed, fp16 hi
__device__ __align__(16) __half g_vtlo[BHT*HD*SEQ];     // V transposed, fp16 lo
__device__ __align__(16) float  g_att[ROWS_TOT*DIMX];   // attn out, tf32-rounded

// ---- mma.sync m16n8k8 tf32 (row.col), fp32 accum ----
#define MMA_TF32(d0,d1,d2,d3,a0,a1,a2,a3,b0,b1)                              \
  asm volatile("mma.sync.aligned.m16n8k8.row.col.f32.tf32.tf32.f32 "         \
               "{%0,%1,%2,%3}, {%4,%5,%6,%7}, {%8,%9}, {%0,%1,%2,%3};\n"     \
               : "+f"(d0), "+f"(d1), "+f"(d2), "+f"(d3)                      \
               : "r"(a0), "r"(a1), "r"(a2), "r"(a3), "r"(b0), "r"(b1))

// ---- mma.sync m16n8k16 fp16 (row.col), fp32 accum ----
#define MMA_F16(d0,d1,d2,d3,a0,a1,a2,a3,b0,b1)                               \
  asm volatile("mma.sync.aligned.m16n8k16.row.col.f32.f16.f16.f32 "          \
               "{%0,%1,%2,%3}, {%4,%5,%6,%7}, {%8,%9}, {%0,%1,%2,%3};\n"     \
               : "+f"(d0), "+f"(d1), "+f"(d2), "+f"(d3)                      \
               : "r"(a0), "r"(a1), "r"(a2), "r"(a3), "r"(b0), "r"(b1))

#define CP16(d, s)                                                            \
  asm volatile("cp.async.cg.shared.global [%0], [%1], 16;\n"                  \
               :: "r"(d), "l"(s))
#define CPCOMMIT asm volatile("cp.async.commit_group;\n")

// round fp32 -> tf32 (rne) keeping fp32 bit container
__device__ __forceinline__ float tf32r(float x)
{
    unsigned u;
    asm("cvt.rna.tf32.f32 %0, %1;" : "=r"(u) : "f"(x));
    return __uint_as_float(u);
}

__device__ __forceinline__ void split1h(float x, __half &h, __half &l)
{
    h = __float2half_rn(x);
    l = __float2half_rn(x - __half2float(h));
}

// ============================================================
// fp32 -> tf32-rounded fp32 (vectorized). WHICH: 0->x 1->qkv_w 2->proj_w
// ============================================================
template<int WHICH>
__global__ void cvt_tf32(const float4* __restrict__ src, int n4)
{
    float4* dst = (WHICH == 0) ? (float4*)g_x32
                : (WHICH == 1) ? (float4*)g_w132
                               : (float4*)g_w232;
    int i = blockIdx.x*blockDim.x + threadIdx.x;
    if (i >= n4) return;
    float4 v = src[i];
    dst[i] = make_float4(tf32r(v.x), tf32r(v.y), tf32r(v.z), tf32r(v.w));
}

// ============================================================
// tf32 GEMM: C[m,j] = sum_k A[m,k]*W[j,k] + bias[j]
// BM=128 BN=128 BK=32, 256 thr, 2 CTAs/SM, 3-stage cp.async
// pipeline (one barrier per k-tile), inputs pre-rounded tf32.
// QKV=true: scatter Q(scaled)/K/V(fp16 hi/lo, transposed).
// ============================================================
#define SA 36                         /* smem row stride (floats) */
#define GS_ARR (128*SA)               /* floats per array  */
#define GS_STG (2*GS_ARR)             /* A|B per stage     */
#define GS_STG_B (GS_STG*4)           /* bytes per stage   */
#define GS_AB_OFF (GS_ARR*4)          /* B offset in stage */
#define GS_SMEM (3*GS_STG_B)          /* 110592 B          */
#define NKT (DIMX/32)                 /* 24 k-tiles        */

template<bool QKV>
__global__ __launch_bounds__(256, 2) void gemm_tf32(const float* __restrict__ bias,
                                                    float* __restrict__ out)
{
    const float* __restrict__ A = QKV ? g_x32  : g_att;
    const float* __restrict__ B = QKV ? g_w132 : g_w232;

    extern __shared__ float smg[];
    const unsigned smem_u32 = (unsigned)__cvta_generic_to_shared(smg);

    const int tid  = threadIdx.x;
    const int lane = tid & 31;
    const int w    = tid >> 5;
    const int g    = lane >> 2;
    const int tig  = lane & 3;
    const int wm   = w & 1;
    const int wn   = w >> 1;
    const int bm   = blockIdx.y * 128;
    const int bn   = blockIdx.x * 128;

    float acc[4][4][4];
    #pragma unroll
    for (int i = 0; i < 4; i++)
        #pragma unroll
        for (int j = 0; j < 4; j++)
            #pragma unroll
            for (int r = 0; r < 4; r++) acc[i][j][r] = 0.f;

    auto load_stage = [&](int st, int k0) {
        unsigned base = smem_u32 + (unsigned)st*GS_STG_B;
        #pragma unroll
        for (int t = 0; t < 4; t++) {
            int idx = tid + t*256;        // 0..1023
            int row = idx >> 3;
            int c4  = (idx & 7) * 4;
            unsigned doff = (unsigned)(row*SA + c4)*4u;
            CP16(base +             doff, &A[(size_t)(bm+row)*DIMX + k0 + c4]);
            CP16(base + GS_AB_OFF + doff, &B[(size_t)(bn+row)*DIMX + k0 + c4]);
        }
    };

    load_stage(0, 0);  CPCOMMIT;
    load_stage(1, 32); CPCOMMIT;

    for (int kt = 0; kt < NKT; kt++) {
        const int s = kt % 3;
        if (kt >= NKT-2) asm volatile("cp.async.wait_group 0;\n");
        else             asm volatile("cp.async.wait_group 1;\n");
        __syncthreads();

        if (kt + 2 < NKT) {
            load_stage((kt+2) % 3, (kt+2)*32);
            CPCOMMIT;
        }

        const float* As = smg + s*GS_STG;
        const float* Bs = As + GS_ARR;

        #pragma unroll
        for (int ks = 0; ks < 32; ks += 8) {
            unsigned af[4][4];
            #pragma unroll
            for (int mf = 0; mf < 4; mf++) {
                int rm = wm*64 + mf*16 + g;
                af[mf][0] = __float_as_uint(As[ rm   *SA + ks + tig    ]);
                af[mf][1] = __float_as_uint(As[(rm+8)*SA + ks + tig    ]);
                af[mf][2] = __float_as_uint(As[ rm   *SA + ks + tig + 4]);
                af[mf][3] = __float_as_uint(As[(rm+8)*SA + ks + tig + 4]);
            }
            #pragma unroll
            for (int nf = 0; nf < 4; nf++) {
                int n = wn*32 + nf*8 + g;
                unsigned b0 = __float_as_uint(Bs[n*SA + ks + tig    ]);
                unsigned b1 = __float_as_uint(Bs[n*SA + ks + tig + 4]);
                #pragma unroll
                for (int mf = 0; mf < 4; mf++)
                    MMA_TF32(acc[mf][nf][0], acc[mf][nf][1],
                             acc[mf][nf][2], acc[mf][nf][3],
                             af[mf][0], af[mf][1], af[mf][2], af[mf][3], b0, b1);
            }
        }
    }

    // ---- epilogue ----
    #pragma unroll
    for (int nf = 0; nf < 4; nf++) {
        int col = bn + wn*32 + nf*8 + tig*2;
        float bx = bias[col], by = bias[col+1];
        if (QKV) {
            int c  = col / DIMX;            // 0=Q 1=K 2=V
            int hh = (col % DIMX) >> 6;
            int dd = col & 63;
            #pragma unroll
            for (int mf = 0; mf < 4; mf++)
                #pragma unroll
                for (int h2 = 0; h2 < 2; h2++) {
                    int row = bm + wm*64 + mf*16 + g + h2*8;
                    int b_ = row >> 11, n_ = row & 2047;
                    float vx = acc[mf][nf][h2*2+0] + bx;
                    float vy = acc[mf][nf][h2*2+1] + by;
                    if (c == 0) {
                        size_t idx = (((size_t)(b_*NHEAD + hh))*SEQ + n_)*HD + dd;
                        *(float2*)&g_q[idx] =
                            make_float2(tf32r(vx*ATTN_SCALE), tf32r(vy*ATTN_SCALE));
                    } else if (c == 1) {
                        size_t idx = (((size_t)(b_*NHEAD + hh))*SEQ + n_)*HD + dd;
                        *(float2*)&g_k[idx] = make_float2(tf32r(vx), tf32r(vy));
                    } else {
                        size_t idx = (((size_t)(b_*NHEAD + hh))*HD + dd)*SEQ + n_;
                        split1h(vx, g_vthi[idx],     g_vtlo[idx]);
                        split1h(vy, g_vthi[idx+SEQ], g_vtlo[idx+SEQ]);
                    }
                }
        } else {
            #pragma unroll
            for (int mf = 0; mf < 4; mf++)
                #pragma unroll
                for (int h2 = 0; h2 < 2; h2++) {
                    int row = bm + wm*64 + mf*16 + g + h2*8;
                    float2 v = make_float2(acc[mf][nf][h2*2+0] + bx,
                                           acc[mf][nf][h2*2+1] + by);
                    *(float2*)&out[(size_t)row*DIMX + col] = v;
                }
        }
    }
}

// ============================================================
// Flash attention: QK^T tf32 m16n8k8, PV fp16 2-term.
// 3-stage cp.async pipeline, 2 CTAs/SM. Block = (b*h, 128 q rows).
// ============================================================
#define KS_STRIDE 68                       /* floats per K row  */
#define VT_STRIDE 72                       /* halves per Vt row */
#define K_BYTES   (64*KS_STRIDE*4)         /* 17408 */
#define V_BYTES   (64*VT_STRIDE*2)         /* 9216  */
#define AT_STG    (K_BYTES + 2*V_BYTES)    /* 35840 per stage */
#define AT_SMEM   (3*AT_STG)               /* 107520 */
#define NTILES    (SEQ/64)                 /* 32 */

__global__ __launch_bounds__(256, 2) void attn_mma()
{
    extern __shared__ char sma[];
    const unsigned smem_u32 = (unsigned)__cvta_generic_to_shared(sma);

    const int tid  = threadIdx.x;
    const int lane = tid & 31;
    const int w    = tid >> 5;
    const int g    = lane >> 2;
    const int tig  = lane & 3;
    const int bh   = blockIdx.y;
    const int q0   = blockIdx.x * 128;
    const size_t kbase = (size_t)bh * SEQ * HD;
    const size_t vbase = (size_t)bh * HD * SEQ;
    const int row0 = q0 + w*16 + g;

    // Q fragments: 8 k-steps x 4 regs (tf32-rounded, pre-scaled in gmem)
    unsigned qf[8][4];
    #pragma unroll
    for (int ks = 0; ks < 8; ks++) {
        int c0 = ks*8 + tig;
        qf[ks][0] = __float_as_uint(g_q[kbase + (size_t) row0   *HD + c0    ]);
        qf[ks][1] = __float_as_uint(g_q[kbase + (size_t)(row0+8)*HD + c0    ]);
        qf[ks][2] = __float_as_uint(g_q[kbase + (size_t) row0   *HD + c0 + 4]);
        qf[ks][3] = __float_as_uint(g_q[kbase + (size_t)(row0+8)*HD + c0 + 4]);
    }

    float m0 = -INFINITY, m1 = -INFINITY, l0 = 0.f, l1 = 0.f;
    float o[8][4];
    #pragma unroll
    for (int nf = 0; nf < 8; nf++)
        #pragma unroll
        for (int r = 0; r < 4; r++) o[nf][r] = 0.f;

    auto load_tile = [&](int st, int j0) {
        unsigned sb = smem_u32 + (unsigned)st*AT_STG;
        #pragma unroll
        for (int t = 0; t < 4; t++) {
            int idx = tid + t*256;
            int row = idx >> 4;
            int c4  = (idx & 15) * 4;
            CP16(sb + (unsigned)(row*KS_STRIDE + c4)*4u,
                 &g_k[kbase + (size_t)(j0+row)*HD + c4]);
        }
        unsigned vb = sb + K_BYTES;
        #pragma unroll
        for (int t = 0; t < 2; t++) {
            int idx = tid + t*256;
            int d   = idx >> 3;
            int c8  = (idx & 7) * 8;
            unsigned doff = (unsigned)(d*VT_STRIDE + c8)*2u;
            CP16(vb +           doff, &g_vthi[vbase + (size_t)d*SEQ + j0 + c8]);
            CP16(vb + V_BYTES + doff, &g_vtlo[vbase + (size_t)d*SEQ + j0 + c8]);
        }
    };

    load_tile(0, 0);  CPCOMMIT;
    load_tile(1, 64); CPCOMMIT;

    for (int it = 0; it < NTILES; it++) {
        const int s = it % 3;
        if (it >= NTILES-2) asm volatile("cp.async.wait_group 0;\n");
        else                asm volatile("cp.async.wait_group 1;\n");
        __syncthreads();

        if (it + 2 < NTILES) {
            load_tile((it+2) % 3, (it+2)*64);
            CPCOMMIT;
        }

        const float*  Ks = (const float*)(sma + s*AT_STG);
        const __half* Vh = (const __half*)(sma + s*AT_STG + K_BYTES);
        const __half* Vl = (const __half*)(sma + s*AT_STG + K_BYTES + V_BYTES);

        // ---- S = Q K^T (tf32) ----
        float sres[8][4];
        #pragma unroll
        for (int nf = 0; nf < 8; nf++)
            #pragma unroll
            for (int r = 0; r < 4; r++) sres[nf][r] = 0.f;

        #pragma unroll
        for (int ks = 0; ks < 8; ks++) {
            #pragma unroll
            for (int nf = 0; nf < 8; nf++) {
                int kv = nf*8 + g;
                unsigned b0 = __float_as_uint(Ks[kv*KS_STRIDE + ks*8 + tig    ]);
                unsigned b1 = __float_as_uint(Ks[kv*KS_STRIDE + ks*8 + tig + 4]);
                MMA_TF32(sres[nf][0], sres[nf][1], sres[nf][2], sres[nf][3],
                         qf[ks][0], qf[ks][1], qf[ks][2], qf[ks][3], b0, b1);
            }
        }

        // ---- online softmax ----
        float rm0 = -INFINITY, rm1 = -INFINITY;
        #pragma unroll
        for (int nf = 0; nf < 8; nf++) {
            rm0 = fmaxf(rm0, fmaxf(sres[nf][0], sres[nf][1]));
            rm1 = fmaxf(rm1, fmaxf(sres[nf][2], sres[nf][3]));
        }
        rm0 = fmaxf(rm0, __shfl_xor_sync(0xFFFFFFFFu, rm0, 1));
        rm0 = fmaxf(rm0, __shfl_xor_sync(0xFFFFFFFFu, rm0, 2));
        rm1 = fmaxf(rm1, __shfl_xor_sync(0xFFFFFFFFu, rm1, 1));
        rm1 = fmaxf(rm1, __shfl_xor_sync(0xFFFFFFFFu, rm1, 2));
        float mn0 = fmaxf(m0, rm0), mn1 = fmaxf(m1, rm1);
        float al0 = __expf(m0 - mn0), al1 = __expf(m1 - mn1);
        m0 = mn0; m1 = mn1;

        float rs0 = 0.f, rs1 = 0.f;
        #pragma unroll
        for (int nf = 0; nf < 8; nf++) {
            sres[nf][0] = __expf(sres[nf][0] - mn0);
            sres[nf][1] = __expf(sres[nf][1] - mn0);
            sres[nf][2] = __expf(sres[nf][2] - mn1);
            sres[nf][3] = __expf(sres[nf][3] - mn1);
            rs0 += sres[nf][0] + sres[nf][1];
            rs1 += sres[nf][2] + sres[nf][3];
        }
        rs0 += __shfl_xor_sync(0xFFFFFFFFu, rs0, 1);
        rs0 += __shfl_xor_sync(0xFFFFFFFFu, rs0, 2);
        rs1 += __shfl_xor_sync(0xFFFFFFFFu, rs1, 1);
        rs1 += __shfl_xor_sync(0xFFFFFFFFu, rs1, 2);
        l0 = l0*al0 + rs0;
        l1 = l1*al1 + rs1;

        #pragma unroll
        for (int nf = 0; nf < 8; nf++) {
            o[nf][0] *= al0; o[nf][1] *= al0;
            o[nf][2] *= al1; o[nf][3] *= al1;
        }

        // ---- O += P @ V  (fp16 2-term; C-frag -> A-frag direct) ----
        #pragma unroll
        for (int jj = 0; jj < 4; jj++) {
            __half2 ph[4];
            ph[0] = __floats2half2_rn(sres[2*jj  ][0], sres[2*jj  ][1]);
            ph[1] = __floats2half2_rn(sres[2*jj  ][2], sres[2*jj  ][3]);
            ph[2] = __floats2half2_rn(sres[2*jj+1][0], sres[2*jj+1][1]);
            ph[3] = __floats2half2_rn(sres[2*jj+1][2], sres[2*jj+1][3]);
            unsigned pa0 = *reinterpret_cast<unsigned*>(&ph[0]);
            unsigned pa1 = *reinterpret_cast<unsigned*>(&ph[1]);
            unsigned pa2 = *reinterpret_cast<unsigned*>(&ph[2]);
            unsigned pa3 = *reinterpret_cast<unsigned*>(&ph[3]);
            int kc = jj*16 + tig*2;
            #pragma unroll
            for (int nf = 0; nf < 8; nf++) {
                int d = nf*8 + g;
                unsigned v0h = *(const unsigned*)&Vh[d*VT_STRIDE + kc    ];
                unsigned v1h = *(const unsigned*)&Vh[d*VT_STRIDE + kc + 8];
                unsigned v0l = *(const unsigned*)&Vl[d*VT_STRIDE + kc    ];
                unsigned v1l = *(const unsigned*)&Vl[d*VT_STRIDE + kc + 8];
                MMA_F16(o[nf][0], o[nf][1], o[nf][2], o[nf][3],
                        pa0, pa1, pa2, pa3, v0h, v1h);
                MMA_F16(o[nf][0], o[nf][1], o[nf][2], o[nf][3],
                        pa0, pa1, pa2, pa3, v0l, v1l);
            }
        }
    }

    // ---- epilogue: normalize, tf32-round, write g_att ----
    float inv0 = 1.0f / l0, inv1 = 1.0f / l1;
    int b_ = bh / NHEAD, hh = bh % NHEAD;
    #pragma unroll
    for (int nf = 0; nf < 8; nf++) {
        int col = hh*64 + nf*8 + tig*2;
        *(float2*)&g_att[((size_t)(b_*SEQ + row0  ))*DIMX + col] =
            make_float2(tf32r(o[nf][0]*inv0), tf32r(o[nf][1]*inv0));
        *(float2*)&g_att[((size_t)(b_*SEQ + row0+8))*DIMX + col] =
            make_float2(tf32r(o[nf][2]*inv1), tf32r(o[nf][3]*inv1));
    }
}

// ============================================================
extern "C" void kernel_launch(void* const* d_in, const int* in_sizes, int n_in,
                              void* d_out, int out_size)
{
    const float* x      = (const float*)d_in[0];
    const float* qkv_w  = (const float*)d_in[1];
    const float* qkv_b  = (const float*)d_in[2];
    const float* proj_w = (const float*)d_in[3];
    const float* proj_b = (const float*)d_in[4];
    float* out = (float*)d_out;
    (void)in_sizes; (void)n_in; (void)out_size;

    cudaFuncSetAttribute(gemm_tf32<true>,
                         cudaFuncAttributeMaxDynamicSharedMemorySize, GS_SMEM);
    cudaFuncSetAttribute(gemm_tf32<false>,
                         cudaFuncAttributeMaxDynamicSharedMemorySize, GS_SMEM);
    cudaFuncSetAttribute(attn_mma,
                         cudaFuncAttributeMaxDynamicSharedMemorySize, AT_SMEM);

    // pre-round inputs to tf32 (rne)
    {
        int n4 = ROWS_TOT*DIMX/4;
        cvt_tf32<0><<<(n4+255)/256, 256>>>((const float4*)x, n4);
        n4 = 3*DIMX*DIMX/4;
        cvt_tf32<1><<<(n4+255)/256, 256>>>((const float4*)qkv_w, n4);
        n4 = DIMX*DIMX/4;
        cvt_tf32<2><<<(n4+255)/256, 256>>>((const float4*)proj_w, n4);
    }

    dim3 g1(2304/128, ROWS_TOT/128);   // (18, 64)
    gemm_tf32<true><<<g1, 256, GS_SMEM>>>(qkv_b, nullptr);

    dim3 g2(SEQ/128, BATCH*NHEAD);     // (16, 48)
    attn_mma<<<g2, 256, AT_SMEM>>>();

    dim3 g3(DIMX/128, ROWS_TOT/128);   // (6, 64)
    gemm_tf32<false><<<g3, 256, GS_SMEM>>>(proj_b, out);
}

// round 11
// speedup vs baseline: 1.8470x; 1.1369x over previous
#include <cuda_runtime.h>
#include <cuda_fp16.h>
#include <cstdint>
#include <cmath>

#define DIMX 768
#define NHEAD 12
#define HD 64
#define BATCH 4
#define SEQ 2048
#define ROWS_TOT (BATCH*SEQ)   /* 8192 */
#define ATTN_SCALE 0.125f
#define BHT (BATCH*NHEAD)

// ---- scratch (allocation-free __device__ globals; device-side access ONLY) ----
__device__ __align__(16) float  g_x32[ROWS_TOT*DIMX];   // x, tf32-rounded
__device__ __align__(16) float  g_w132[3*DIMX*DIMX];    // qkv_w, tf32-rounded
__device__ __align__(16) float  g_w232[DIMX*DIMX];      // proj_w, tf32-rounded
__device__ __align__(16) float  g_q[BHT*SEQ*HD];        // tf32-rounded, pre-scaled
__device__ __align__(16) float  g_k[BHT*SEQ*HD];        // tf32-rounded
__device__ __align__(16) __half g_vt[BHT*HD*SEQ];       // V transposed, fp16
__device__ __align__(16) float  g_att[ROWS_TOT*DIMX];   // attn out, tf32-rounded

// ---- mma.sync m16n8k8 tf32 (row.col), fp32 accum ----
#define MMA_TF32(d0,d1,d2,d3,a0,a1,a2,a3,b0,b1)                              \
  asm volatile("mma.sync.aligned.m16n8k8.row.col.f32.tf32.tf32.f32 "         \
               "{%0,%1,%2,%3}, {%4,%5,%6,%7}, {%8,%9}, {%0,%1,%2,%3};\n"     \
               : "+f"(d0), "+f"(d1), "+f"(d2), "+f"(d3)                      \
               : "r"(a0), "r"(a1), "r"(a2), "r"(a3), "r"(b0), "r"(b1))

// ---- mma.sync m16n8k16 fp16 (row.col), fp32 accum ----
#define MMA_F16(d0,d1,d2,d3,a0,a1,a2,a3,b0,b1)                               \
  asm volatile("mma.sync.aligned.m16n8k16.row.col.f32.f16.f16.f32 "          \
               "{%0,%1,%2,%3}, {%4,%5,%6,%7}, {%8,%9}, {%0,%1,%2,%3};\n"     \
               : "+f"(d0), "+f"(d1), "+f"(d2), "+f"(d3)                      \
               : "r"(a0), "r"(a1), "r"(a2), "r"(a3), "r"(b0), "r"(b1))

#define CP16(d, s)                                                            \
  asm volatile("cp.async.cg.shared.global [%0], [%1], 16;\n"                  \
               :: "r"(d), "l"(s))
#define CPCOMMIT asm volatile("cp.async.commit_group;\n")

// round fp32 -> tf32 (rne) keeping fp32 bit container
__device__ __forceinline__ float tf32r(float x)
{
    unsigned u;
    asm("cvt.rna.tf32.f32 %0, %1;" : "=r"(u) : "f"(x));
    return __uint_as_float(u);
}

// ============================================================
// fp32 -> tf32-rounded fp32 (vectorized). WHICH: 0->x 1->qkv_w 2->proj_w
// ============================================================
template<int WHICH>
__global__ void cvt_tf32(const float4* __restrict__ src, int n4)
{
    float4* dst = (WHICH == 0) ? (float4*)g_x32
                : (WHICH == 1) ? (float4*)g_w132
                               : (float4*)g_w232;
    int i = blockIdx.x*blockDim.x + threadIdx.x;
    if (i >= n4) return;
    float4 v = src[i];
    dst[i] = make_float4(tf32r(v.x), tf32r(v.y), tf32r(v.z), tf32r(v.w));
}

// ============================================================
// tf32 GEMM: C[m,j] = sum_k A[m,k]*W[j,k] + bias[j]
// BM=128 BN=128 BK=32, 256 thr, 2 CTAs/SM, 3-stage cp.async.
// QKV=true: scatter Q(scaled)/K(tf32)/V(fp16, transposed).
// ============================================================
#define SA 36                         /* smem row stride (floats) */
#define GS_ARR (128*SA)               /* floats per array  */
#define GS_STG (2*GS_ARR)             /* A|B per stage     */
#define GS_STG_B (GS_STG*4)           /* bytes per stage   */
#define GS_AB_OFF (GS_ARR*4)          /* B offset in stage */
#define GS_SMEM (3*GS_STG_B)          /* 110592 B          */
#define NKT (DIMX/32)                 /* 24 k-tiles        */

template<bool QKV>
__global__ __launch_bounds__(256, 2) void gemm_tf32(const float* __restrict__ bias,
                                                    float* __restrict__ out)
{
    const float* __restrict__ A = QKV ? g_x32  : g_att;
    const float* __restrict__ B = QKV ? g_w132 : g_w232;

    extern __shared__ float smg[];
    const unsigned smem_u32 = (unsigned)__cvta_generic_to_shared(smg);

    const int tid  = threadIdx.x;
    const int lane = tid & 31;
    const int w    = tid >> 5;
    const int g    = lane >> 2;
    const int tig  = lane & 3;
    const int wm   = w & 1;
    const int wn   = w >> 1;
    const int bm   = blockIdx.y * 128;
    const int bn   = blockIdx.x * 128;

    float acc[4][4][4];
    #pragma unroll
    for (int i = 0; i < 4; i++)
        #pragma unroll
        for (int j = 0; j < 4; j++)
            #pragma unroll
            for (int r = 0; r < 4; r++) acc[i][j][r] = 0.f;

    auto load_stage = [&](int st, int k0) {
        unsigned base = smem_u32 + (unsigned)st*GS_STG_B;
        #pragma unroll
        for (int t = 0; t < 4; t++) {
            int idx = tid + t*256;        // 0..1023
            int row = idx >> 3;
            int c4  = (idx & 7) * 4;
            unsigned doff = (unsigned)(row*SA + c4)*4u;
            CP16(base +             doff, &A[(size_t)(bm+row)*DIMX + k0 + c4]);
            CP16(base + GS_AB_OFF + doff, &B[(size_t)(bn+row)*DIMX + k0 + c4]);
        }
    };

    load_stage(0, 0);  CPCOMMIT;
    load_stage(1, 32); CPCOMMIT;

    for (int kt = 0; kt < NKT; kt++) {
        const int s = kt % 3;
        if (kt >= NKT-2) asm volatile("cp.async.wait_group 0;\n");
        else             asm volatile("cp.async.wait_group 1;\n");
        __syncthreads();

        if (kt + 2 < NKT) {
            load_stage((kt+2) % 3, (kt+2)*32);
            CPCOMMIT;
        }

        const float* As = smg + s*GS_STG;
        const float* Bs = As + GS_ARR;

        #pragma unroll
        for (int ks = 0; ks < 32; ks += 8) {
            unsigned af[4][4];
            #pragma unroll
            for (int mf = 0; mf < 4; mf++) {
                int rm = wm*64 + mf*16 + g;
                af[mf][0] = __float_as_uint(As[ rm   *SA + ks + tig    ]);
                af[mf][1] = __float_as_uint(As[(rm+8)*SA + ks + tig    ]);
                af[mf][2] = __float_as_uint(As[ rm   *SA + ks + tig + 4]);
                af[mf][3] = __float_as_uint(As[(rm+8)*SA + ks + tig + 4]);
            }
            #pragma unroll
            for (int nf = 0; nf < 4; nf++) {
                int n = wn*32 + nf*8 + g;
                unsigned b0 = __float_as_uint(Bs[n*SA + ks + tig    ]);
                unsigned b1 = __float_as_uint(Bs[n*SA + ks + tig + 4]);
                #pragma unroll
                for (int mf = 0; mf < 4; mf++)
                    MMA_TF32(acc[mf][nf][0], acc[mf][nf][1],
                             acc[mf][nf][2], acc[mf][nf][3],
                             af[mf][0], af[mf][1], af[mf][2], af[mf][3], b0, b1);
            }
        }
    }

    // ---- epilogue ----
    #pragma unroll
    for (int nf = 0; nf < 4; nf++) {
        int col = bn + wn*32 + nf*8 + tig*2;
        float bx = bias[col], by = bias[col+1];
        if (QKV) {
            int c  = col / DIMX;            // 0=Q 1=K 2=V
            int hh = (col % DIMX) >> 6;
            int dd = col & 63;
            #pragma unroll
            for (int mf = 0; mf < 4; mf++)
                #pragma unroll
                for (int h2 = 0; h2 < 2; h2++) {
                    int row = bm + wm*64 + mf*16 + g + h2*8;
                    int b_ = row >> 11, n_ = row & 2047;
                    float vx = acc[mf][nf][h2*2+0] + bx;
                    float vy = acc[mf][nf][h2*2+1] + by;
                    if (c == 0) {
                        size_t idx = (((size_t)(b_*NHEAD + hh))*SEQ + n_)*HD + dd;
                        *(float2*)&g_q[idx] =
                            make_float2(tf32r(vx*ATTN_SCALE), tf32r(vy*ATTN_SCALE));
                    } else if (c == 1) {
                        size_t idx = (((size_t)(b_*NHEAD + hh))*SEQ + n_)*HD + dd;
                        *(float2*)&g_k[idx] = make_float2(tf32r(vx), tf32r(vy));
                    } else {
                        size_t idx = (((size_t)(b_*NHEAD + hh))*HD + dd)*SEQ + n_;
                        g_vt[idx]     = __float2half_rn(vx);
                        g_vt[idx+SEQ] = __float2half_rn(vy);
                    }
                }
        } else {
            #pragma unroll
            for (int mf = 0; mf < 4; mf++)
                #pragma unroll
                for (int h2 = 0; h2 < 2; h2++) {
                    int row = bm + wm*64 + mf*16 + g + h2*8;
                    float2 v = make_float2(acc[mf][nf][h2*2+0] + bx,
                                           acc[mf][nf][h2*2+1] + by);
                    *(float2*)&out[(size_t)row*DIMX + col] = v;
                }
        }
    }
}

// ============================================================
// Flash attention: QK^T tf32 m16n8k8, PV fp16 single-term.
// 3-stage cp.async pipeline, 2 CTAs/SM. Block = (b*h, 128 q rows).
// ============================================================
#define KS_STRIDE 68                       /* floats per K row  */
#define VT_STRIDE 72                       /* halves per Vt row */
#define K_BYTES   (64*KS_STRIDE*4)         /* 17408 */
#define V_BYTES   (64*VT_STRIDE*2)         /* 9216  */
#define AT_STG    (K_BYTES + V_BYTES)      /* 26624 per stage */
#define AT_SMEM   (3*AT_STG)               /* 79872 */
#define NTILES    (SEQ/64)                 /* 32 */

__global__ __launch_bounds__(256, 2) void attn_mma()
{
    extern __shared__ char sma[];
    const unsigned smem_u32 = (unsigned)__cvta_generic_to_shared(sma);

    const int tid  = threadIdx.x;
    const int lane = tid & 31;
    const int w    = tid >> 5;
    const int g    = lane >> 2;
    const int tig  = lane & 3;
    const int bh   = blockIdx.y;
    const int q0   = blockIdx.x * 128;
    const size_t kbase = (size_t)bh * SEQ * HD;
    const size_t vbase = (size_t)bh * HD * SEQ;
    const int row0 = q0 + w*16 + g;

    // Q fragments: 8 k-steps x 4 regs (tf32-rounded, pre-scaled in gmem)
    unsigned qf[8][4];
    #pragma unroll
    for (int ks = 0; ks < 8; ks++) {
        int c0 = ks*8 + tig;
        qf[ks][0] = __float_as_uint(g_q[kbase + (size_t) row0   *HD + c0    ]);
        qf[ks][1] = __float_as_uint(g_q[kbase + (size_t)(row0+8)*HD + c0    ]);
        qf[ks][2] = __float_as_uint(g_q[kbase + (size_t) row0   *HD + c0 + 4]);
        qf[ks][3] = __float_as_uint(g_q[kbase + (size_t)(row0+8)*HD + c0 + 4]);
    }

    float m0 = -INFINITY, m1 = -INFINITY, l0 = 0.f, l1 = 0.f;
    float o[8][4];
    #pragma unroll
    for (int nf = 0; nf < 8; nf++)
        #pragma unroll
        for (int r = 0; r < 4; r++) o[nf][r] = 0.f;

    auto load_tile = [&](int st, int j0) {
        unsigned sb = smem_u32 + (unsigned)st*AT_STG;
        #pragma unroll
        for (int t = 0; t < 4; t++) {
            int idx = tid + t*256;
            int row = idx >> 4;
            int c4  = (idx & 15) * 4;
            CP16(sb + (unsigned)(row*KS_STRIDE + c4)*4u,
                 &g_k[kbase + (size_t)(j0+row)*HD + c4]);
        }
        unsigned vb = sb + K_BYTES;
        {
            int idx = tid;                 // 512 chunks, 256 threads x2
            #pragma unroll
            for (int t = 0; t < 2; t++) {
                int id2 = idx + t*256;
                int d   = id2 >> 3;
                int c8  = (id2 & 7) * 8;
                CP16(vb + (unsigned)(d*VT_STRIDE + c8)*2u,
                     &g_vt[vbase + (size_t)d*SEQ + j0 + c8]);
            }
        }
    };

    load_tile(0, 0);  CPCOMMIT;
    load_tile(1, 64); CPCOMMIT;

    for (int it = 0; it < NTILES; it++) {
        const int s = it % 3;
        if (it >= NTILES-2) asm volatile("cp.async.wait_group 0;\n");
        else                asm volatile("cp.async.wait_group 1;\n");
        __syncthreads();

        if (it + 2 < NTILES) {
            load_tile((it+2) % 3, (it+2)*64);
            CPCOMMIT;
        }

        const float*  Ks = (const float*)(sma + s*AT_STG);
        const __half* Vh = (const __half*)(sma + s*AT_STG + K_BYTES);

        // ---- S = Q K^T (tf32) ----
        float sres[8][4];
        #pragma unroll
        for (int nf = 0; nf < 8; nf++)
            #pragma unroll
            for (int r = 0; r < 4; r++) sres[nf][r] = 0.f;

        #pragma unroll
        for (int ks = 0; ks < 8; ks++) {
            #pragma unroll
            for (int nf = 0; nf < 8; nf++) {
                int kv = nf*8 + g;
                unsigned b0 = __float_as_uint(Ks[kv*KS_STRIDE + ks*8 + tig    ]);
                unsigned b1 = __float_as_uint(Ks[kv*KS_STRIDE + ks*8 + tig + 4]);
                MMA_TF32(sres[nf][0], sres[nf][1], sres[nf][2], sres[nf][3],
                         qf[ks][0], qf[ks][1], qf[ks][2], qf[ks][3], b0, b1);
            }
        }

        // ---- online softmax ----
        float rm0 = -INFINITY, rm1 = -INFINITY;
        #pragma unroll
        for (int nf = 0; nf < 8; nf++) {
            rm0 = fmaxf(rm0, fmaxf(sres[nf][0], sres[nf][1]));
            rm1 = fmaxf(rm1, fmaxf(sres[nf][2], sres[nf][3]));
        }
        rm0 = fmaxf(rm0, __shfl_xor_sync(0xFFFFFFFFu, rm0, 1));
        rm0 = fmaxf(rm0, __shfl_xor_sync(0xFFFFFFFFu, rm0, 2));
        rm1 = fmaxf(rm1, __shfl_xor_sync(0xFFFFFFFFu, rm1, 1));
        rm1 = fmaxf(rm1, __shfl_xor_sync(0xFFFFFFFFu, rm1, 2));
        float mn0 = fmaxf(m0, rm0), mn1 = fmaxf(m1, rm1);
        float al0 = __expf(m0 - mn0), al1 = __expf(m1 - mn1);
        m0 = mn0; m1 = mn1;

        float rs0 = 0.f, rs1 = 0.f;
        #pragma unroll
        for (int nf = 0; nf < 8; nf++) {
            sres[nf][0] = __expf(sres[nf][0] - mn0);
            sres[nf][1] = __expf(sres[nf][1] - mn0);
            sres[nf][2] = __expf(sres[nf][2] - mn1);
            sres[nf][3] = __expf(sres[nf][3] - mn1);
            rs0 += sres[nf][0] + sres[nf][1];
            rs1 += sres[nf][2] + sres[nf][3];
        }
        rs0 += __shfl_xor_sync(0xFFFFFFFFu, rs0, 1);
        rs0 += __shfl_xor_sync(0xFFFFFFFFu, rs0, 2);
        rs1 += __shfl_xor_sync(0xFFFFFFFFu, rs1, 1);
        rs1 += __shfl_xor_sync(0xFFFFFFFFu, rs1, 2);
        l0 = l0*al0 + rs0;
        l1 = l1*al1 + rs1;

        #pragma unroll
        for (int nf = 0; nf < 8; nf++) {
            o[nf][0] *= al0; o[nf][1] *= al0;
            o[nf][2] *= al1; o[nf][3] *= al1;
        }

        // ---- O += P @ V  (fp16 single term; C-frag -> A-frag direct) ----
        #pragma unroll
        for (int jj = 0; jj < 4; jj++) {
            __half2 ph[4];
            ph[0] = __floats2half2_rn(sres[2*jj  ][0], sres[2*jj  ][1]);
            ph[1] = __floats2half2_rn(sres[2*jj  ][2], sres[2*jj  ][3]);
            ph[2] = __floats2half2_rn(sres[2*jj+1][0], sres[2*jj+1][1]);
            ph[3] = __floats2half2_rn(sres[2*jj+1][2], sres[2*jj+1][3]);
            unsigned pa0 = *reinterpret_cast<unsigned*>(&ph[0]);
            unsigned pa1 = *reinterpret_cast<unsigned*>(&ph[1]);
            unsigned pa2 = *reinterpret_cast<unsigned*>(&ph[2]);
            unsigned pa3 = *reinterpret_cast<unsigned*>(&ph[3]);
            int kc = jj*16 + tig*2;
            #pragma unroll
            for (int nf = 0; nf < 8; nf++) {
                int d = nf*8 + g;
                unsigned v0 = *(const unsigned*)&Vh[d*VT_STRIDE + kc    ];
                unsigned v1 = *(const unsigned*)&Vh[d*VT_STRIDE + kc + 8];
                MMA_F16(o[nf][0], o[nf][1], o[nf][2], o[nf][3],
                        pa0, pa1, pa2, pa3, v0, v1);
            }
        }
    }

    // ---- epilogue: normalize, tf32-round, write g_att ----
    float inv0 = 1.0f / l0, inv1 = 1.0f / l1;
    int b_ = bh / NHEAD, hh = bh % NHEAD;
    #pragma unroll
    for (int nf = 0; nf < 8; nf++) {
        int col = hh*64 + nf*8 + tig*2;
        *(float2*)&g_att[((size_t)(b_*SEQ + row0  ))*DIMX + col] =
            make_float2(tf32r(o[nf][0]*inv0), tf32r(o[nf][1]*inv0));
        *(float2*)&g_att[((size_t)(b_*SEQ + row0+8))*DIMX + col] =
            make_float2(tf32r(o[nf][2]*inv1), tf32r(o[nf][3]*inv1));
    }
}

// ============================================================
extern "C" void kernel_launch(void* const* d_in, const int* in_sizes, int n_in,
                              void* d_out, int out_size)
{
    const float* x      = (const float*)d_in[0];
    const float* qkv_w  = (const float*)d_in[1];
    const float* qkv_b  = (const float*)d_in[2];
    const float* proj_w = (const float*)d_in[3];
    const float* proj_b = (const float*)d_in[4];
    float* out = (float*)d_out;
    (void)in_sizes; (void)n_in; (void)out_size;

    cudaFuncSetAttribute(gemm_tf32<true>,
                         cudaFuncAttributeMaxDynamicSharedMemorySize, GS_SMEM);
    cudaFuncSetAttribute(gemm_tf32<false>,
                         cudaFuncAttributeMaxDynamicSharedMemorySize, GS_SMEM);
    cudaFuncSetAttribute(attn_mma,
                         cudaFuncAttributeMaxDynamicSharedMemorySize, AT_SMEM);

    // pre-round inputs to tf32 (rne)
    {
        int n4 = ROWS_TOT*DIMX/4;
        cvt_tf32<0><<<(n4+255)/256, 256>>>((const float4*)x, n4);
        n4 = 3*DIMX*DIMX/4;
        cvt_tf32<1><<<(n4+255)/256, 256>>>((const float4*)qkv_w, n4);
        n4 = DIMX*DIMX/4;
        cvt_tf32<2><<<(n4+255)/256, 256>>>((const float4*)proj_w, n4);
    }

    dim3 g1(2304/128, ROWS_TOT/128);   // (18, 64)
    gemm_tf32<true><<<g1, 256, GS_SMEM>>>(qkv_b, nullptr);

    dim3 g2(SEQ/128, BATCH*NHEAD);     // (16, 48)
    attn_mma<<<g2, 256, AT_SMEM>>>();

    dim3 g3(DIMX/128, ROWS_TOT/128);   // (6, 64)
    gemm_tf32<false><<<g3, 256, GS_SMEM>>>(proj_b, out);
}

// round 12
// speedup vs baseline: 2.2381x; 1.2118x over previous
#include <cuda_runtime.h>
#include <cuda_fp16.h>
#include <cstdint>
#include <cmath>

#define DIMX 768
#define NHEAD 12
#define HD 64
#define BATCH 4
#define SEQ 2048
#define ROWS_TOT (BATCH*SEQ)   /* 8192 */
#define ATTN_SCALE 0.125f
#define BHT (BATCH*NHEAD)

// ---- scratch (allocation-free __device__ globals; device-side access ONLY) ----
__device__ __align__(16) float  g_x32[ROWS_TOT*DIMX];   // x, tf32-rounded
__device__ __align__(16) float  g_w132[3*DIMX*DIMX];    // qkv_w, tf32-rounded
__device__ __align__(16) float  g_w232[DIMX*DIMX];      // proj_w, tf32-rounded
__device__ __align__(16) __half g_q[BHT*SEQ*HD];        // fp16, pre-scaled
__device__ __align__(16) __half g_k[BHT*SEQ*HD];        // fp16
__device__ __align__(16) __half g_vt[BHT*HD*SEQ];       // V transposed, fp16
__device__ __align__(16) float  g_att[ROWS_TOT*DIMX];   // attn out, tf32-rounded

// ---- mma.sync m16n8k8 tf32 (row.col), fp32 accum ----
#define MMA_TF32(d0,d1,d2,d3,a0,a1,a2,a3,b0,b1)                              \
  asm volatile("mma.sync.aligned.m16n8k8.row.col.f32.tf32.tf32.f32 "         \
               "{%0,%1,%2,%3}, {%4,%5,%6,%7}, {%8,%9}, {%0,%1,%2,%3};\n"     \
               : "+f"(d0), "+f"(d1), "+f"(d2), "+f"(d3)                      \
               : "r"(a0), "r"(a1), "r"(a2), "r"(a3), "r"(b0), "r"(b1))

// ---- mma.sync m16n8k16 fp16 (row.col), fp32 accum ----
#define MMA_F16(d0,d1,d2,d3,a0,a1,a2,a3,b0,b1)                               \
  asm volatile("mma.sync.aligned.m16n8k16.row.col.f32.f16.f16.f32 "          \
               "{%0,%1,%2,%3}, {%4,%5,%6,%7}, {%8,%9}, {%0,%1,%2,%3};\n"     \
               : "+f"(d0), "+f"(d1), "+f"(d2), "+f"(d3)                      \
               : "r"(a0), "r"(a1), "r"(a2), "r"(a3), "r"(b0), "r"(b1))

#define CP16(d, s)                                                            \
  asm volatile("cp.async.cg.shared.global [%0], [%1], 16;\n"                  \
               :: "r"(d), "l"(s))
#define CPCOMMIT asm volatile("cp.async.commit_group;\n")

// round fp32 -> tf32 (rne) keeping fp32 bit container
__device__ __forceinline__ float tf32r(float x)
{
    unsigned u;
    asm("cvt.rna.tf32.f32 %0, %1;" : "=r"(u) : "f"(x));
    return __uint_as_float(u);
}

// ============================================================
// fp32 -> tf32-rounded fp32 (vectorized). WHICH: 0->x 1->qkv_w 2->proj_w
// ============================================================
template<int WHICH>
__global__ void cvt_tf32(const float4* __restrict__ src, int n4)
{
    float4* dst = (WHICH == 0) ? (float4*)g_x32
                : (WHICH == 1) ? (float4*)g_w132
                               : (float4*)g_w232;
    int i = blockIdx.x*blockDim.x + threadIdx.x;
    if (i >= n4) return;
    float4 v = src[i];
    dst[i] = make_float4(tf32r(v.x), tf32r(v.y), tf32r(v.z), tf32r(v.w));
}

// ============================================================
// tf32 GEMM: C[m,j] = sum_k A[m,k]*W[j,k] + bias[j]
// BM=128 BN=128 BK=32, 256 thr, 2 CTAs/SM, 3-stage cp.async.
// QKV=true: scatter Q(scaled,fp16)/K(fp16)/V(fp16, transposed).
// ============================================================
#define SA 36                         /* smem row stride (floats) */
#define GS_ARR (128*SA)               /* floats per array  */
#define GS_STG (2*GS_ARR)             /* A|B per stage     */
#define GS_STG_B (GS_STG*4)           /* bytes per stage   */
#define GS_AB_OFF (GS_ARR*4)          /* B offset in stage */
#define GS_SMEM (3*GS_STG_B)          /* 110592 B          */
#define NKT (DIMX/32)                 /* 24 k-tiles        */

template<bool QKV>
__global__ __launch_bounds__(256, 2) void gemm_tf32(const float* __restrict__ bias,
                                                    float* __restrict__ out)
{
    const float* __restrict__ A = QKV ? g_x32  : g_att;
    const float* __restrict__ B = QKV ? g_w132 : g_w232;

    extern __shared__ float smg[];
    const unsigned smem_u32 = (unsigned)__cvta_generic_to_shared(smg);

    const int tid  = threadIdx.x;
    const int lane = tid & 31;
    const int w    = tid >> 5;
    const int g    = lane >> 2;
    const int tig  = lane & 3;
    const int wm   = w & 1;
    const int wn   = w >> 1;
    const int bm   = blockIdx.y * 128;
    const int bn   = blockIdx.x * 128;

    float acc[4][4][4];
    #pragma unroll
    for (int i = 0; i < 4; i++)
        #pragma unroll
        for (int j = 0; j < 4; j++)
            #pragma unroll
            for (int r = 0; r < 4; r++) acc[i][j][r] = 0.f;

    auto load_stage = [&](int st, int k0) {
        unsigned base = smem_u32 + (unsigned)st*GS_STG_B;
        #pragma unroll
        for (int t = 0; t < 4; t++) {
            int idx = tid + t*256;        // 0..1023
            int row = idx >> 3;
            int c4  = (idx & 7) * 4;
            unsigned doff = (unsigned)(row*SA + c4)*4u;
            CP16(base +             doff, &A[(size_t)(bm+row)*DIMX + k0 + c4]);
            CP16(base + GS_AB_OFF + doff, &B[(size_t)(bn+row)*DIMX + k0 + c4]);
        }
    };

    load_stage(0, 0);  CPCOMMIT;
    load_stage(1, 32); CPCOMMIT;

    for (int kt = 0; kt < NKT; kt++) {
        const int s = kt % 3;
        if (kt >= NKT-2) asm volatile("cp.async.wait_group 0;\n");
        else             asm volatile("cp.async.wait_group 1;\n");
        __syncthreads();

        if (kt + 2 < NKT) {
            load_stage((kt+2) % 3, (kt+2)*32);
            CPCOMMIT;
        }

        const float* As = smg + s*GS_STG;
        const float* Bs = As + GS_ARR;

        #pragma unroll
        for (int ks = 0; ks < 32; ks += 8) {
            unsigned af[4][4];
            #pragma unroll
            for (int mf = 0; mf < 4; mf++) {
                int rm = wm*64 + mf*16 + g;
                af[mf][0] = __float_as_uint(As[ rm   *SA + ks + tig    ]);
                af[mf][1] = __float_as_uint(As[(rm+8)*SA + ks + tig    ]);
                af[mf][2] = __float_as_uint(As[ rm   *SA + ks + tig + 4]);
                af[mf][3] = __float_as_uint(As[(rm+8)*SA + ks + tig + 4]);
            }
            #pragma unroll
            for (int nf = 0; nf < 4; nf++) {
                int n = wn*32 + nf*8 + g;
                unsigned b0 = __float_as_uint(Bs[n*SA + ks + tig    ]);
                unsigned b1 = __float_as_uint(Bs[n*SA + ks + tig + 4]);
                #pragma unroll
                for (int mf = 0; mf < 4; mf++)
                    MMA_TF32(acc[mf][nf][0], acc[mf][nf][1],
                             acc[mf][nf][2], acc[mf][nf][3],
                             af[mf][0], af[mf][1], af[mf][2], af[mf][3], b0, b1);
            }
        }
    }

    // ---- epilogue ----
    #pragma unroll
    for (int nf = 0; nf < 4; nf++) {
        int col = bn + wn*32 + nf*8 + tig*2;
        float bx = bias[col], by = bias[col+1];
        if (QKV) {
            int c  = col / DIMX;            // 0=Q 1=K 2=V
            int hh = (col % DIMX) >> 6;
            int dd = col & 63;
            #pragma unroll
            for (int mf = 0; mf < 4; mf++)
                #pragma unroll
                for (int h2 = 0; h2 < 2; h2++) {
                    int row = bm + wm*64 + mf*16 + g + h2*8;
                    int b_ = row >> 11, n_ = row & 2047;
                    float vx = acc[mf][nf][h2*2+0] + bx;
                    float vy = acc[mf][nf][h2*2+1] + by;
                    if (c == 0) {
                        size_t idx = (((size_t)(b_*NHEAD + hh))*SEQ + n_)*HD + dd;
                        *(__half2*)&g_q[idx] =
                            __floats2half2_rn(vx*ATTN_SCALE, vy*ATTN_SCALE);
                    } else if (c == 1) {
                        size_t idx = (((size_t)(b_*NHEAD + hh))*SEQ + n_)*HD + dd;
                        *(__half2*)&g_k[idx] = __floats2half2_rn(vx, vy);
                    } else {
                        size_t idx = (((size_t)(b_*NHEAD + hh))*HD + dd)*SEQ + n_;
                        g_vt[idx]     = __float2half_rn(vx);
                        g_vt[idx+SEQ] = __float2half_rn(vy);
                    }
                }
        } else {
            #pragma unroll
            for (int mf = 0; mf < 4; mf++)
                #pragma unroll
                for (int h2 = 0; h2 < 2; h2++) {
                    int row = bm + wm*64 + mf*16 + g + h2*8;
                    float2 v = make_float2(acc[mf][nf][h2*2+0] + bx,
                                           acc[mf][nf][h2*2+1] + by);
                    *(float2*)&out[(size_t)row*DIMX + col] = v;
                }
        }
    }
}

// ============================================================
// Flash attention: QK^T fp16 m16n8k16, PV fp16 single-term.
// 3-stage cp.async pipeline, 2 CTAs/SM. Block = (b*h, 128 q rows).
// ============================================================
#define KH_STRIDE 72                       /* halves per K row  */
#define VT_STRIDE 72                       /* halves per Vt row */
#define K_BYTES   (64*KH_STRIDE*2)         /* 9216 */
#define V_BYTES   (64*VT_STRIDE*2)         /* 9216 */
#define AT_STG    (K_BYTES + V_BYTES)      /* 18432 per stage */
#define AT_SMEM   (3*AT_STG)               /* 55296 */
#define NTILES    (SEQ/64)                 /* 32 */

__global__ __launch_bounds__(256, 2) void attn_mma()
{
    extern __shared__ char sma[];
    const unsigned smem_u32 = (unsigned)__cvta_generic_to_shared(sma);

    const int tid  = threadIdx.x;
    const int lane = tid & 31;
    const int w    = tid >> 5;
    const int g    = lane >> 2;
    const int tig  = lane & 3;
    const int bh   = blockIdx.y;
    const int q0   = blockIdx.x * 128;
    const size_t kbase = (size_t)bh * SEQ * HD;
    const size_t vbase = (size_t)bh * HD * SEQ;
    const int row0 = q0 + w*16 + g;

    // Q fragments: 4 k16-steps x 4 regs (fp16 pairs, pre-scaled in gmem)
    unsigned qf[4][4];
    #pragma unroll
    for (int ks = 0; ks < 4; ks++) {
        int c0 = ks*16 + tig*2;
        qf[ks][0] = *(const unsigned*)&g_q[kbase + (size_t) row0   *HD + c0    ];
        qf[ks][1] = *(const unsigned*)&g_q[kbase + (size_t)(row0+8)*HD + c0    ];
        qf[ks][2] = *(const unsigned*)&g_q[kbase + (size_t) row0   *HD + c0 + 8];
        qf[ks][3] = *(const unsigned*)&g_q[kbase + (size_t)(row0+8)*HD + c0 + 8];
    }

    float m0 = -INFINITY, m1 = -INFINITY, l0 = 0.f, l1 = 0.f;
    float o[8][4];
    #pragma unroll
    for (int nf = 0; nf < 8; nf++)
        #pragma unroll
        for (int r = 0; r < 4; r++) o[nf][r] = 0.f;

    auto load_tile = [&](int st, int j0) {
        unsigned sb = smem_u32 + (unsigned)st*AT_STG;
        // K: 64 rows x 64 fp16 = 512 16B chunks
        #pragma unroll
        for (int t = 0; t < 2; t++) {
            int idx = tid + t*256;
            int row = idx >> 3;
            int c8  = (idx & 7) * 8;
            CP16(sb + (unsigned)(row*KH_STRIDE + c8)*2u,
                 &g_k[kbase + (size_t)(j0+row)*HD + c8]);
        }
        // V: 64 d-rows x 64 fp16 = 512 chunks
        unsigned vb = sb + K_BYTES;
        #pragma unroll
        for (int t = 0; t < 2; t++) {
            int idx = tid + t*256;
            int d   = idx >> 3;
            int c8  = (idx & 7) * 8;
            CP16(vb + (unsigned)(d*VT_STRIDE + c8)*2u,
                 &g_vt[vbase + (size_t)d*SEQ + j0 + c8]);
        }
    };

    load_tile(0, 0);  CPCOMMIT;
    load_tile(1, 64); CPCOMMIT;

    for (int it = 0; it < NTILES; it++) {
        const int s = it % 3;
        if (it >= NTILES-2) asm volatile("cp.async.wait_group 0;\n");
        else                asm volatile("cp.async.wait_group 1;\n");
        __syncthreads();

        if (it + 2 < NTILES) {
            load_tile((it+2) % 3, (it+2)*64);
            CPCOMMIT;
        }

        const __half* Kh = (const __half*)(sma + s*AT_STG);
        const __half* Vh = (const __half*)(sma + s*AT_STG + K_BYTES);

        // ---- S = Q K^T (fp16, fp32 accum) ----
        float sres[8][4];
        #pragma unroll
        for (int nf = 0; nf < 8; nf++)
            #pragma unroll
            for (int r = 0; r < 4; r++) sres[nf][r] = 0.f;

        #pragma unroll
        for (int ks = 0; ks < 4; ks++) {
            int kc = ks*16 + tig*2;
            #pragma unroll
            for (int nf = 0; nf < 8; nf++) {
                int kv = nf*8 + g;
                unsigned b0 = *(const unsigned*)&Kh[kv*KH_STRIDE + kc    ];
                unsigned b1 = *(const unsigned*)&Kh[kv*KH_STRIDE + kc + 8];
                MMA_F16(sres[nf][0], sres[nf][1], sres[nf][2], sres[nf][3],
                        qf[ks][0], qf[ks][1], qf[ks][2], qf[ks][3], b0, b1);
            }
        }

        // ---- online softmax ----
        float rm0 = -INFINITY, rm1 = -INFINITY;
        #pragma unroll
        for (int nf = 0; nf < 8; nf++) {
            rm0 = fmaxf(rm0, fmaxf(sres[nf][0], sres[nf][1]));
            rm1 = fmaxf(rm1, fmaxf(sres[nf][2], sres[nf][3]));
        }
        rm0 = fmaxf(rm0, __shfl_xor_sync(0xFFFFFFFFu, rm0, 1));
        rm0 = fmaxf(rm0, __shfl_xor_sync(0xFFFFFFFFu, rm0, 2));
        rm1 = fmaxf(rm1, __shfl_xor_sync(0xFFFFFFFFu, rm1, 1));
        rm1 = fmaxf(rm1, __shfl_xor_sync(0xFFFFFFFFu, rm1, 2));
        float mn0 = fmaxf(m0, rm0), mn1 = fmaxf(m1, rm1);
        float al0 = __expf(m0 - mn0), al1 = __expf(m1 - mn1);
        m0 = mn0; m1 = mn1;

        float rs0 = 0.f, rs1 = 0.f;
        #pragma unroll
        for (int nf = 0; nf < 8; nf++) {
            sres[nf][0] = __expf(sres[nf][0] - mn0);
            sres[nf][1] = __expf(sres[nf][1] - mn0);
            sres[nf][2] = __expf(sres[nf][2] - mn1);
            sres[nf][3] = __expf(sres[nf][3] - mn1);
            rs0 += sres[nf][0] + sres[nf][1];
            rs1 += sres[nf][2] + sres[nf][3];
        }
        rs0 += __shfl_xor_sync(0xFFFFFFFFu, rs0, 1);
        rs0 += __shfl_xor_sync(0xFFFFFFFFu, rs0, 2);
        rs1 += __shfl_xor_sync(0xFFFFFFFFu, rs1, 1);
        rs1 += __shfl_xor_sync(0xFFFFFFFFu, rs1, 2);
        l0 = l0*al0 + rs0;
        l1 = l1*al1 + rs1;

        #pragma unroll
        for (int nf = 0; nf < 8; nf++) {
            o[nf][0] *= al0; o[nf][1] *= al0;
            o[nf][2] *= al1; o[nf][3] *= al1;
        }

        // ---- O += P @ V  (fp16; C-frag -> A-frag direct) ----
        #pragma unroll
        for (int jj = 0; jj < 4; jj++) {
            __half2 ph[4];
            ph[0] = __floats2half2_rn(sres[2*jj  ][0], sres[2*jj  ][1]);
            ph[1] = __floats2half2_rn(sres[2*jj  ][2], sres[2*jj  ][3]);
            ph[2] = __floats2half2_rn(sres[2*jj+1][0], sres[2*jj+1][1]);
            ph[3] = __floats2half2_rn(sres[2*jj+1][2], sres[2*jj+1][3]);
            unsigned pa0 = *reinterpret_cast<unsigned*>(&ph[0]);
            unsigned pa1 = *reinterpret_cast<unsigned*>(&ph[1]);
            unsigned pa2 = *reinterpret_cast<unsigned*>(&ph[2]);
            unsigned pa3 = *reinterpret_cast<unsigned*>(&ph[3]);
            int kc = jj*16 + tig*2;
            #pragma unroll
            for (int nf = 0; nf < 8; nf++) {
                int d = nf*8 + g;
                unsigned v0 = *(const unsigned*)&Vh[d*VT_STRIDE + kc    ];
                unsigned v1 = *(const unsigned*)&Vh[d*VT_STRIDE + kc + 8];
                MMA_F16(o[nf][0], o[nf][1], o[nf][2], o[nf][3],
                        pa0, pa1, pa2, pa3, v0, v1);
            }
        }
    }

    // ---- epilogue: normalize, tf32-round, write g_att ----
    float inv0 = 1.0f / l0, inv1 = 1.0f / l1;
    int b_ = bh / NHEAD, hh = bh % NHEAD;
    #pragma unroll
    for (int nf = 0; nf < 8; nf++) {
        int col = hh*64 + nf*8 + tig*2;
        *(float2*)&g_att[((size_t)(b_*SEQ + row0  ))*DIMX + col] =
            make_float2(tf32r(o[nf][0]*inv0), tf32r(o[nf][1]*inv0));
        *(float2*)&g_att[((size_t)(b_*SEQ + row0+8))*DIMX + col] =
            make_float2(tf32r(o[nf][2]*inv1), tf32r(o[nf][3]*inv1));
    }
}

// ============================================================
extern "C" void kernel_launch(void* const* d_in, const int* in_sizes, int n_in,
                              void* d_out, int out_size)
{
    const float* x      = (const float*)d_in[0];
    const float* qkv_w  = (const float*)d_in[1];
    const float* qkv_b  = (const float*)d_in[2];
    const float* proj_w = (const float*)d_in[3];
    const float* proj_b = (const float*)d_in[4];
    float* out = (float*)d_out;
    (void)in_sizes; (void)n_in; (void)out_size;

    cudaFuncSetAttribute(gemm_tf32<true>,
                         cudaFuncAttributeMaxDynamicSharedMemorySize, GS_SMEM);
    cudaFuncSetAttribute(gemm_tf32<false>,
                         cudaFuncAttributeMaxDynamicSharedMemorySize, GS_SMEM);
    cudaFuncSetAttribute(attn_mma,
                         cudaFuncAttributeMaxDynamicSharedMemorySize, AT_SMEM);

    // pre-round inputs to tf32 (rne)
    {
        int n4 = ROWS_TOT*DIMX/4;
        cvt_tf32<0><<<(n4+255)/256, 256>>>((const float4*)x, n4);
        n4 = 3*DIMX*DIMX/4;
        cvt_tf32<1><<<(n4+255)/256, 256>>>((const float4*)qkv_w, n4);
        n4 = DIMX*DIMX/4;
        cvt_tf32<2><<<(n4+255)/256, 256>>>((const float4*)proj_w, n4);
    }

    dim3 g1(2304/128, ROWS_TOT/128);   // (18, 64)
    gemm_tf32<true><<<g1, 256, GS_SMEM>>>(qkv_b, nullptr);

    dim3 g2(SEQ/128, BATCH*NHEAD);     // (16, 48)
    attn_mma<<<g2, 256, AT_SMEM>>>();

    dim3 g3(DIMX/128, ROWS_TOT/128);   // (6, 64)
    gemm_tf32<false><<<g3, 256, GS_SMEM>>>(proj_b, out);
}

// round 13
// speedup vs baseline: 2.7707x; 1.2380x over previous
#include <cuda_runtime.h>
#include <cuda_fp16.h>
#include <cstdint>
#include <cmath>

#define DIMX 768
#define NHEAD 12
#define HD 64
#define BATCH 4
#define SEQ 2048
#define ROWS_TOT (BATCH*SEQ)   /* 8192 */
#define ATTN_SCALE 0.125f
#define BHT (BATCH*NHEAD)

// ---- scratch (allocation-free __device__ globals; device-side access ONLY) ----
__device__ __align__(16) __half g_xh[ROWS_TOT*DIMX];    // x, fp16
__device__ __align__(16) __half g_w1h[3*DIMX*DIMX];     // qkv_w, fp16
__device__ __align__(16) __half g_w2h[DIMX*DIMX];       // proj_w, fp16
__device__ __align__(16) __half g_q[BHT*SEQ*HD];        // fp16, pre-scaled
__device__ __align__(16) __half g_k[BHT*SEQ*HD];        // fp16
__device__ __align__(16) __half g_vt[BHT*HD*SEQ];       // V transposed, fp16
__device__ __align__(16) __half g_att[ROWS_TOT*DIMX];   // attn out, fp16

// ---- mma.sync m16n8k16 fp16 (row.col), fp32 accum ----
#define MMA_F16(d0,d1,d2,d3,a0,a1,a2,a3,b0,b1)                               \
  asm volatile("mma.sync.aligned.m16n8k16.row.col.f32.f16.f16.f32 "          \
               "{%0,%1,%2,%3}, {%4,%5,%6,%7}, {%8,%9}, {%0,%1,%2,%3};\n"     \
               : "+f"(d0), "+f"(d1), "+f"(d2), "+f"(d3)                      \
               : "r"(a0), "r"(a1), "r"(a2), "r"(a3), "r"(b0), "r"(b1))

#define CP16(d, s)                                                            \
  asm volatile("cp.async.cg.shared.global [%0], [%1], 16;\n"                  \
               :: "r"(d), "l"(s))
#define CPCOMMIT asm volatile("cp.async.commit_group;\n")

// ============================================================
// fp32 -> fp16 convert (vectorized). WHICH: 0->x 1->qkv_w 2->proj_w
// ============================================================
template<int WHICH>
__global__ void cvt_f16(const float4* __restrict__ src, int n4)
{
    __half2* dst = (WHICH == 0) ? (__half2*)g_xh
                 : (WHICH == 1) ? (__half2*)g_w1h
                                : (__half2*)g_w2h;
    int i = blockIdx.x*blockDim.x + threadIdx.x;
    if (i >= n4) return;
    float4 v = src[i];
    dst[i*2]   = __floats2half2_rn(v.x, v.y);
    dst[i*2+1] = __floats2half2_rn(v.z, v.w);
}

// ============================================================
// fp16 GEMM (fp32 accum): C[m,j] = sum_k A[m,k]*W[j,k] + bias[j]
// BM=128 BN=128 BK=32, 256 thr, 2 CTAs/SM, 3-stage cp.async.
// QKV=true: scatter Q(scaled,fp16)/K(fp16)/V(fp16, transposed).
// ============================================================
#define SH 40                          /* smem row stride (halves) */
#define GH_ARR (128*SH)                /* halves per array   */
#define GH_ARR_B (GH_ARR*2)            /* bytes per array    */
#define GH_STG_B (2*GH_ARR_B)          /* A|B per stage      */
#define GH_SMEM (3*GH_STG_B)           /* 61440 B            */
#define NKT (DIMX/32)                  /* 24 k-tiles         */

template<bool QKV>
__global__ __launch_bounds__(256, 2) void gemm_f16(const float* __restrict__ bias,
                                                   float* __restrict__ out)
{
    const __half* __restrict__ A = QKV ? g_xh  : g_att;
    const __half* __restrict__ B = QKV ? g_w1h : g_w2h;

    extern __shared__ __half smg[];
    const unsigned smem_u32 = (unsigned)__cvta_generic_to_shared(smg);

    const int tid  = threadIdx.x;
    const int lane = tid & 31;
    const int w    = tid >> 5;
    const int g    = lane >> 2;
    const int tig  = lane & 3;
    const int wm   = w & 1;
    const int wn   = w >> 1;
    const int bm   = blockIdx.y * 128;
    const int bn   = blockIdx.x * 128;

    float acc[4][4][4];
    #pragma unroll
    for (int i = 0; i < 4; i++)
        #pragma unroll
        for (int j = 0; j < 4; j++)
            #pragma unroll
            for (int r = 0; r < 4; r++) acc[i][j][r] = 0.f;

    auto load_stage = [&](int st, int k0) {
        unsigned base = smem_u32 + (unsigned)st*GH_STG_B;
        #pragma unroll
        for (int t = 0; t < 2; t++) {
            int idx = tid + t*256;        // 0..511
            int row = idx >> 2;
            int c8  = (idx & 3) * 8;
            unsigned doff = (unsigned)(row*SH + c8)*2u;
            CP16(base +            doff, &A[(size_t)(bm+row)*DIMX + k0 + c8]);
            CP16(base + GH_ARR_B + doff, &B[(size_t)(bn+row)*DIMX + k0 + c8]);
        }
    };

    load_stage(0, 0);  CPCOMMIT;
    load_stage(1, 32); CPCOMMIT;

    for (int kt = 0; kt < NKT; kt++) {
        const int s = kt % 3;
        if (kt >= NKT-2) asm volatile("cp.async.wait_group 0;\n");
        else             asm volatile("cp.async.wait_group 1;\n");
        __syncthreads();

        if (kt + 2 < NKT) {
            load_stage((kt+2) % 3, (kt+2)*32);
            CPCOMMIT;
        }

        const __half* As = smg + s*(GH_STG_B/2);
        const __half* Bs = As + GH_ARR;

        #pragma unroll
        for (int ks = 0; ks < 32; ks += 16) {
            const int kc = ks + tig*2;
            unsigned af[4][4];
            #pragma unroll
            for (int mf = 0; mf < 4; mf++) {
                int rm = wm*64 + mf*16 + g;
                af[mf][0] = *(const unsigned*)&As[ rm   *SH + kc    ];
                af[mf][1] = *(const unsigned*)&As[(rm+8)*SH + kc    ];
                af[mf][2] = *(const unsigned*)&As[ rm   *SH + kc + 8];
                af[mf][3] = *(const unsigned*)&As[(rm+8)*SH + kc + 8];
            }
            #pragma unroll
            for (int nf = 0; nf < 4; nf++) {
                int n = wn*32 + nf*8 + g;
                unsigned b0 = *(const unsigned*)&Bs[n*SH + kc    ];
                unsigned b1 = *(const unsigned*)&Bs[n*SH + kc + 8];
                #pragma unroll
                for (int mf = 0; mf < 4; mf++)
                    MMA_F16(acc[mf][nf][0], acc[mf][nf][1],
                            acc[mf][nf][2], acc[mf][nf][3],
                            af[mf][0], af[mf][1], af[mf][2], af[mf][3], b0, b1);
            }
        }
    }

    // ---- epilogue ----
    #pragma unroll
    for (int nf = 0; nf < 4; nf++) {
        int col = bn + wn*32 + nf*8 + tig*2;
        float bx = bias[col], by = bias[col+1];
        if (QKV) {
            int c  = col / DIMX;            // 0=Q 1=K 2=V
            int hh = (col % DIMX) >> 6;
            int dd = col & 63;
            #pragma unroll
            for (int mf = 0; mf < 4; mf++)
                #pragma unroll
                for (int h2 = 0; h2 < 2; h2++) {
                    int row = bm + wm*64 + mf*16 + g + h2*8;
                    int b_ = row >> 11, n_ = row & 2047;
                    float vx = acc[mf][nf][h2*2+0] + bx;
                    float vy = acc[mf][nf][h2*2+1] + by;
                    if (c == 0) {
                        size_t idx = (((size_t)(b_*NHEAD + hh))*SEQ + n_)*HD + dd;
                        *(__half2*)&g_q[idx] =
                            __floats2half2_rn(vx*ATTN_SCALE, vy*ATTN_SCALE);
                    } else if (c == 1) {
                        size_t idx = (((size_t)(b_*NHEAD + hh))*SEQ + n_)*HD + dd;
                        *(__half2*)&g_k[idx] = __floats2half2_rn(vx, vy);
                    } else {
                        size_t idx = (((size_t)(b_*NHEAD + hh))*HD + dd)*SEQ + n_;
                        g_vt[idx]     = __float2half_rn(vx);
                        g_vt[idx+SEQ] = __float2half_rn(vy);
                    }
                }
        } else {
            #pragma unroll
            for (int mf = 0; mf < 4; mf++)
                #pragma unroll
                for (int h2 = 0; h2 < 2; h2++) {
                    int row = bm + wm*64 + mf*16 + g + h2*8;
                    float2 v = make_float2(acc[mf][nf][h2*2+0] + bx,
                                           acc[mf][nf][h2*2+1] + by);
                    *(float2*)&out[(size_t)row*DIMX + col] = v;
                }
        }
    }
}

// ============================================================
// Flash attention (R12 proven): QK^T fp16, PV fp16, fp32 accum.
// 3-stage cp.async pipeline, 2 CTAs/SM. Block = (b*h, 128 q rows).
// Epilogue writes fp16 g_att (proj GEMM reads fp16).
// ============================================================
#define KH_STRIDE 72                       /* halves per K row  */
#define VT_STRIDE 72                       /* halves per Vt row */
#define K_BYTES   (64*KH_STRIDE*2)         /* 9216 */
#define V_BYTES   (64*VT_STRIDE*2)         /* 9216 */
#define AT_STG    (K_BYTES + V_BYTES)      /* 18432 per stage */
#define AT_SMEM   (3*AT_STG)               /* 55296 */
#define NTILES    (SEQ/64)                 /* 32 */

__global__ __launch_bounds__(256, 2) void attn_mma()
{
    extern __shared__ char sma[];
    const unsigned smem_u32 = (unsigned)__cvta_generic_to_shared(sma);

    const int tid  = threadIdx.x;
    const int lane = tid & 31;
    const int w    = tid >> 5;
    const int g    = lane >> 2;
    const int tig  = lane & 3;
    const int bh   = blockIdx.y;
    const int q0   = blockIdx.x * 128;
    const size_t kbase = (size_t)bh * SEQ * HD;
    const size_t vbase = (size_t)bh * HD * SEQ;
    const int row0 = q0 + w*16 + g;

    // Q fragments: 4 k16-steps x 4 regs (fp16 pairs, pre-scaled in gmem)
    unsigned qf[4][4];
    #pragma unroll
    for (int ks = 0; ks < 4; ks++) {
        int c0 = ks*16 + tig*2;
        qf[ks][0] = *(const unsigned*)&g_q[kbase + (size_t) row0   *HD + c0    ];
        qf[ks][1] = *(const unsigned*)&g_q[kbase + (size_t)(row0+8)*HD + c0    ];
        qf[ks][2] = *(const unsigned*)&g_q[kbase + (size_t) row0   *HD + c0 + 8];
        qf[ks][3] = *(const unsigned*)&g_q[kbase + (size_t)(row0+8)*HD + c0 + 8];
    }

    float m0 = -INFINITY, m1 = -INFINITY, l0 = 0.f, l1 = 0.f;
    float o[8][4];
    #pragma unroll
    for (int nf = 0; nf < 8; nf++)
        #pragma unroll
        for (int r = 0; r < 4; r++) o[nf][r] = 0.f;

    auto load_tile = [&](int st, int j0) {
        unsigned sb = smem_u32 + (unsigned)st*AT_STG;
        #pragma unroll
        for (int t = 0; t < 2; t++) {
            int idx = tid + t*256;
            int row = idx >> 3;
            int c8  = (idx & 7) * 8;
            CP16(sb + (unsigned)(row*KH_STRIDE + c8)*2u,
                 &g_k[kbase + (size_t)(j0+row)*HD + c8]);
        }
        unsigned vb = sb + K_BYTES;
        #pragma unroll
        for (int t = 0; t < 2; t++) {
            int idx = tid + t*256;
            int d   = idx >> 3;
            int c8  = (idx & 7) * 8;
            CP16(vb + (unsigned)(d*VT_STRIDE + c8)*2u,
                 &g_vt[vbase + (size_t)d*SEQ + j0 + c8]);
        }
    };

    load_tile(0, 0);  CPCOMMIT;
    load_tile(1, 64); CPCOMMIT;

    for (int it = 0; it < NTILES; it++) {
        const int s = it % 3;
        if (it >= NTILES-2) asm volatile("cp.async.wait_group 0;\n");
        else                asm volatile("cp.async.wait_group 1;\n");
        __syncthreads();

        if (it + 2 < NTILES) {
            load_tile((it+2) % 3, (it+2)*64);
            CPCOMMIT;
        }

        const __half* Kh = (const __half*)(sma + s*AT_STG);
        const __half* Vh = (const __half*)(sma + s*AT_STG + K_BYTES);

        // ---- S = Q K^T (fp16, fp32 accum) ----
        float sres[8][4];
        #pragma unroll
        for (int nf = 0; nf < 8; nf++)
            #pragma unroll
            for (int r = 0; r < 4; r++) sres[nf][r] = 0.f;

        #pragma unroll
        for (int ks = 0; ks < 4; ks++) {
            int kc = ks*16 + tig*2;
            #pragma unroll
            for (int nf = 0; nf < 8; nf++) {
                int kv = nf*8 + g;
                unsigned b0 = *(const unsigned*)&Kh[kv*KH_STRIDE + kc    ];
                unsigned b1 = *(const unsigned*)&Kh[kv*KH_STRIDE + kc + 8];
                MMA_F16(sres[nf][0], sres[nf][1], sres[nf][2], sres[nf][3],
                        qf[ks][0], qf[ks][1], qf[ks][2], qf[ks][3], b0, b1);
            }
        }

        // ---- online softmax ----
        float rm0 = -INFINITY, rm1 = -INFINITY;
        #pragma unroll
        for (int nf = 0; nf < 8; nf++) {
            rm0 = fmaxf(rm0, fmaxf(sres[nf][0], sres[nf][1]));
            rm1 = fmaxf(rm1, fmaxf(sres[nf][2], sres[nf][3]));
        }
        rm0 = fmaxf(rm0, __shfl_xor_sync(0xFFFFFFFFu, rm0, 1));
        rm0 = fmaxf(rm0, __shfl_xor_sync(0xFFFFFFFFu, rm0, 2));
        rm1 = fmaxf(rm1, __shfl_xor_sync(0xFFFFFFFFu, rm1, 1));
        rm1 = fmaxf(rm1, __shfl_xor_sync(0xFFFFFFFFu, rm1, 2));
        float mn0 = fmaxf(m0, rm0), mn1 = fmaxf(m1, rm1);
        float al0 = __expf(m0 - mn0), al1 = __expf(m1 - mn1);
        m0 = mn0; m1 = mn1;

        float rs0 = 0.f, rs1 = 0.f;
        #pragma unroll
        for (int nf = 0; nf < 8; nf++) {
            sres[nf][0] = __expf(sres[nf][0] - mn0);
            sres[nf][1] = __expf(sres[nf][1] - mn0);
            sres[nf][2] = __expf(sres[nf][2] - mn1);
            sres[nf][3] = __expf(sres[nf][3] - mn1);
            rs0 += sres[nf][0] + sres[nf][1];
            rs1 += sres[nf][2] + sres[nf][3];
        }
        rs0 += __shfl_xor_sync(0xFFFFFFFFu, rs0, 1);
        rs0 += __shfl_xor_sync(0xFFFFFFFFu, rs0, 2);
        rs1 += __shfl_xor_sync(0xFFFFFFFFu, rs1, 1);
        rs1 += __shfl_xor_sync(0xFFFFFFFFu, rs1, 2);
        l0 = l0*al0 + rs0;
        l1 = l1*al1 + rs1;

        #pragma unroll
        for (int nf = 0; nf < 8; nf++) {
            o[nf][0] *= al0; o[nf][1] *= al0;
            o[nf][2] *= al1; o[nf][3] *= al1;
        }

        // ---- O += P @ V  (fp16; C-frag -> A-frag direct) ----
        #pragma unroll
        for (int jj = 0; jj < 4; jj++) {
            __half2 ph[4];
            ph[0] = __floats2half2_rn(sres[2*jj  ][0], sres[2*jj  ][1]);
            ph[1] = __floats2half2_rn(sres[2*jj  ][2], sres[2*jj  ][3]);
            ph[2] = __floats2half2_rn(sres[2*jj+1][0], sres[2*jj+1][1]);
            ph[3] = __floats2half2_rn(sres[2*jj+1][2], sres[2*jj+1][3]);
            unsigned pa0 = *reinterpret_cast<unsigned*>(&ph[0]);
            unsigned pa1 = *reinterpret_cast<unsigned*>(&ph[1]);
            unsigned pa2 = *reinterpret_cast<unsigned*>(&ph[2]);
            unsigned pa3 = *reinterpret_cast<unsigned*>(&ph[3]);
            int kc = jj*16 + tig*2;
            #pragma unroll
            for (int nf = 0; nf < 8; nf++) {
                int d = nf*8 + g;
                unsigned v0 = *(const unsigned*)&Vh[d*VT_STRIDE + kc    ];
                unsigned v1 = *(const unsigned*)&Vh[d*VT_STRIDE + kc + 8];
                MMA_F16(o[nf][0], o[nf][1], o[nf][2], o[nf][3],
                        pa0, pa1, pa2, pa3, v0, v1);
            }
        }
    }

    // ---- epilogue: normalize, fp16 g_att ----
    float inv0 = 1.0f / l0, inv1 = 1.0f / l1;
    int b_ = bh / NHEAD, hh = bh % NHEAD;
    #pragma unroll
    for (int nf = 0; nf < 8; nf++) {
        int col = hh*64 + nf*8 + tig*2;
        *(__half2*)&g_att[((size_t)(b_*SEQ + row0  ))*DIMX + col] =
            __floats2half2_rn(o[nf][0]*inv0, o[nf][1]*inv0);
        *(__half2*)&g_att[((size_t)(b_*SEQ + row0+8))*DIMX + col] =
            __floats2half2_rn(o[nf][2]*inv1, o[nf][3]*inv1);
    }
}

// ============================================================
extern "C" void kernel_launch(void* const* d_in, const int* in_sizes, int n_in,
                              void* d_out, int out_size)
{
    const float* x      = (const float*)d_in[0];
    const float* qkv_w  = (const float*)d_in[1];
    const float* qkv_b  = (const float*)d_in[2];
    const float* proj_w = (const float*)d_in[3];
    const float* proj_b = (const float*)d_in[4];
    float* out = (float*)d_out;
    (void)in_sizes; (void)n_in; (void)out_size;

    cudaFuncSetAttribute(gemm_f16<true>,
                         cudaFuncAttributeMaxDynamicSharedMemorySize, GH_SMEM);
    cudaFuncSetAttribute(gemm_f16<false>,
                         cudaFuncAttributeMaxDynamicSharedMemorySize, GH_SMEM);
    cudaFuncSetAttribute(attn_mma,
                         cudaFuncAttributeMaxDynamicSharedMemorySize, AT_SMEM);

    // convert inputs to fp16
    {
        int n4 = ROWS_TOT*DIMX/4;
        cvt_f16<0><<<(n4+255)/256, 256>>>((const float4*)x, n4);
        n4 = 3*DIMX*DIMX/4;
        cvt_f16<1><<<(n4+255)/256, 256>>>((const float4*)qkv_w, n4);
        n4 = DIMX*DIMX/4;
        cvt_f16<2><<<(n4+255)/256, 256>>>((const float4*)proj_w, n4);
    }

    dim3 g1(2304/128, ROWS_TOT/128);   // (18, 64)
    gemm_f16<true><<<g1, 256, GH_SMEM>>>(qkv_b, nullptr);

    dim3 g2(SEQ/128, BATCH*NHEAD);     // (16, 48)
    attn_mma<<<g2, 256, AT_SMEM>>>();

    dim3 g3(DIMX/128, ROWS_TOT/128);   // (6, 64)
    gemm_f16<false><<<g3, 256, GH_SMEM>>>(proj_b, out);
}

// round 14
// speedup vs baseline: 2.7950x; 1.0088x over previous
#include <cuda_runtime.h>
#include <cuda_fp16.h>
#include <cstdint>
#include <cmath>

#define DIMX 768
#define NHEAD 12
#define HD 64
#define BATCH 4
#define SEQ 2048
#define ROWS_TOT (BATCH*SEQ)   /* 8192 */
#define ATTN_SCALE 0.125f
#define BHT (BATCH*NHEAD)

// ---- scratch (allocation-free __device__ globals; device-side access ONLY) ----
__device__ __align__(16) __half g_xh[ROWS_TOT*DIMX];    // x, fp16
__device__ __align__(16) __half g_w1h[3*DIMX*DIMX];     // qkv_w, fp16
__device__ __align__(16) __half g_w2h[DIMX*DIMX];       // proj_w, fp16
__device__ __align__(16) __half g_q[BHT*SEQ*HD];        // fp16, pre-scaled
__device__ __align__(16) __half g_k[BHT*SEQ*HD];        // fp16
__device__ __align__(16) __half g_vt[BHT*HD*SEQ];       // V transposed, fp16
__device__ __align__(16) __half g_att[ROWS_TOT*DIMX];   // attn out, fp16

// ---- mma.sync m16n8k16 fp16 (row.col), fp32 accum ----
#define MMA_F16(d0,d1,d2,d3,a0,a1,a2,a3,b0,b1)                               \
  asm volatile("mma.sync.aligned.m16n8k16.row.col.f32.f16.f16.f32 "          \
               "{%0,%1,%2,%3}, {%4,%5,%6,%7}, {%8,%9}, {%0,%1,%2,%3};\n"     \
               : "+f"(d0), "+f"(d1), "+f"(d2), "+f"(d3)                      \
               : "r"(a0), "r"(a1), "r"(a2), "r"(a3), "r"(b0), "r"(b1))

#define LDSM4(r0,r1,r2,r3, addr)                                             \
  asm volatile("ldmatrix.sync.aligned.m8n8.x4.shared.b16 {%0,%1,%2,%3}, [%4];\n" \
               : "=r"(r0), "=r"(r1), "=r"(r2), "=r"(r3) : "r"(addr))

#define CP16(d, s)                                                            \
  asm volatile("cp.async.cg.shared.global [%0], [%1], 16;\n"                  \
               :: "r"(d), "l"(s))
#define CPCOMMIT asm volatile("cp.async.commit_group;\n")

// ============================================================
// fp32 -> fp16 convert (vectorized). WHICH: 0->x 1->qkv_w 2->proj_w
// ============================================================
template<int WHICH>
__global__ void cvt_f16(const float4* __restrict__ src, int n4)
{
    __half2* dst = (WHICH == 0) ? (__half2*)g_xh
                 : (WHICH == 1) ? (__half2*)g_w1h
                                : (__half2*)g_w2h;
    int i = blockIdx.x*blockDim.x + threadIdx.x;
    if (i >= n4) return;
    float4 v = src[i];
    dst[i*2]   = __floats2half2_rn(v.x, v.y);
    dst[i*2+1] = __floats2half2_rn(v.z, v.w);
}

// ============================================================
// fp16 GEMM (fp32 accum): C[m,j] = sum_k A[m,k]*W[j,k] + bias[j]
// BM=128 BN=128 BK=32, 256 thr, 2 CTAs/SM, 3-stage cp.async,
// ldmatrix.x4 fragment loads.
// QKV=true: scatter Q(scaled,fp16)/K(fp16)/V(fp16, transposed).
// ============================================================
#define SH 40                          /* smem row stride (halves) */
#define GH_ARR (128*SH)                /* halves per array   */
#define GH_ARR_B (GH_ARR*2)            /* bytes per array    */
#define GH_STG_B (2*GH_ARR_B)          /* A|B per stage      */
#define GH_SMEM (3*GH_STG_B)           /* 61440 B            */
#define NKT (DIMX/32)                  /* 24 k-tiles         */

template<bool QKV>
__global__ __launch_bounds__(256, 2) void gemm_f16(const float* __restrict__ bias,
                                                   float* __restrict__ out)
{
    const __half* __restrict__ A = QKV ? g_xh  : g_att;
    const __half* __restrict__ B = QKV ? g_w1h : g_w2h;

    extern __shared__ __half smg[];
    const unsigned smem_u32 = (unsigned)__cvta_generic_to_shared(smg);

    const int tid  = threadIdx.x;
    const int lane = tid & 31;
    const int w    = tid >> 5;
    const int g    = lane >> 2;
    const int tig  = lane & 3;
    const int wm   = w & 1;
    const int wn   = w >> 1;
    const int bm   = blockIdx.y * 128;
    const int bn   = blockIdx.x * 128;

    // ldmatrix per-lane offset (stride SH halves)
    const unsigned aoff = (unsigned)(((lane & 15)*SH + ((lane >> 4) << 3)) * 2);

    float acc[4][4][4];
    #pragma unroll
    for (int i = 0; i < 4; i++)
        #pragma unroll
        for (int j = 0; j < 4; j++)
            #pragma unroll
            for (int r = 0; r < 4; r++) acc[i][j][r] = 0.f;

    auto load_stage = [&](int st, int k0) {
        unsigned base = smem_u32 + (unsigned)st*GH_STG_B;
        #pragma unroll
        for (int t = 0; t < 2; t++) {
            int idx = tid + t*256;        // 0..511
            int row = idx >> 2;
            int c8  = (idx & 3) * 8;
            unsigned doff = (unsigned)(row*SH + c8)*2u;
            CP16(base +            doff, &A[(size_t)(bm+row)*DIMX + k0 + c8]);
            CP16(base + GH_ARR_B + doff, &B[(size_t)(bn+row)*DIMX + k0 + c8]);
        }
    };

    load_stage(0, 0);  CPCOMMIT;
    load_stage(1, 32); CPCOMMIT;

    for (int kt = 0; kt < NKT; kt++) {
        const int s = kt % 3;
        if (kt >= NKT-2) asm volatile("cp.async.wait_group 0;\n");
        else             asm volatile("cp.async.wait_group 1;\n");
        __syncthreads();

        if (kt + 2 < NKT) {
            load_stage((kt+2) % 3, (kt+2)*32);
            CPCOMMIT;
        }

        const unsigned sA = smem_u32 + s*GH_STG_B;
        const unsigned sB = sA + GH_ARR_B;

        #pragma unroll
        for (int ks = 0; ks < 32; ks += 16) {
            unsigned af[4][4];
            #pragma unroll
            for (int mf = 0; mf < 4; mf++) {
                unsigned ra = sA + (unsigned)(((wm*64 + mf*16)*SH + ks)*2) + aoff;
                LDSM4(af[mf][0], af[mf][1], af[mf][2], af[mf][3], ra);
            }
            unsigned bf[4][2];
            #pragma unroll
            for (int p = 0; p < 2; p++) {
                unsigned rb = sB + (unsigned)(((wn*32 + p*16)*SH + ks)*2) + aoff;
                unsigned r0, r1, r2, r3;
                LDSM4(r0, r1, r2, r3, rb);
                bf[p*2][0] = r0; bf[p*2+1][0] = r1;
                bf[p*2][1] = r2; bf[p*2+1][1] = r3;
            }
            #pragma unroll
            for (int nf = 0; nf < 4; nf++)
                #pragma unroll
                for (int mf = 0; mf < 4; mf++)
                    MMA_F16(acc[mf][nf][0], acc[mf][nf][1],
                            acc[mf][nf][2], acc[mf][nf][3],
                            af[mf][0], af[mf][1], af[mf][2], af[mf][3],
                            bf[nf][0], bf[nf][1]);
        }
    }

    // ---- epilogue ----
    #pragma unroll
    for (int nf = 0; nf < 4; nf++) {
        int col = bn + wn*32 + nf*8 + tig*2;
        float bx = bias[col], by = bias[col+1];
        if (QKV) {
            int c  = col / DIMX;            // 0=Q 1=K 2=V
            int hh = (col % DIMX) >> 6;
            int dd = col & 63;
            #pragma unroll
            for (int mf = 0; mf < 4; mf++)
                #pragma unroll
                for (int h2 = 0; h2 < 2; h2++) {
                    int row = bm + wm*64 + mf*16 + g + h2*8;
                    int b_ = row >> 11, n_ = row & 2047;
                    float vx = acc[mf][nf][h2*2+0] + bx;
                    float vy = acc[mf][nf][h2*2+1] + by;
                    if (c == 0) {
                        size_t idx = (((size_t)(b_*NHEAD + hh))*SEQ + n_)*HD + dd;
                        *(__half2*)&g_q[idx] =
                            __floats2half2_rn(vx*ATTN_SCALE, vy*ATTN_SCALE);
                    } else if (c == 1) {
                        size_t idx = (((size_t)(b_*NHEAD + hh))*SEQ + n_)*HD + dd;
                        *(__half2*)&g_k[idx] = __floats2half2_rn(vx, vy);
                    } else {
                        size_t idx = (((size_t)(b_*NHEAD + hh))*HD + dd)*SEQ + n_;
                        g_vt[idx]     = __float2half_rn(vx);
                        g_vt[idx+SEQ] = __float2half_rn(vy);
                    }
                }
        } else {
            #pragma unroll
            for (int mf = 0; mf < 4; mf++)
                #pragma unroll
                for (int h2 = 0; h2 < 2; h2++) {
                    int row = bm + wm*64 + mf*16 + g + h2*8;
                    float2 v = make_float2(acc[mf][nf][h2*2+0] + bx,
                                           acc[mf][nf][h2*2+1] + by);
                    *(float2*)&out[(size_t)row*DIMX + col] = v;
                }
        }
    }
}

// ============================================================
// Flash attention: QK^T fp16, PV fp16, fp32 accum, ldmatrix frags.
// 3-stage cp.async pipeline, 2 CTAs/SM. Block = (b*h, 128 q rows).
// ============================================================
#define KH_STRIDE 72                       /* halves per K row  */
#define VT_STRIDE 72                       /* halves per Vt row */
#define K_BYTES   (64*KH_STRIDE*2)         /* 9216 */
#define V_BYTES   (64*VT_STRIDE*2)         /* 9216 */
#define AT_STG    (K_BYTES + V_BYTES)      /* 18432 per stage */
#define AT_SMEM   (3*AT_STG)               /* 55296 */
#define NTILES    (SEQ/64)                 /* 32 */

__global__ __launch_bounds__(256, 2) void attn_mma()
{
    extern __shared__ char sma[];
    const unsigned smem_u32 = (unsigned)__cvta_generic_to_shared(sma);

    const int tid  = threadIdx.x;
    const int lane = tid & 31;
    const int w    = tid >> 5;
    const int g    = lane >> 2;
    const int tig  = lane & 3;
    const int bh   = blockIdx.y;
    const int q0   = blockIdx.x * 128;
    const size_t kbase = (size_t)bh * SEQ * HD;
    const size_t vbase = (size_t)bh * HD * SEQ;
    const int row0 = q0 + w*16 + g;

    // ldmatrix per-lane offset (stride 72 halves)
    const unsigned aoff = (unsigned)(((lane & 15)*72 + ((lane >> 4) << 3)) * 2);

    // Q fragments: 4 k16-steps x 4 regs (fp16 pairs, pre-scaled in gmem)
    unsigned qf[4][4];
    #pragma unroll
    for (int ks = 0; ks < 4; ks++) {
        int c0 = ks*16 + tig*2;
        qf[ks][0] = *(const unsigned*)&g_q[kbase + (size_t) row0   *HD + c0    ];
        qf[ks][1] = *(const unsigned*)&g_q[kbase + (size_t)(row0+8)*HD + c0    ];
        qf[ks][2] = *(const unsigned*)&g_q[kbase + (size_t) row0   *HD + c0 + 8];
        qf[ks][3] = *(const unsigned*)&g_q[kbase + (size_t)(row0+8)*HD + c0 + 8];
    }

    float m0 = -INFINITY, m1 = -INFINITY, l0 = 0.f, l1 = 0.f;
    float o[8][4];
    #pragma unroll
    for (int nf = 0; nf < 8; nf++)
        #pragma unroll
        for (int r = 0; r < 4; r++) o[nf][r] = 0.f;

    auto load_tile = [&](int st, int j0) {
        unsigned sb = smem_u32 + (unsigned)st*AT_STG;
        #pragma unroll
        for (int t = 0; t < 2; t++) {
            int idx = tid + t*256;
            int row = idx >> 3;
            int c8  = (idx & 7) * 8;
            CP16(sb + (unsigned)(row*KH_STRIDE + c8)*2u,
                 &g_k[kbase + (size_t)(j0+row)*HD + c8]);
        }
        unsigned vb = sb + K_BYTES;
        #pragma unroll
        for (int t = 0; t < 2; t++) {
            int idx = tid + t*256;
            int d   = idx >> 3;
            int c8  = (idx & 7) * 8;
            CP16(vb + (unsigned)(d*VT_STRIDE + c8)*2u,
                 &g_vt[vbase + (size_t)d*SEQ + j0 + c8]);
        }
    };

    load_tile(0, 0);  CPCOMMIT;
    load_tile(1, 64); CPCOMMIT;

    for (int it = 0; it < NTILES; it++) {
        const int s = it % 3;
        if (it >= NTILES-2) asm volatile("cp.async.wait_group 0;\n");
        else                asm volatile("cp.async.wait_group 1;\n");
        __syncthreads();

        if (it + 2 < NTILES) {
            load_tile((it+2) % 3, (it+2)*64);
            CPCOMMIT;
        }

        const unsigned sK = smem_u32 + (unsigned)s*AT_STG;
        const unsigned sV = sK + K_BYTES;

        // ---- S = Q K^T (fp16, fp32 accum) ----
        float sres[8][4];
        #pragma unroll
        for (int nf = 0; nf < 8; nf++)
            #pragma unroll
            for (int r = 0; r < 4; r++) sres[nf][r] = 0.f;

        #pragma unroll
        for (int ks = 0; ks < 4; ks++) {
            #pragma unroll
            for (int p = 0; p < 4; p++) {
                unsigned rb = sK + (unsigned)((p*16*72 + ks*16)*2) + aoff;
                unsigned r0, r1, r2, r3;
                LDSM4(r0, r1, r2, r3, rb);
                MMA_F16(sres[2*p][0], sres[2*p][1], sres[2*p][2], sres[2*p][3],
                        qf[ks][0], qf[ks][1], qf[ks][2], qf[ks][3], r0, r2);
                MMA_F16(sres[2*p+1][0], sres[2*p+1][1], sres[2*p+1][2], sres[2*p+1][3],
                        qf[ks][0], qf[ks][1], qf[ks][2], qf[ks][3], r1, r3);
            }
        }

        // ---- online softmax ----
        float rm0 = -INFINITY, rm1 = -INFINITY;
        #pragma unroll
        for (int nf = 0; nf < 8; nf++) {
            rm0 = fmaxf(rm0, fmaxf(sres[nf][0], sres[nf][1]));
            rm1 = fmaxf(rm1, fmaxf(sres[nf][2], sres[nf][3]));
        }
        rm0 = fmaxf(rm0, __shfl_xor_sync(0xFFFFFFFFu, rm0, 1));
        rm0 = fmaxf(rm0, __shfl_xor_sync(0xFFFFFFFFu, rm0, 2));
        rm1 = fmaxf(rm1, __shfl_xor_sync(0xFFFFFFFFu, rm1, 1));
        rm1 = fmaxf(rm1, __shfl_xor_sync(0xFFFFFFFFu, rm1, 2));
        float mn0 = fmaxf(m0, rm0), mn1 = fmaxf(m1, rm1);
        float al0 = __expf(m0 - mn0), al1 = __expf(m1 - mn1);
        m0 = mn0; m1 = mn1;

        float rs0 = 0.f, rs1 = 0.f;
        #pragma unroll
        for (int nf = 0; nf < 8; nf++) {
            sres[nf][0] = __expf(sres[nf][0] - mn0);
            sres[nf][1] = __expf(sres[nf][1] - mn0);
            sres[nf][2] = __expf(sres[nf][2] - mn1);
            sres[nf][3] = __expf(sres[nf][3] - mn1);
            rs0 += sres[nf][0] + sres[nf][1];
            rs1 += sres[nf][2] + sres[nf][3];
        }
        rs0 += __shfl_xor_sync(0xFFFFFFFFu, rs0, 1);
        rs0 += __shfl_xor_sync(0xFFFFFFFFu, rs0, 2);
        rs1 += __shfl_xor_sync(0xFFFFFFFFu, rs1, 1);
        rs1 += __shfl_xor_sync(0xFFFFFFFFu, rs1, 2);
        l0 = l0*al0 + rs0;
        l1 = l1*al1 + rs1;

        #pragma unroll
        for (int nf = 0; nf < 8; nf++) {
            o[nf][0] *= al0; o[nf][1] *= al0;
            o[nf][2] *= al1; o[nf][3] *= al1;
        }

        // ---- O += P @ V  (fp16; C-frag -> A-frag direct, ldmatrix V) ----
        #pragma unroll
        for (int jj = 0; jj < 4; jj++) {
            __half2 ph[4];
            ph[0] = __floats2half2_rn(sres[2*jj  ][0], sres[2*jj  ][1]);
            ph[1] = __floats2half2_rn(sres[2*jj  ][2], sres[2*jj  ][3]);
            ph[2] = __floats2half2_rn(sres[2*jj+1][0], sres[2*jj+1][1]);
            ph[3] = __floats2half2_rn(sres[2*jj+1][2], sres[2*jj+1][3]);
            unsigned pa0 = *reinterpret_cast<unsigned*>(&ph[0]);
            unsigned pa1 = *reinterpret_cast<unsigned*>(&ph[1]);
            unsigned pa2 = *reinterpret_cast<unsigned*>(&ph[2]);
            unsigned pa3 = *reinterpret_cast<unsigned*>(&ph[3]);
            #pragma unroll
            for (int p = 0; p < 4; p++) {
                unsigned rb = sV + (unsigned)((p*16*72 + jj*16)*2) + aoff;
                unsigned r0, r1, r2, r3;
                LDSM4(r0, r1, r2, r3, rb);
                MMA_F16(o[2*p][0], o[2*p][1], o[2*p][2], o[2*p][3],
                        pa0, pa1, pa2, pa3, r0, r2);
                MMA_F16(o[2*p+1][0], o[2*p+1][1], o[2*p+1][2], o[2*p+1][3],
                        pa0, pa1, pa2, pa3, r1, r3);
            }
        }
    }

    // ---- epilogue: normalize, fp16 g_att ----
    float inv0 = 1.0f / l0, inv1 = 1.0f / l1;
    int b_ = bh / NHEAD, hh = bh % NHEAD;
    #pragma unroll
    for (int nf = 0; nf < 8; nf++) {
        int col = hh*64 + nf*8 + tig*2;
        *(__half2*)&g_att[((size_t)(b_*SEQ + row0  ))*DIMX + col] =
            __floats2half2_rn(o[nf][0]*inv0, o[nf][1]*inv0);
        *(__half2*)&g_att[((size_t)(b_*SEQ + row0+8))*DIMX + col] =
            __floats2half2_rn(o[nf][2]*inv1, o[nf][3]*inv1);
    }
}

// ============================================================
extern "C" void kernel_launch(void* const* d_in, const int* in_sizes, int n_in,
                              void* d_out, int out_size)
{
    const float* x      = (const float*)d_in[0];
    const float* qkv_w  = (const float*)d_in[1];
    const float* qkv_b  = (const float*)d_in[2];
    const float* proj_w = (const float*)d_in[3];
    const float* proj_b = (const float*)d_in[4];
    float* out = (float*)d_out;
    (void)in_sizes; (void)n_in; (void)out_size;

    cudaFuncSetAttribute(gemm_f16<true>,
                         cudaFuncAttributeMaxDynamicSharedMemorySize, GH_SMEM);
    cudaFuncSetAttribute(gemm_f16<false>,
                         cudaFuncAttributeMaxDynamicSharedMemorySize, GH_SMEM);
    cudaFuncSetAttribute(attn_mma,
                         cudaFuncAttributeMaxDynamicSharedMemorySize, AT_SMEM);

    // convert inputs to fp16
    {
        int n4 = ROWS_TOT*DIMX/4;
        cvt_f16<0><<<(n4+255)/256, 256>>>((const float4*)x, n4);
        n4 = 3*DIMX*DIMX/4;
        cvt_f16<1><<<(n4+255)/256, 256>>>((const float4*)qkv_w, n4);
        n4 = DIMX*DIMX/4;
        cvt_f16<2><<<(n4+255)/256, 256>>>((const float4*)proj_w, n4);
    }

    dim3 g1(2304/128, ROWS_TOT/128);   // (18, 64)
    gemm_f16<true><<<g1, 256, GH_SMEM>>>(qkv_b, nullptr);

    dim3 g2(SEQ/128, BATCH*NHEAD);     // (16, 48)
    attn_mma<<<g2, 256, AT_SMEM>>>();

    dim3 g3(DIMX/128, ROWS_TOT/128);   // (6, 64)
    gemm_f16<false><<<g3, 256, GH_SMEM>>>(proj_b, out);
}

// round 15
// speedup vs baseline: 2.8118x; 1.0060x over previous
#include <cuda_runtime.h>
#include <cuda_fp16.h>
#include <cstdint>
#include <cmath>

#define DIMX 768
#define NHEAD 12
#define HD 64
#define BATCH 4
#define SEQ 2048
#define ROWS_TOT (BATCH*SEQ)   /* 8192 */
#define BHT (BATCH*NHEAD)
/* Q pre-scale: Hd^-0.5 * log2(e) -> scores directly in log2 units */
#define Q_SCALE (0.125f * 1.4426950408889634f)

// ---- scratch (allocation-free __device__ globals; device-side access ONLY) ----
__device__ __align__(16) __half g_xh[ROWS_TOT*DIMX];    // x, fp16
__device__ __align__(16) __half g_w1h[3*DIMX*DIMX];     // qkv_w, fp16
__device__ __align__(16) __half g_w2h[DIMX*DIMX];       // proj_w, fp16
__device__ __align__(16) __half g_q[BHT*SEQ*HD];        // fp16, pre-scaled (log2e folded)
__device__ __align__(16) __half g_k[BHT*SEQ*HD];        // fp16
__device__ __align__(16) __half g_vt[BHT*HD*SEQ];       // V transposed, fp16
__device__ __align__(16) __half g_att[ROWS_TOT*DIMX];   // attn out, fp16

// ---- mma.sync m16n8k16 fp16 (row.col), fp32 accum ----
#define MMA_F16(d0,d1,d2,d3,a0,a1,a2,a3,b0,b1)                               \
  asm volatile("mma.sync.aligned.m16n8k16.row.col.f32.f16.f16.f32 "          \
               "{%0,%1,%2,%3}, {%4,%5,%6,%7}, {%8,%9}, {%0,%1,%2,%3};\n"     \
               : "+f"(d0), "+f"(d1), "+f"(d2), "+f"(d3)                      \
               : "r"(a0), "r"(a1), "r"(a2), "r"(a3), "r"(b0), "r"(b1))

#define LDSM4(r0,r1,r2,r3, addr)                                             \
  asm volatile("ldmatrix.sync.aligned.m8n8.x4.shared.b16 {%0,%1,%2,%3}, [%4];\n" \
               : "=r"(r0), "=r"(r1), "=r"(r2), "=r"(r3) : "r"(addr))

#define CP16(d, s)                                                            \
  asm volatile("cp.async.cg.shared.global [%0], [%1], 16;\n"                  \
               :: "r"(d), "l"(s))
#define CPCOMMIT asm volatile("cp.async.commit_group;\n")

// ============================================================
// fp32 -> fp16 convert (vectorized). WHICH: 0->x 1->qkv_w 2->proj_w
// ============================================================
template<int WHICH>
__global__ void cvt_f16(const float4* __restrict__ src, int n4)
{
    __half2* dst = (WHICH == 0) ? (__half2*)g_xh
                 : (WHICH == 1) ? (__half2*)g_w1h
                                : (__half2*)g_w2h;
    int i = blockIdx.x*blockDim.x + threadIdx.x;
    if (i >= n4) return;
    float4 v = src[i];
    dst[i*2]   = __floats2half2_rn(v.x, v.y);
    dst[i*2+1] = __floats2half2_rn(v.z, v.w);
}

// ============================================================
// fp16 GEMM (fp32 accum): C[m,j] = sum_k A[m,k]*W[j,k] + bias[j]
// BM=128 BN=128 BK=32, 256 thr, 2 CTAs/SM, 3-stage cp.async,
// ldmatrix.x4 fragment loads. (unchanged from R14)
// ============================================================
#define SH 40                          /* smem row stride (halves) */
#define GH_ARR (128*SH)                /* halves per array   */
#define GH_ARR_B (GH_ARR*2)            /* bytes per array    */
#define GH_STG_B (2*GH_ARR_B)          /* A|B per stage      */
#define GH_SMEM (3*GH_STG_B)           /* 61440 B            */
#define NKT (DIMX/32)                  /* 24 k-tiles         */

template<bool QKV>
__global__ __launch_bounds__(256, 2) void gemm_f16(const float* __restrict__ bias,
                                                   float* __restrict__ out)
{
    const __half* __restrict__ A = QKV ? g_xh  : g_att;
    const __half* __restrict__ B = QKV ? g_w1h : g_w2h;

    extern __shared__ __half smg[];
    const unsigned smem_u32 = (unsigned)__cvta_generic_to_shared(smg);

    const int tid  = threadIdx.x;
    const int lane = tid & 31;
    const int w    = tid >> 5;
    const int g    = lane >> 2;
    const int tig  = lane & 3;
    const int wm   = w & 1;
    const int wn   = w >> 1;
    const int bm   = blockIdx.y * 128;
    const int bn   = blockIdx.x * 128;

    const unsigned aoff = (unsigned)(((lane & 15)*SH + ((lane >> 4) << 3)) * 2);

    float acc[4][4][4];
    #pragma unroll
    for (int i = 0; i < 4; i++)
        #pragma unroll
        for (int j = 0; j < 4; j++)
            #pragma unroll
            for (int r = 0; r < 4; r++) acc[i][j][r] = 0.f;

    auto load_stage = [&](int st, int k0) {
        unsigned base = smem_u32 + (unsigned)st*GH_STG_B;
        #pragma unroll
        for (int t = 0; t < 2; t++) {
            int idx = tid + t*256;        // 0..511
            int row = idx >> 2;
            int c8  = (idx & 3) * 8;
            unsigned doff = (unsigned)(row*SH + c8)*2u;
            CP16(base +            doff, &A[(size_t)(bm+row)*DIMX + k0 + c8]);
            CP16(base + GH_ARR_B + doff, &B[(size_t)(bn+row)*DIMX + k0 + c8]);
        }
    };

    load_stage(0, 0);  CPCOMMIT;
    load_stage(1, 32); CPCOMMIT;

    for (int kt = 0; kt < NKT; kt++) {
        const int s = kt % 3;
        if (kt >= NKT-2) asm volatile("cp.async.wait_group 0;\n");
        else             asm volatile("cp.async.wait_group 1;\n");
        __syncthreads();

        if (kt + 2 < NKT) {
            load_stage((kt+2) % 3, (kt+2)*32);
            CPCOMMIT;
        }

        const unsigned sA = smem_u32 + s*GH_STG_B;
        const unsigned sB = sA + GH_ARR_B;

        #pragma unroll
        for (int ks = 0; ks < 32; ks += 16) {
            unsigned af[4][4];
            #pragma unroll
            for (int mf = 0; mf < 4; mf++) {
                unsigned ra = sA + (unsigned)(((wm*64 + mf*16)*SH + ks)*2) + aoff;
                LDSM4(af[mf][0], af[mf][1], af[mf][2], af[mf][3], ra);
            }
            unsigned bf[4][2];
            #pragma unroll
            for (int p = 0; p < 2; p++) {
                unsigned rb = sB + (unsigned)(((wn*32 + p*16)*SH + ks)*2) + aoff;
                unsigned r0, r1, r2, r3;
                LDSM4(r0, r1, r2, r3, rb);
                bf[p*2][0] = r0; bf[p*2+1][0] = r1;
                bf[p*2][1] = r2; bf[p*2+1][1] = r3;
            }
            #pragma unroll
            for (int nf = 0; nf < 4; nf++)
                #pragma unroll
                for (int mf = 0; mf < 4; mf++)
                    MMA_F16(acc[mf][nf][0], acc[mf][nf][1],
                            acc[mf][nf][2], acc[mf][nf][3],
                            af[mf][0], af[mf][1], af[mf][2], af[mf][3],
                            bf[nf][0], bf[nf][1]);
        }
    }

    // ---- epilogue ----
    #pragma unroll
    for (int nf = 0; nf < 4; nf++) {
        int col = bn + wn*32 + nf*8 + tig*2;
        float bx = bias[col], by = bias[col+1];
        if (QKV) {
            int c  = col / DIMX;            // 0=Q 1=K 2=V
            int hh = (col % DIMX) >> 6;
            int dd = col & 63;
            #pragma unroll
            for (int mf = 0; mf < 4; mf++)
                #pragma unroll
                for (int h2 = 0; h2 < 2; h2++) {
                    int row = bm + wm*64 + mf*16 + g + h2*8;
                    int b_ = row >> 11, n_ = row & 2047;
                    float vx = acc[mf][nf][h2*2+0] + bx;
                    float vy = acc[mf][nf][h2*2+1] + by;
                    if (c == 0) {
                        size_t idx = (((size_t)(b_*NHEAD + hh))*SEQ + n_)*HD + dd;
                        *(__half2*)&g_q[idx] =
                            __floats2half2_rn(vx*Q_SCALE, vy*Q_SCALE);
                    } else if (c == 1) {
                        size_t idx = (((size_t)(b_*NHEAD + hh))*SEQ + n_)*HD + dd;
                        *(__half2*)&g_k[idx] = __floats2half2_rn(vx, vy);
                    } else {
                        size_t idx = (((size_t)(b_*NHEAD + hh))*HD + dd)*SEQ + n_;
                        g_vt[idx]     = __float2half_rn(vx);
                        g_vt[idx+SEQ] = __float2half_rn(vy);
                    }
                }
        } else {
            #pragma unroll
            for (int mf = 0; mf < 4; mf++)
                #pragma unroll
                for (int h2 = 0; h2 < 2; h2++) {
                    int row = bm + wm*64 + mf*16 + g + h2*8;
                    float2 v = make_float2(acc[mf][nf][h2*2+0] + bx,
                                           acc[mf][nf][h2*2+1] + by);
                    *(float2*)&out[(size_t)row*DIMX + col] = v;
                }
        }
    }
}

// ============================================================
// Flash attention: QK^T fp16 (scores in log2 units), packed fp16
// exp2 (h2exp2), row-sum l via ones-row MMA. 3-stage cp.async,
// 2 CTAs/SM. Block = (b*h, 128 q rows).
// V smem tile has 80 n-rows: 0-63 = V data (cp.async), 64 = ones,
// 65-79 = zeros (init once, never overwritten).
// ============================================================
#define KH_STRIDE 72                       /* halves per K row  */
#define VT_STRIDE 72                       /* halves per Vt row */
#define K_BYTES   (64*KH_STRIDE*2)         /* 9216  */
#define V_ROWS    80
#define V_BYTES   (V_ROWS*VT_STRIDE*2)     /* 11520 */
#define AT_STG    (K_BYTES + V_BYTES)      /* 20736 per stage */
#define AT_SMEM   (3*AT_STG)               /* 62208 */
#define NTILES    (SEQ/64)                 /* 32 */

__global__ __launch_bounds__(256, 2) void attn_mma()
{
    extern __shared__ char sma[];
    const unsigned smem_u32 = (unsigned)__cvta_generic_to_shared(sma);

    const int tid  = threadIdx.x;
    const int lane = tid & 31;
    const int w    = tid >> 5;
    const int g    = lane >> 2;
    const int tig  = lane & 3;
    const int bh   = blockIdx.y;
    const int q0   = blockIdx.x * 128;
    const size_t kbase = (size_t)bh * SEQ * HD;
    const size_t vbase = (size_t)bh * HD * SEQ;
    const int row0 = q0 + w*16 + g;

    const unsigned aoff = (unsigned)(((lane & 15)*72 + ((lane >> 4) << 3)) * 2);

    // init ones/zero rows (64..79) of all 3 V stages; cp.async never writes them
    {
        __half* vbase_s = (__half*)sma;
        for (int idx = tid; idx < 3*16*VT_STRIDE; idx += 256) {
            int st  = idx / (16*VT_STRIDE);
            int rem = idx % (16*VT_STRIDE);
            int r   = rem / VT_STRIDE;     // 0..15 -> row 64+r
            int c   = rem % VT_STRIDE;
            __half v = (r == 0) ? __float2half(1.0f) : __float2half(0.0f);
            vbase_s[(st*AT_STG + K_BYTES)/2 + (64 + r)*VT_STRIDE + c] = v;
        }
    }

    // Q fragments: 4 k16-steps x 4 regs (fp16 pairs, pre-scaled in gmem)
    unsigned qf[4][4];
    #pragma unroll
    for (int ks = 0; ks < 4; ks++) {
        int c0 = ks*16 + tig*2;
        qf[ks][0] = *(const unsigned*)&g_q[kbase + (size_t) row0   *HD + c0    ];
        qf[ks][1] = *(const unsigned*)&g_q[kbase + (size_t)(row0+8)*HD + c0    ];
        qf[ks][2] = *(const unsigned*)&g_q[kbase + (size_t) row0   *HD + c0 + 8];
        qf[ks][3] = *(const unsigned*)&g_q[kbase + (size_t)(row0+8)*HD + c0 + 8];
    }

    float m0 = -INFINITY, m1 = -INFINITY;
    float o[8][4], ol[4];
    #pragma unroll
    for (int nf = 0; nf < 8; nf++)
        #pragma unroll
        for (int r = 0; r < 4; r++) o[nf][r] = 0.f;
    #pragma unroll
    for (int r = 0; r < 4; r++) ol[r] = 0.f;

    auto load_tile = [&](int st, int j0) {
        unsigned sb = smem_u32 + (unsigned)st*AT_STG;
        #pragma unroll
        for (int t = 0; t < 2; t++) {
            int idx = tid + t*256;
            int row = idx >> 3;
            int c8  = (idx & 7) * 8;
            CP16(sb + (unsigned)(row*KH_STRIDE + c8)*2u,
                 &g_k[kbase + (size_t)(j0+row)*HD + c8]);
        }
        unsigned vb = sb + K_BYTES;
        #pragma unroll
        for (int t = 0; t < 2; t++) {
            int idx = tid + t*256;
            int d   = idx >> 3;
            int c8  = (idx & 7) * 8;
            CP16(vb + (unsigned)(d*VT_STRIDE + c8)*2u,
                 &g_vt[vbase + (size_t)d*SEQ + j0 + c8]);
        }
    };

    load_tile(0, 0);  CPCOMMIT;
    load_tile(1, 64); CPCOMMIT;

    for (int it = 0; it < NTILES; it++) {
        const int s = it % 3;
        if (it >= NTILES-2) asm volatile("cp.async.wait_group 0;\n");
        else                asm volatile("cp.async.wait_group 1;\n");
        __syncthreads();

        if (it + 2 < NTILES) {
            load_tile((it+2) % 3, (it+2)*64);
            CPCOMMIT;
        }

        const unsigned sK = smem_u32 + (unsigned)s*AT_STG;
        const unsigned sV = sK + K_BYTES;

        // ---- S = Q K^T (scores in log2 units) ----
        float sres[8][4];
        #pragma unroll
        for (int nf = 0; nf < 8; nf++)
            #pragma unroll
            for (int r = 0; r < 4; r++) sres[nf][r] = 0.f;

        #pragma unroll
        for (int ks = 0; ks < 4; ks++) {
            #pragma unroll
            for (int p = 0; p < 4; p++) {
                unsigned rb = sK + (unsigned)((p*16*72 + ks*16)*2) + aoff;
                unsigned r0, r1, r2, r3;
                LDSM4(r0, r1, r2, r3, rb);
                MMA_F16(sres[2*p][0], sres[2*p][1], sres[2*p][2], sres[2*p][3],
                        qf[ks][0], qf[ks][1], qf[ks][2], qf[ks][3], r0, r2);
                MMA_F16(sres[2*p+1][0], sres[2*p+1][1], sres[2*p+1][2], sres[2*p+1][3],
                        qf[ks][0], qf[ks][1], qf[ks][2], qf[ks][3], r1, r3);
            }
        }

        // ---- online softmax: max reduce only ----
        float rm0 = -INFINITY, rm1 = -INFINITY;
        #pragma unroll
        for (int nf = 0; nf < 8; nf++) {
            rm0 = fmaxf(rm0, fmaxf(sres[nf][0], sres[nf][1]));
            rm1 = fmaxf(rm1, fmaxf(sres[nf][2], sres[nf][3]));
        }
        rm0 = fmaxf(rm0, __shfl_xor_sync(0xFFFFFFFFu, rm0, 1));
        rm0 = fmaxf(rm0, __shfl_xor_sync(0xFFFFFFFFu, rm0, 2));
        rm1 = fmaxf(rm1, __shfl_xor_sync(0xFFFFFFFFu, rm1, 1));
        rm1 = fmaxf(rm1, __shfl_xor_sync(0xFFFFFFFFu, rm1, 2));
        float mn0 = fmaxf(m0, rm0), mn1 = fmaxf(m1, rm1);
        float al0 = exp2f(m0 - mn0), al1 = exp2f(m1 - mn1);
        m0 = mn0; m1 = mn1;

        #pragma unroll
        for (int nf = 0; nf < 8; nf++) {
            o[nf][0] *= al0; o[nf][1] *= al0;
            o[nf][2] *= al1; o[nf][3] *= al1;
        }
        ol[0] *= al0; ol[1] *= al0;
        ol[2] *= al1; ol[3] *= al1;

        // ---- P = exp2(S - m) packed fp16; O += P@V; l += P@1 ----
        #pragma unroll
        for (int jj = 0; jj < 4; jj++) {
            __half2 ph[4];
            ph[0] = h2exp2(__floats2half2_rn(sres[2*jj  ][0]-mn0, sres[2*jj  ][1]-mn0));
            ph[1] = h2exp2(__floats2half2_rn(sres[2*jj  ][2]-mn1, sres[2*jj  ][3]-mn1));
            ph[2] = h2exp2(__floats2half2_rn(sres[2*jj+1][0]-mn0, sres[2*jj+1][1]-mn0));
            ph[3] = h2exp2(__floats2half2_rn(sres[2*jj+1][2]-mn1, sres[2*jj+1][3]-mn1));
            unsigned pa0 = *reinterpret_cast<unsigned*>(&ph[0]);
            unsigned pa1 = *reinterpret_cast<unsigned*>(&ph[1]);
            unsigned pa2 = *reinterpret_cast<unsigned*>(&ph[2]);
            unsigned pa3 = *reinterpret_cast<unsigned*>(&ph[3]);
            #pragma unroll
            for (int p = 0; p < 4; p++) {
                unsigned rb = sV + (unsigned)((p*16*72 + jj*16)*2) + aoff;
                unsigned r0, r1, r2, r3;
                LDSM4(r0, r1, r2, r3, rb);
                MMA_F16(o[2*p][0], o[2*p][1], o[2*p][2], o[2*p][3],
                        pa0, pa1, pa2, pa3, r0, r2);
                MMA_F16(o[2*p+1][0], o[2*p+1][1], o[2*p+1][2], o[2*p+1][3],
                        pa0, pa1, pa2, pa3, r1, r3);
            }
            // l fragment: ones-row block (n rows 64..79)
            {
                unsigned rb = sV + (unsigned)((64*72 + jj*16)*2) + aoff;
                unsigned r0, r1, r2, r3;
                LDSM4(r0, r1, r2, r3, rb);
                MMA_F16(ol[0], ol[1], ol[2], ol[3], pa0, pa1, pa2, pa3, r0, r2);
            }
        }
    }

    // ---- epilogue: l lives at col 64 (tig==0 lanes); broadcast, normalize ----
    int src = lane & 28;     // quad leader (tig = 0, same g)
    float lw0 = __shfl_sync(0xFFFFFFFFu, ol[0], src);
    float lw1 = __shfl_sync(0xFFFFFFFFu, ol[2], src);
    float inv0 = 1.0f / lw0, inv1 = 1.0f / lw1;
    int b_ = bh / NHEAD, hh = bh % NHEAD;
    #pragma unroll
    for (int nf = 0; nf < 8; nf++) {
        int col = hh*64 + nf*8 + tig*2;
        *(__half2*)&g_att[((size_t)(b_*SEQ + row0  ))*DIMX + col] =
            __floats2half2_rn(o[nf][0]*inv0, o[nf][1]*inv0);
        *(__half2*)&g_att[((size_t)(b_*SEQ + row0+8))*DIMX + col] =
            __floats2half2_rn(o[nf][2]*inv1, o[nf][3]*inv1);
    }
}

// ============================================================
extern "C" void kernel_launch(void* const* d_in, const int* in_sizes, int n_in,
                              void* d_out, int out_size)
{
    const float* x      = (const float*)d_in[0];
    const float* qkv_w  = (const float*)d_in[1];
    const float* qkv_b  = (const float*)d_in[2];
    const float* proj_w = (const float*)d_in[3];
    const float* proj_b = (const float*)d_in[4];
    float* out = (float*)d_out;
    (void)in_sizes; (void)n_in; (void)out_size;

    cudaFuncSetAttribute(gemm_f16<true>,
                         cudaFuncAttributeMaxDynamicSharedMemorySize, GH_SMEM);
    cudaFuncSetAttribute(gemm_f16<false>,
                         cudaFuncAttributeMaxDynamicSharedMemorySize, GH_SMEM);
    cudaFuncSetAttribute(attn_mma,
                         cudaFuncAttributeMaxDynamicSharedMemorySize, AT_SMEM);

    // convert inputs to fp16
    {
        int n4 = ROWS_TOT*DIMX/4;
        cvt_f16<0><<<(n4+255)/256, 256>>>((const float4*)x, n4);
        n4 = 3*DIMX*DIMX/4;
        cvt_f16<1><<<(n4+255)/256, 256>>>((const float4*)qkv_w, n4);
        n4 = DIMX*DIMX/4;
        cvt_f16<2><<<(n4+255)/256, 256>>>((const float4*)proj_w, n4);
    }

    dim3 g1(2304/128, ROWS_TOT/128);   // (18, 64)
    gemm_f16<true><<<g1, 256, GH_SMEM>>>(qkv_b, nullptr);

    dim3 g2(SEQ/128, BATCH*NHEAD);     // (16, 48)
    attn_mma<<<g2, 256, AT_SMEM>>>();

    dim3 g3(DIMX/128, ROWS_TOT/128);   // (6, 64)
    gemm_f16<false><<<g3, 256, GH_SMEM>>>(proj_b, out);
}

// round 16
// speedup vs baseline: 2.9401x; 1.0456x over previous
#include <cuda_runtime.h>
#include <cuda_fp16.h>
#include <cstdint>
#include <cmath>

#define DIMX 768
#define NHEAD 12
#define HD 64
#define BATCH 4
#define SEQ 2048
#define ROWS_TOT (BATCH*SEQ)   /* 8192 */
#define BHT (BATCH*NHEAD)
#define Q_SCALE (0.125f * 1.4426950408889634f)

// ---- scratch (allocation-free __device__ globals; device-side access ONLY) ----
__device__ __align__(16) __half g_xh[ROWS_TOT*DIMX];
__device__ __align__(16) __half g_w1h[3*DIMX*DIMX];
__device__ __align__(16) __half g_w2h[DIMX*DIMX];
__device__ __align__(16) __half g_q[BHT*SEQ*HD];        // fp16, pre-scaled (log2e folded)
__device__ __align__(16) __half g_k[BHT*SEQ*HD];
__device__ __align__(16) __half g_vt[BHT*HD*SEQ];       // V transposed, fp16
__device__ __align__(16) __half g_att[ROWS_TOT*DIMX];

#define MMA_F16(d0,d1,d2,d3,a0,a1,a2,a3,b0,b1)                               \
  asm volatile("mma.sync.aligned.m16n8k16.row.col.f32.f16.f16.f32 "          \
               "{%0,%1,%2,%3}, {%4,%5,%6,%7}, {%8,%9}, {%0,%1,%2,%3};\n"     \
               : "+f"(d0), "+f"(d1), "+f"(d2), "+f"(d3)                      \
               : "r"(a0), "r"(a1), "r"(a2), "r"(a3), "r"(b0), "r"(b1))

#define LDSM4(r0,r1,r2,r3, addr)                                             \
  asm volatile("ldmatrix.sync.aligned.m8n8.x4.shared.b16 {%0,%1,%2,%3}, [%4];\n" \
               : "=r"(r0), "=r"(r1), "=r"(r2), "=r"(r3) : "r"(addr))

#define CP16(d, s)                                                            \
  asm volatile("cp.async.cg.shared.global [%0], [%1], 16;\n"                  \
               :: "r"(d), "l"(s))
#define CPCOMMIT asm volatile("cp.async.commit_group;\n")

// ============================================================
// fp32 -> fp16 convert. WHICH: 0->x 1->qkv_w 2->proj_w
// ============================================================
template<int WHICH>
__global__ void cvt_f16(const float4* __restrict__ src, int n4)
{
    __half2* dst = (WHICH == 0) ? (__half2*)g_xh
                 : (WHICH == 1) ? (__half2*)g_w1h
                                : (__half2*)g_w2h;
    int i = blockIdx.x*blockDim.x + threadIdx.x;
    if (i >= n4) return;
    float4 v = src[i];
    dst[i*2]   = __floats2half2_rn(v.x, v.y);
    dst[i*2+1] = __floats2half2_rn(v.z, v.w);
}

// ============================================================
// fp16 GEMM (fp32 accum): BM=128 BN=128 BK=64, 256 thr,
// 2 CTAs/SM, 3-stage cp.async, ldmatrix.x4. 12 sync phases.
// ============================================================
#define SH 72                          /* smem row stride (halves) */
#define GH_ARR (128*SH)                /* halves per array   */
#define GH_ARR_B (GH_ARR*2)            /* 18432 B            */
#define GH_STG_B (2*GH_ARR_B)          /* 36864 B            */
#define GH_SMEM (3*GH_STG_B)           /* 110592 B           */
#define NKT (DIMX/64)                  /* 12 k-tiles         */

template<bool QKV>
__global__ __launch_bounds__(256, 2) void gemm_f16(const float* __restrict__ bias,
                                                   float* __restrict__ out)
{
    const __half* __restrict__ A = QKV ? g_xh  : g_att;
    const __half* __restrict__ B = QKV ? g_w1h : g_w2h;

    extern __shared__ __half smg[];
    const unsigned smem_u32 = (unsigned)__cvta_generic_to_shared(smg);

    const int tid  = threadIdx.x;
    const int lane = tid & 31;
    const int w    = tid >> 5;
    const int g    = lane >> 2;
    const int tig  = lane & 3;
    const int wm   = w & 1;
    const int wn   = w >> 1;
    const int bm   = blockIdx.y * 128;
    const int bn   = blockIdx.x * 128;

    const unsigned aoff = (unsigned)(((lane & 15)*SH + ((lane >> 4) << 3)) * 2);

    float acc[4][4][4];
    #pragma unroll
    for (int i = 0; i < 4; i++)
        #pragma unroll
        for (int j = 0; j < 4; j++)
            #pragma unroll
            for (int r = 0; r < 4; r++) acc[i][j][r] = 0.f;

    auto load_stage = [&](int st, int k0) {
        unsigned base = smem_u32 + (unsigned)st*GH_STG_B;
        #pragma unroll
        for (int t = 0; t < 4; t++) {
            int idx = tid + t*256;        // 0..1023
            int row = idx >> 3;
            int c8  = (idx & 7) * 8;
            unsigned doff = (unsigned)(row*SH + c8)*2u;
            CP16(base +            doff, &A[(size_t)(bm+row)*DIMX + k0 + c8]);
            CP16(base + GH_ARR_B + doff, &B[(size_t)(bn+row)*DIMX + k0 + c8]);
        }
    };

    load_stage(0, 0);  CPCOMMIT;
    load_stage(1, 64); CPCOMMIT;

    for (int kt = 0; kt < NKT; kt++) {
        const int s = kt % 3;
        if (kt >= NKT-2) asm volatile("cp.async.wait_group 0;\n");
        else             asm volatile("cp.async.wait_group 1;\n");
        __syncthreads();

        if (kt + 2 < NKT) {
            load_stage((kt+2) % 3, (kt+2)*64);
            CPCOMMIT;
        }

        const unsigned sA = smem_u32 + s*GH_STG_B;
        const unsigned sB = sA + GH_ARR_B;

        #pragma unroll
        for (int ks = 0; ks < 64; ks += 16) {
            unsigned af[4][4];
            #pragma unroll
            for (int mf = 0; mf < 4; mf++) {
                unsigned ra = sA + (unsigned)(((wm*64 + mf*16)*SH + ks)*2) + aoff;
                LDSM4(af[mf][0], af[mf][1], af[mf][2], af[mf][3], ra);
            }
            unsigned bf[4][2];
            #pragma unroll
            for (int p = 0; p < 2; p++) {
                unsigned rb = sB + (unsigned)(((wn*32 + p*16)*SH + ks)*2) + aoff;
                unsigned r0, r1, r2, r3;
                LDSM4(r0, r1, r2, r3, rb);
                bf[p*2][0] = r0; bf[p*2+1][0] = r1;
                bf[p*2][1] = r2; bf[p*2+1][1] = r3;
            }
            #pragma unroll
            for (int nf = 0; nf < 4; nf++)
                #pragma unroll
                for (int mf = 0; mf < 4; mf++)
                    MMA_F16(acc[mf][nf][0], acc[mf][nf][1],
                            acc[mf][nf][2], acc[mf][nf][3],
                            af[mf][0], af[mf][1], af[mf][2], af[mf][3],
                            bf[nf][0], bf[nf][1]);
        }
    }

    // ---- epilogue ----
    #pragma unroll
    for (int nf = 0; nf < 4; nf++) {
        int col = bn + wn*32 + nf*8 + tig*2;
        float bx = bias[col], by = bias[col+1];
        if (QKV) {
            int c  = col / DIMX;            // 0=Q 1=K 2=V
            int hh = (col % DIMX) >> 6;
            int dd = col & 63;
            #pragma unroll
            for (int mf = 0; mf < 4; mf++)
                #pragma unroll
                for (int h2 = 0; h2 < 2; h2++) {
                    int row = bm + wm*64 + mf*16 + g + h2*8;
                    int b_ = row >> 11, n_ = row & 2047;
                    float vx = acc[mf][nf][h2*2+0] + bx;
                    float vy = acc[mf][nf][h2*2+1] + by;
                    if (c == 0) {
                        size_t idx = (((size_t)(b_*NHEAD + hh))*SEQ + n_)*HD + dd;
                        *(__half2*)&g_q[idx] =
                            __floats2half2_rn(vx*Q_SCALE, vy*Q_SCALE);
                    } else if (c == 1) {
                        size_t idx = (((size_t)(b_*NHEAD + hh))*SEQ + n_)*HD + dd;
                        *(__half2*)&g_k[idx] = __floats2half2_rn(vx, vy);
                    } else {
                        size_t idx = (((size_t)(b_*NHEAD + hh))*HD + dd)*SEQ + n_;
                        g_vt[idx]     = __float2half_rn(vx);
                        g_vt[idx+SEQ] = __float2half_rn(vy);
                    }
                }
        } else {
            #pragma unroll
            for (int mf = 0; mf < 4; mf++)
                #pragma unroll
                for (int h2 = 0; h2 < 2; h2++) {
                    int row = bm + wm*64 + mf*16 + g + h2*8;
                    float2 v = make_float2(acc[mf][nf][h2*2+0] + bx,
                                           acc[mf][nf][h2*2+1] + by);
                    *(float2*)&out[(size_t)row*DIMX + col] = v;
                }
        }
    }
}

// ============================================================
// Flash attention: 128-kv K/V tiles (2-stage), processed as two
// 64-kv chunks. QK^T fp16 (log2 units), h2exp2, l via ones-row
// MMA. 2 CTAs/SM. Block = (b*h, 128 q rows). 16 sync phases.
// ============================================================
#define KH_STRIDE 72                        /* halves per K row (kv rows) */
#define VT_STRIDE 136                       /* halves per Vt row (d rows) */
#define K_BYTES   (128*KH_STRIDE*2)         /* 18432 */
#define V_ROWS    80
#define V_BYTES   (V_ROWS*VT_STRIDE*2)      /* 21760 */
#define AT_STG    (K_BYTES + V_BYTES)       /* 40192 per stage */
#define AT_SMEM   (2*AT_STG)                /* 80384 */
#define NTILES    (SEQ/128)                 /* 16 */

__global__ __launch_bounds__(256, 2) void attn_mma()
{
    extern __shared__ char sma[];
    const unsigned smem_u32 = (unsigned)__cvta_generic_to_shared(sma);

    const int tid  = threadIdx.x;
    const int lane = tid & 31;
    const int w    = tid >> 5;
    const int g    = lane >> 2;
    const int tig  = lane & 3;
    const int bh   = blockIdx.y;
    const int q0   = blockIdx.x * 128;
    const size_t kbase = (size_t)bh * SEQ * HD;
    const size_t vbase = (size_t)bh * HD * SEQ;
    const int row0 = q0 + w*16 + g;

    const unsigned koff = (unsigned)(((lane & 15)*KH_STRIDE + ((lane >> 4) << 3)) * 2);
    const unsigned voff = (unsigned)(((lane & 15)*VT_STRIDE + ((lane >> 4) << 3)) * 2);

    // init ones/zero rows (64..79) of both V stages; cp.async never writes them
    {
        __half* vs = (__half*)sma;
        for (int idx = tid; idx < 2*16*VT_STRIDE; idx += 256) {
            int st  = idx / (16*VT_STRIDE);
            int rem = idx % (16*VT_STRIDE);
            int r   = rem / VT_STRIDE;
            int c   = rem % VT_STRIDE;
            vs[(st*AT_STG + K_BYTES)/2 + (64 + r)*VT_STRIDE + c] =
                (r == 0) ? __float2half(1.0f) : __float2half(0.0f);
        }
    }

    // Q fragments
    unsigned qf[4][4];
    #pragma unroll
    for (int ks = 0; ks < 4; ks++) {
        int c0 = ks*16 + tig*2;
        qf[ks][0] = *(const unsigned*)&g_q[kbase + (size_t) row0   *HD + c0    ];
        qf[ks][1] = *(const unsigned*)&g_q[kbase + (size_t)(row0+8)*HD + c0    ];
        qf[ks][2] = *(const unsigned*)&g_q[kbase + (size_t) row0   *HD + c0 + 8];
        qf[ks][3] = *(const unsigned*)&g_q[kbase + (size_t)(row0+8)*HD + c0 + 8];
    }

    float m0 = -INFINITY, m1 = -INFINITY;
    float o[8][4], ol[4];
    #pragma unroll
    for (int nf = 0; nf < 8; nf++)
        #pragma unroll
        for (int r = 0; r < 4; r++) o[nf][r] = 0.f;
    #pragma unroll
    for (int r = 0; r < 4; r++) ol[r] = 0.f;

    auto load_tile = [&](int st, int j0) {
        unsigned sb = smem_u32 + (unsigned)st*AT_STG;
        // K: 128 kv-rows x 64 halves = 1024 chunks
        #pragma unroll
        for (int t = 0; t < 4; t++) {
            int idx = tid + t*256;
            int row = idx >> 3;
            int c8  = (idx & 7) * 8;
            CP16(sb + (unsigned)(row*KH_STRIDE + c8)*2u,
                 &g_k[kbase + (size_t)(j0+row)*HD + c8]);
        }
        // V: 64 d-rows x 128 halves = 1024 chunks
        unsigned vb = sb + K_BYTES;
        #pragma unroll
        for (int t = 0; t < 4; t++) {
            int idx = tid + t*256;
            int d   = idx >> 4;
            int c8  = (idx & 15) * 8;
            CP16(vb + (unsigned)(d*VT_STRIDE + c8)*2u,
                 &g_vt[vbase + (size_t)d*SEQ + j0 + c8]);
        }
    };

    load_tile(0, 0); CPCOMMIT;

    for (int it = 0; it < NTILES; it++) {
        const int s = it & 1;
        asm volatile("cp.async.wait_group 0;\n");
        __syncthreads();

        if (it + 1 < NTILES) {
            load_tile(s^1, (it+1)*128);
            CPCOMMIT;
        }

        const unsigned sK = smem_u32 + (unsigned)s*AT_STG;
        const unsigned sV = sK + K_BYTES;

        #pragma unroll
        for (int ch = 0; ch < 2; ch++) {   // two 64-kv chunks
            // ---- S = Q K^T (log2 units) ----
            float sres[8][4];
            #pragma unroll
            for (int nf = 0; nf < 8; nf++)
                #pragma unroll
                for (int r = 0; r < 4; r++) sres[nf][r] = 0.f;

            #pragma unroll
            for (int ks = 0; ks < 4; ks++) {
                #pragma unroll
                for (int p = 0; p < 4; p++) {
                    unsigned rb = sK + (unsigned)(((ch*64 + p*16)*KH_STRIDE + ks*16)*2) + koff;
                    unsigned r0, r1, r2, r3;
                    LDSM4(r0, r1, r2, r3, rb);
                    MMA_F16(sres[2*p][0], sres[2*p][1], sres[2*p][2], sres[2*p][3],
                            qf[ks][0], qf[ks][1], qf[ks][2], qf[ks][3], r0, r2);
                    MMA_F16(sres[2*p+1][0], sres[2*p+1][1], sres[2*p+1][2], sres[2*p+1][3],
                            qf[ks][0], qf[ks][1], qf[ks][2], qf[ks][3], r1, r3);
                }
            }

            // ---- max reduce ----
            float rm0 = -INFINITY, rm1 = -INFINITY;
            #pragma unroll
            for (int nf = 0; nf < 8; nf++) {
                rm0 = fmaxf(rm0, fmaxf(sres[nf][0], sres[nf][1]));
                rm1 = fmaxf(rm1, fmaxf(sres[nf][2], sres[nf][3]));
            }
            rm0 = fmaxf(rm0, __shfl_xor_sync(0xFFFFFFFFu, rm0, 1));
            rm0 = fmaxf(rm0, __shfl_xor_sync(0xFFFFFFFFu, rm0, 2));
            rm1 = fmaxf(rm1, __shfl_xor_sync(0xFFFFFFFFu, rm1, 1));
            rm1 = fmaxf(rm1, __shfl_xor_sync(0xFFFFFFFFu, rm1, 2));
            float mn0 = fmaxf(m0, rm0), mn1 = fmaxf(m1, rm1);
            float al0 = exp2f(m0 - mn0), al1 = exp2f(m1 - mn1);
            m0 = mn0; m1 = mn1;

            #pragma unroll
            for (int nf = 0; nf < 8; nf++) {
                o[nf][0] *= al0; o[nf][1] *= al0;
                o[nf][2] *= al1; o[nf][3] *= al1;
            }
            ol[0] *= al0; ol[1] *= al0;
            ol[2] *= al1; ol[3] *= al1;

            // ---- P = exp2(S-m) fp16; O += P@V; l += P@1 ----
            #pragma unroll
            for (int jj = 0; jj < 4; jj++) {
                __half2 ph[4];
                ph[0] = h2exp2(__floats2half2_rn(sres[2*jj  ][0]-mn0, sres[2*jj  ][1]-mn0));
                ph[1] = h2exp2(__floats2half2_rn(sres[2*jj  ][2]-mn1, sres[2*jj  ][3]-mn1));
                ph[2] = h2exp2(__floats2half2_rn(sres[2*jj+1][0]-mn0, sres[2*jj+1][1]-mn0));
                ph[3] = h2exp2(__floats2half2_rn(sres[2*jj+1][2]-mn1, sres[2*jj+1][3]-mn1));
                unsigned pa0 = *reinterpret_cast<unsigned*>(&ph[0]);
                unsigned pa1 = *reinterpret_cast<unsigned*>(&ph[1]);
                unsigned pa2 = *reinterpret_cast<unsigned*>(&ph[2]);
                unsigned pa3 = *reinterpret_cast<unsigned*>(&ph[3]);
                const int kc = ch*64 + jj*16;
                #pragma unroll
                for (int p = 0; p < 4; p++) {
                    unsigned rb = sV + (unsigned)((p*16*VT_STRIDE + kc)*2) + voff;
                    unsigned r0, r1, r2, r3;
                    LDSM4(r0, r1, r2, r3, rb);
                    MMA_F16(o[2*p][0], o[2*p][1], o[2*p][2], o[2*p][3],
                            pa0, pa1, pa2, pa3, r0, r2);
                    MMA_F16(o[2*p+1][0], o[2*p+1][1], o[2*p+1][2], o[2*p+1][3],
                            pa0, pa1, pa2, pa3, r1, r3);
                }
                {   // l fragment: ones-row block
                    unsigned rb = sV + (unsigned)((64*VT_STRIDE + kc)*2) + voff;
                    unsigned r0, r1, r2, r3;
                    LDSM4(r0, r1, r2, r3, rb);
                    MMA_F16(ol[0], ol[1], ol[2], ol[3], pa0, pa1, pa2, pa3, r0, r2);
                }
            }
        }
    }

    // ---- epilogue ----
    int src = lane & 28;
    float lw0 = __shfl_sync(0xFFFFFFFFu, ol[0], src);
    float lw1 = __shfl_sync(0xFFFFFFFFu, ol[2], src);
    float inv0 = 1.0f / lw0, inv1 = 1.0f / lw1;
    int b_ = bh / NHEAD, hh = bh % NHEAD;
    #pragma unroll
    for (int nf = 0; nf < 8; nf++) {
        int col = hh*64 + nf*8 + tig*2;
        *(__half2*)&g_att[((size_t)(b_*SEQ + row0  ))*DIMX + col] =
            __floats2half2_rn(o[nf][0]*inv0, o[nf][1]*inv0);
        *(__half2*)&g_att[((size_t)(b_*SEQ + row0+8))*DIMX + col] =
            __floats2half2_rn(o[nf][2]*inv1, o[nf][3]*inv1);
    }
}

// ============================================================
extern "C" void kernel_launch(void* const* d_in, const int* in_sizes, int n_in,
                              void* d_out, int out_size)
{
    const float* x      = (const float*)d_in[0];
    const float* qkv_w  = (const float*)d_in[1];
    const float* qkv_b  = (const float*)d_in[2];
    const float* proj_w = (const float*)d_in[3];
    const float* proj_b = (const float*)d_in[4];
    float* out = (float*)d_out;
    (void)in_sizes; (void)n_in; (void)out_size;

    cudaFuncSetAttribute(gemm_f16<true>,
                         cudaFuncAttributeMaxDynamicSharedMemorySize, GH_SMEM);
    cudaFuncSetAttribute(gemm_f16<false>,
                         cudaFuncAttributeMaxDynamicSharedMemorySize, GH_SMEM);
    cudaFuncSetAttribute(attn_mma,
                         cudaFuncAttributeMaxDynamicSharedMemorySize, AT_SMEM);

    {
        int n4 = ROWS_TOT*DIMX/4;
        cvt_f16<0><<<(n4+255)/256, 256>>>((const float4*)x, n4);
        n4 = 3*DIMX*DIMX/4;
        cvt_f16<1><<<(n4+255)/256, 256>>>((const float4*)qkv_w, n4);
        n4 = DIMX*DIMX/4;
        cvt_f16<2><<<(n4+255)/256, 256>>>((const float4*)proj_w, n4);
    }

    dim3 g1(2304/128, ROWS_TOT/128);   // (18, 64)
    gemm_f16<true><<<g1, 256, GH_SMEM>>>(qkv_b, nullptr);

    dim3 g2(SEQ/128, BATCH*NHEAD);     // (16, 48)
    attn_mma<<<g2, 256, AT_SMEM>>>();

    dim3 g3(DIMX/128, ROWS_TOT/128);   // (6, 64)
    gemm_f16<false><<<g3, 256, GH_SMEM>>>(proj_b, out);
}